// round 1
// baseline (speedup 1.0000x reference)
#include <cuda_runtime.h>
#include <math.h>

#define D_MODEL 2048
#define NH 16
#define DK 128
#define S_LEN 2048
#define BATCH 2

// Scratch (device globals — no allocations allowed)
__device__ float g_qkv[(size_t)BATCH * S_LEN * 3 * D_MODEL];   // [B,S,3,H,dk]
__device__ float g_attn[(size_t)BATCH * S_LEN * D_MODEL];      // [B,S,H*dk]

// ---------------------------------------------------------------------------
// SGEMM: C[M,N] = A[M,K] @ B[N,K]^T   (both row-major, K-contiguous)
// 128x128 tile, BK=8, 256 threads, 8x8 per-thread register tile.
// ---------------------------------------------------------------------------
__global__ void sgemm_nt(const float* __restrict__ A, const float* __restrict__ B,
                         float* __restrict__ C, int M, int N, int K) {
    __shared__ float As[8][128];
    __shared__ float Bs[8][128];

    const int bm = blockIdx.y * 128;
    const int bn = blockIdx.x * 128;
    const int tid = (int)threadIdx.x;
    const int tx = tid & 15;        // 0..15 -> col group
    const int ty = tid >> 4;        // 0..15 -> row group

    // Each thread loads one float4 from A-tile and one from B-tile per k-step.
    const int lr = tid >> 1;              // row within tile (0..127)
    const int lk = (tid & 1) * 4;         // k offset (0 or 4)

    float acc[8][8];
#pragma unroll
    for (int i = 0; i < 8; i++)
#pragma unroll
        for (int j = 0; j < 8; j++) acc[i][j] = 0.f;

    for (int k0 = 0; k0 < K; k0 += 8) {
        float4 av = *(const float4*)&A[(size_t)(bm + lr) * K + k0 + lk];
        float4 bv = *(const float4*)&B[(size_t)(bn + lr) * K + k0 + lk];
        As[lk + 0][lr] = av.x; As[lk + 1][lr] = av.y;
        As[lk + 2][lr] = av.z; As[lk + 3][lr] = av.w;
        Bs[lk + 0][lr] = bv.x; Bs[lk + 1][lr] = bv.y;
        Bs[lk + 2][lr] = bv.z; Bs[lk + 3][lr] = bv.w;
        __syncthreads();

#pragma unroll
        for (int kk = 0; kk < 8; kk++) {
            float4 ra0 = *(const float4*)&As[kk][ty * 8];
            float4 ra1 = *(const float4*)&As[kk][ty * 8 + 4];
            float4 rb0 = *(const float4*)&Bs[kk][tx * 8];
            float4 rb1 = *(const float4*)&Bs[kk][tx * 8 + 4];
            float ra[8] = {ra0.x, ra0.y, ra0.z, ra0.w, ra1.x, ra1.y, ra1.z, ra1.w};
            float rb[8] = {rb0.x, rb0.y, rb0.z, rb0.w, rb1.x, rb1.y, rb1.z, rb1.w};
#pragma unroll
            for (int i = 0; i < 8; i++)
#pragma unroll
                for (int j = 0; j < 8; j++) acc[i][j] = fmaf(ra[i], rb[j], acc[i][j]);
        }
        __syncthreads();
    }

#pragma unroll
    for (int i = 0; i < 8; i++) {
        const size_t row = (size_t)(bm + ty * 8 + i);
#pragma unroll
        for (int j = 0; j < 8; j += 4) {
            float4 v = make_float4(acc[i][j], acc[i][j + 1], acc[i][j + 2], acc[i][j + 3]);
            *(float4*)&C[row * N + bn + tx * 8 + j] = v;
        }
    }
}

// ---------------------------------------------------------------------------
// Rotary: in-place on Q (t=0) and K (t=1) halves of g_qkv.
// One thread handles one (x1, x2) pair. freq[j] = (1e-4)^(j/63).
// ---------------------------------------------------------------------------
__global__ void rotary_kernel() {
    int idx = blockIdx.x * blockDim.x + threadIdx.x;
    // bits: j(6) | h(4) | t(1) | s(11) | b(1)  => 2^23 threads total
    const int total = BATCH * S_LEN * 2 * NH * 64;
    if (idx >= total) return;
    int j = idx & 63;
    int h = (idx >> 6) & 15;
    int t = (idx >> 10) & 1;
    int s = (idx >> 11) & (S_LEN - 1);
    int b = idx >> 22;

    // ln(1e-4) = -9.210340371976184
    float freq = expf((float)j * (-9.210340371976184f / 63.0f));
    float theta = (float)s * freq;
    float sn, cs;
    sincosf(theta, &sn, &cs);

    size_t base = (((size_t)(b * S_LEN + s)) * 3 + t) * (size_t)D_MODEL + (size_t)h * DK;
    float x1 = g_qkv[base + j];
    float x2 = g_qkv[base + 64 + j];
    g_qkv[base + j]      = x1 * cs - x2 * sn;
    g_qkv[base + 64 + j] = x1 * sn + x2 * cs;
}

// ---------------------------------------------------------------------------
// Causal flash attention, fp32. Block = 64 queries of one (b, h).
// 256 threads: (ty 0..15) x (tx 0..15). Each thread: 4 rows x (4 score cols),
// O accumulator 4 rows x 8 dk-cols.
// ---------------------------------------------------------------------------
#define BM 64
#define BN 64
#define PADD 132   // row stride (floats) for 128-wide tiles (bank stagger)
#define PPAD 68    // row stride for the 64-wide P tile

__global__ void flash_kernel() {
    extern __shared__ float sm[];
    float* Qs = sm;                       // BM * PADD
    float* Ks = Qs + BM * PADD;           // BN * PADD
    float* Vs = Ks + BN * PADD;           // BN * PADD
    float* Ps = Vs + BN * PADD;           // BM * PPAD

    const int qblk = blockIdx.x;
    const int h = blockIdx.y;
    const int b = blockIdx.z;
    const int tid = (int)threadIdx.x;
    const int tx = tid & 15;
    const int ty = tid >> 4;
    const float scale = 0.08838834764831845f;  // 1/sqrt(128)

    // Load Q tile (t=0)
    for (int e = tid; e < BM * (DK / 4); e += 256) {
        int r = e >> 5;           // 32 float4 per row
        int c4 = e & 31;
        size_t g = (((size_t)(b * S_LEN + qblk * BM + r)) * 3 + 0) * (size_t)D_MODEL
                   + (size_t)h * DK + c4 * 4;
        *(float4*)&Qs[r * PADD + c4 * 4] = *(const float4*)&g_qkv[g];
    }

    float m_i[4], l_i[4], o[4][8];
#pragma unroll
    for (int i = 0; i < 4; i++) {
        m_i[i] = -1e30f;
        l_i[i] = 0.f;
#pragma unroll
        for (int c = 0; c < 8; c++) o[i][c] = 0.f;
    }

    for (int jblk = 0; jblk <= qblk; jblk++) {
        __syncthreads();  // protect K/V/P from previous iteration (and Q load)
        // Load K (t=1) and V (t=2) tiles
        for (int e = tid; e < BN * (DK / 4); e += 256) {
            int r = e >> 5;
            int c4 = e & 31;
            size_t rowbase = (size_t)(b * S_LEN + jblk * BN + r) * 3;
            size_t gk = (rowbase + 1) * (size_t)D_MODEL + (size_t)h * DK + c4 * 4;
            size_t gv = (rowbase + 2) * (size_t)D_MODEL + (size_t)h * DK + c4 * 4;
            *(float4*)&Ks[r * PADD + c4 * 4] = *(const float4*)&g_qkv[gk];
            *(float4*)&Vs[r * PADD + c4 * 4] = *(const float4*)&g_qkv[gv];
        }
        __syncthreads();

        // Scores S = Q K^T  (4x4 per thread)
        float sacc[4][4];
#pragma unroll
        for (int i = 0; i < 4; i++)
#pragma unroll
            for (int j = 0; j < 4; j++) sacc[i][j] = 0.f;

        for (int d4 = 0; d4 < DK / 4; d4++) {
            float4 qa[4], kb[4];
#pragma unroll
            for (int i = 0; i < 4; i++)
                qa[i] = *(const float4*)&Qs[(ty * 4 + i) * PADD + d4 * 4];
#pragma unroll
            for (int j = 0; j < 4; j++)
                kb[j] = *(const float4*)&Ks[(tx * 4 + j) * PADD + d4 * 4];
#pragma unroll
            for (int i = 0; i < 4; i++)
#pragma unroll
                for (int j = 0; j < 4; j++) {
                    sacc[i][j] = fmaf(qa[i].x, kb[j].x, sacc[i][j]);
                    sacc[i][j] = fmaf(qa[i].y, kb[j].y, sacc[i][j]);
                    sacc[i][j] = fmaf(qa[i].z, kb[j].z, sacc[i][j]);
                    sacc[i][j] = fmaf(qa[i].w, kb[j].w, sacc[i][j]);
                }
        }

        // Scale + causal mask
        const int qbase = qblk * BM + ty * 4;
        const int kbase = jblk * BN + tx * 4;
#pragma unroll
        for (int i = 0; i < 4; i++)
#pragma unroll
            for (int j = 0; j < 4; j++) {
                float sv = sacc[i][j] * scale;
                if (kbase + j > qbase + i) sv = -1e30f;
                sacc[i][j] = sv;
            }

        // Online softmax per row (16 threads per row group share ty)
#pragma unroll
        for (int i = 0; i < 4; i++) {
            float mrow = fmaxf(fmaxf(sacc[i][0], sacc[i][1]),
                               fmaxf(sacc[i][2], sacc[i][3]));
#pragma unroll
            for (int off = 8; off >= 1; off >>= 1)
                mrow = fmaxf(mrow, __shfl_xor_sync(0xffffffffu, mrow, off));
            float mnew = fmaxf(m_i[i], mrow);
            float corr = expf(m_i[i] - mnew);
            float psum = 0.f;
#pragma unroll
            for (int j = 0; j < 4; j++) {
                float p = expf(sacc[i][j] - mnew);
                Ps[(ty * 4 + i) * PPAD + tx * 4 + j] = p;
                psum += p;
            }
#pragma unroll
            for (int off = 8; off >= 1; off >>= 1)
                psum += __shfl_xor_sync(0xffffffffu, psum, off);
            l_i[i] = l_i[i] * corr + psum;
            m_i[i] = mnew;
#pragma unroll
            for (int c = 0; c < 8; c++) o[i][c] *= corr;
        }
        __syncthreads();

        // O += P @ V  (this thread's cols: tx*8 .. tx*8+7)
        for (int k = 0; k < BN; k++) {
            float4 v0 = *(const float4*)&Vs[k * PADD + tx * 8];
            float4 v1 = *(const float4*)&Vs[k * PADD + tx * 8 + 4];
#pragma unroll
            for (int i = 0; i < 4; i++) {
                float p = Ps[(ty * 4 + i) * PPAD + k];
                o[i][0] = fmaf(p, v0.x, o[i][0]);
                o[i][1] = fmaf(p, v0.y, o[i][1]);
                o[i][2] = fmaf(p, v0.z, o[i][2]);
                o[i][3] = fmaf(p, v0.w, o[i][3]);
                o[i][4] = fmaf(p, v1.x, o[i][4]);
                o[i][5] = fmaf(p, v1.y, o[i][5]);
                o[i][6] = fmaf(p, v1.z, o[i][6]);
                o[i][7] = fmaf(p, v1.w, o[i][7]);
            }
        }
    }

    // Epilogue: normalize + write to [B,S,H*dk]
#pragma unroll
    for (int i = 0; i < 4; i++) {
        float inv = 1.0f / l_i[i];
        size_t row = (size_t)(b * S_LEN + qblk * BM + ty * 4 + i);
        float* dst = &g_attn[row * D_MODEL + (size_t)h * DK + tx * 8];
        float4 w0 = make_float4(o[i][0] * inv, o[i][1] * inv, o[i][2] * inv, o[i][3] * inv);
        float4 w1 = make_float4(o[i][4] * inv, o[i][5] * inv, o[i][6] * inv, o[i][7] * inv);
        *(float4*)&dst[0] = w0;
        *(float4*)&dst[4] = w1;
    }
}

// ---------------------------------------------------------------------------
// Launch
// ---------------------------------------------------------------------------
extern "C" void kernel_launch(void* const* d_in, const int* in_sizes, int n_in,
                              void* d_out, int out_size) {
    const float* x     = (const float*)d_in[0];
    const float* w_qkv = (const float*)d_in[1];
    const float* w_o   = (const float*)d_in[2];
    float* out = (float*)d_out;

    float *qkv_ptr, *attn_ptr;
    cudaGetSymbolAddress((void**)&qkv_ptr, g_qkv);
    cudaGetSymbolAddress((void**)&attn_ptr, g_attn);

    const int M = BATCH * S_LEN;          // 4096
    // 1) QKV projection: [4096,2048] @ [6144,2048]^T -> [4096,6144]
    {
        dim3 grid((3 * D_MODEL) / 128, M / 128);
        sgemm_nt<<<grid, 256>>>(x, w_qkv, qkv_ptr, M, 3 * D_MODEL, D_MODEL);
    }
    // 2) Rotary on Q and K
    {
        int n = BATCH * S_LEN * 2 * NH * 64;
        rotary_kernel<<<(n + 255) / 256, 256>>>();
    }
    // 3) Causal flash attention
    {
        size_t smem = (size_t)(BM * PADD + 2 * BN * PADD + BM * PPAD) * sizeof(float);
        cudaFuncSetAttribute(flash_kernel, cudaFuncAttributeMaxDynamicSharedMemorySize,
                             (int)smem);
        dim3 grid(S_LEN / BM, NH, BATCH);
        flash_kernel<<<grid, 256, smem>>>();
    }
    // 4) Output projection: [4096,2048] @ [2048,2048]^T -> [4096,2048]
    {
        dim3 grid(D_MODEL / 128, M / 128);
        sgemm_nt<<<grid, 256>>>(attn_ptr, w_o, out, M, D_MODEL, D_MODEL);
    }
}

// round 3
// speedup vs baseline: 1.6257x; 1.6257x over previous
#include <cuda_runtime.h>
#include <cuda_bf16.h>
#include <math.h>
#include <stdint.h>

#define D_MODEL 2048
#define NH 16
#define DK 128
#define S_LEN 2048
#define BATCH 2

#define XN   (4096 * 2048)
#define WQN  (6144 * 2048)
#define WON  (2048 * 2048)

// Scratch (device globals — no allocations allowed)
__device__ float g_qkv[(size_t)BATCH * S_LEN * 3 * D_MODEL];   // [B,S,3,H,dk] fp32
__device__ __nv_bfloat16 g_xhi[XN],  g_xlo[XN];
__device__ __nv_bfloat16 g_wqhi[WQN], g_wqlo[WQN];
__device__ __nv_bfloat16 g_wohi[WON], g_wolo[WON];
__device__ __nv_bfloat16 g_ahi[XN],  g_alo[XN];                // attention out hi/lo

// ===========================================================================
// PTX helpers (sm_100-safe: mma.sync / ldmatrix / cp.async)
// ===========================================================================
__device__ __forceinline__ uint32_t smem_u32(const void* p) {
    uint32_t a;
    asm("{ .reg .u64 t; cvta.to.shared.u64 t, %1; cvt.u32.u64 %0, t; }"
        : "=r"(a) : "l"(p));
    return a;
}
__device__ __forceinline__ void cp16(uint32_t dst, const void* src) {
    asm volatile("cp.async.cg.shared.global [%0], [%1], 16;"
                 :: "r"(dst), "l"(src) : "memory");
}
__device__ __forceinline__ void cp_commit() {
    asm volatile("cp.async.commit_group;" ::: "memory");
}
__device__ __forceinline__ void cp_wait0() {
    asm volatile("cp.async.wait_group 0;" ::: "memory");
}
__device__ __forceinline__ void ldm_x4(uint32_t* r, uint32_t addr) {
    asm volatile("ldmatrix.sync.aligned.m8n8.x4.shared.b16 {%0,%1,%2,%3}, [%4];"
                 : "=r"(r[0]), "=r"(r[1]), "=r"(r[2]), "=r"(r[3]) : "r"(addr));
}
__device__ __forceinline__ void mma_bf16(float* d, const uint32_t* a, const uint32_t* b) {
    asm volatile(
        "mma.sync.aligned.m16n8k16.row.col.f32.bf16.bf16.f32 "
        "{%0,%1,%2,%3}, {%4,%5,%6,%7}, {%8,%9}, {%0,%1,%2,%3};"
        : "+f"(d[0]), "+f"(d[1]), "+f"(d[2]), "+f"(d[3])
        : "r"(a[0]), "r"(a[1]), "r"(a[2]), "r"(a[3]), "r"(b[0]), "r"(b[1]));
}

// ===========================================================================
// Split fp32 -> bf16 hi + bf16 lo
// ===========================================================================
__global__ void split_kernel(const float* __restrict__ src,
                             __nv_bfloat16* __restrict__ hi,
                             __nv_bfloat16* __restrict__ lo, int n) {
    int i = blockIdx.x * blockDim.x + threadIdx.x;
    if (i >= n) return;
    float v = src[i];
    __nv_bfloat16 h = __float2bfloat16(v);
    hi[i] = h;
    lo[i] = __float2bfloat16(v - __bfloat162float(h));
}

// ===========================================================================
// HMMA GEMM: C[M,N] = A[M,K] @ B[N,K]^T, bf16 hi/lo 3-pass, fp32 accum.
// 128x128 CTA tile, BK=32, 8 warps (64x32 each), cp.async double buffer.
// ===========================================================================
#define BK 32
#define ASTRIDE 40                        // bf16 elems per smem row (32 + 8 pad)
#define TILE_B (128 * ASTRIDE * 2)        // 10240 B per tile
#define STAGE_B (4 * TILE_B)              // Ahi,Alo,Bhi,Blo = 40960 B
#define GEMM_SMEM (2 * STAGE_B)           // 81920 B

__global__ __launch_bounds__(256, 1)
void gemm_hmma_x3(const __nv_bfloat16* __restrict__ Ahi, const __nv_bfloat16* __restrict__ Alo,
                  const __nv_bfloat16* __restrict__ Bhi, const __nv_bfloat16* __restrict__ Blo,
                  float* __restrict__ C, int M, int N, int K) {
    extern __shared__ char dynsmem[];
    const uint32_t sbase = smem_u32(dynsmem);

    const int tid  = (int)threadIdx.x;
    const int wid  = tid >> 5;
    const int lane = tid & 31;
    const int bm = blockIdx.y * 128, bn = blockIdx.x * 128;
    const int wm = wid & 1;               // 0..1 -> 64-row half
    const int wn = wid >> 1;              // 0..3 -> 32-col quarter

    const __nv_bfloat16* srcs[4] = {
        Ahi + (size_t)bm * K, Alo + (size_t)bm * K,
        Bhi + (size_t)bn * K, Blo + (size_t)bn * K };

    // cp.async mapping: 8 x 16B per thread per stage
    // linear = i*256 + tid; tile = linear>>9; row = (linear>>2)&127; c16 = linear&3
    auto load_stage = [&](int stage, int k0) {
        const uint32_t stg = sbase + stage * STAGE_B;
#pragma unroll
        for (int i = 0; i < 8; i++) {
            int linear = i * 256 + tid;
            int t   = linear >> 9;
            int row = (linear >> 2) & 127;
            int c16 = linear & 3;
            const __nv_bfloat16* src = srcs[t] + (size_t)row * K + k0 + c16 * 8;
            cp16(stg + t * TILE_B + (row * ASTRIDE + c16 * 8) * 2, src);
        }
        cp_commit();
    };

    float acc[4][4][4];
#pragma unroll
    for (int i = 0; i < 4; i++)
#pragma unroll
        for (int j = 0; j < 4; j++)
#pragma unroll
            for (int c = 0; c < 4; c++) acc[i][j][c] = 0.f;

    // Per-lane ldmatrix address components
    const int arow = wm * 64 + (lane & 7) + ((lane >> 3) & 1) * 8;   // + mt*16
    const int acol = ((lane >> 4) & 1) * 8;                          // + ks*16
    const int brow = wn * 32 + (lane & 7) + ((lane >> 4) & 1) * 8;   // + jp*16
    const int bcol = ((lane >> 3) & 1) * 8;                          // + ks*16

    const int nk = K / BK;
    load_stage(0, 0);

    for (int c = 0; c < nk; c++) {
        cp_wait0();
        __syncthreads();
        if (c + 1 < nk) load_stage((c + 1) & 1, (c + 1) * BK);

        const uint32_t stg = sbase + (c & 1) * STAGE_B;
        const uint32_t sAhi = stg;
        const uint32_t sAlo = stg + TILE_B;
        const uint32_t sBhi = stg + 2 * TILE_B;
        const uint32_t sBlo = stg + 3 * TILE_B;

#pragma unroll
        for (int ks = 0; ks < 2; ks++) {
            uint32_t ahi[4][4], alo[4][4];
            uint32_t bhi[4][2], blo[4][2];
#pragma unroll
            for (int mt = 0; mt < 4; mt++) {
                uint32_t off = (uint32_t)(((arow + mt * 16) * ASTRIDE) + ks * 16 + acol) * 2;
                ldm_x4(ahi[mt], sAhi + off);
                ldm_x4(alo[mt], sAlo + off);
            }
#pragma unroll
            for (int jp = 0; jp < 2; jp++) {
                uint32_t off = (uint32_t)(((brow + jp * 16) * ASTRIDE) + ks * 16 + bcol) * 2;
                uint32_t r[4];
                ldm_x4(r, sBhi + off);
                bhi[jp * 2][0] = r[0]; bhi[jp * 2][1] = r[1];
                bhi[jp * 2 + 1][0] = r[2]; bhi[jp * 2 + 1][1] = r[3];
                ldm_x4(r, sBlo + off);
                blo[jp * 2][0] = r[0]; blo[jp * 2][1] = r[1];
                blo[jp * 2 + 1][0] = r[2]; blo[jp * 2 + 1][1] = r[3];
            }
#pragma unroll
            for (int mt = 0; mt < 4; mt++)
#pragma unroll
                for (int nt = 0; nt < 4; nt++) {
                    mma_bf16(acc[mt][nt], ahi[mt], bhi[nt]);
                    mma_bf16(acc[mt][nt], ahi[mt], blo[nt]);
                    mma_bf16(acc[mt][nt], alo[mt], bhi[nt]);
                }
        }
        __syncthreads();
    }

    // Epilogue: fragment layout -> C
    const int g = lane >> 2, t = lane & 3;
#pragma unroll
    for (int mt = 0; mt < 4; mt++) {
#pragma unroll
        for (int nt = 0; nt < 4; nt++) {
            size_t r0 = (size_t)(bm + wm * 64 + mt * 16 + g);
            int col = bn + wn * 32 + nt * 8 + t * 2;
            *(float2*)&C[r0 * N + col] = make_float2(acc[mt][nt][0], acc[mt][nt][1]);
            *(float2*)&C[(r0 + 8) * N + col] = make_float2(acc[mt][nt][2], acc[mt][nt][3]);
        }
    }
}

// ===========================================================================
// Rotary: in-place on Q (t=0) and K (t=1) halves of g_qkv.
// ===========================================================================
__global__ void rotary_kernel() {
    int idx = blockIdx.x * blockDim.x + threadIdx.x;
    const int total = BATCH * S_LEN * 2 * NH * 64;
    if (idx >= total) return;
    int j = idx & 63;
    int h = (idx >> 6) & 15;
    int t = (idx >> 10) & 1;
    int s = (idx >> 11) & (S_LEN - 1);
    int b = idx >> 22;

    float freq = expf((float)j * (-9.210340371976184f / 63.0f));
    float theta = (float)s * freq;
    float sn, cs;
    sincosf(theta, &sn, &cs);

    size_t base = (((size_t)(b * S_LEN + s)) * 3 + t) * (size_t)D_MODEL + (size_t)h * DK;
    float x1 = g_qkv[base + j];
    float x2 = g_qkv[base + 64 + j];
    g_qkv[base + j]      = x1 * cs - x2 * sn;
    g_qkv[base + 64 + j] = x1 * sn + x2 * cs;
}

// ===========================================================================
// Causal flash attention, fp32; epilogue emits bf16 hi/lo.
// ===========================================================================
#define BM 64
#define BN 64
#define PADD 132
#define PPAD 68

__global__ void flash_kernel() {
    extern __shared__ float sm[];
    float* Qs = sm;
    float* Ks = Qs + BM * PADD;
    float* Vs = Ks + BN * PADD;
    float* Ps = Vs + BN * PADD;

    const int qblk = blockIdx.x;
    const int h = blockIdx.y;
    const int b = blockIdx.z;
    const int tid = (int)threadIdx.x;
    const int tx = tid & 15;
    const int ty = tid >> 4;
    const float scale = 0.08838834764831845f;

    for (int e = tid; e < BM * (DK / 4); e += 256) {
        int r = e >> 5;
        int c4 = e & 31;
        size_t g = (((size_t)(b * S_LEN + qblk * BM + r)) * 3 + 0) * (size_t)D_MODEL
                   + (size_t)h * DK + c4 * 4;
        *(float4*)&Qs[r * PADD + c4 * 4] = *(const float4*)&g_qkv[g];
    }

    float m_i[4], l_i[4], o[4][8];
#pragma unroll
    for (int i = 0; i < 4; i++) {
        m_i[i] = -1e30f;
        l_i[i] = 0.f;
#pragma unroll
        for (int c = 0; c < 8; c++) o[i][c] = 0.f;
    }

    for (int jblk = 0; jblk <= qblk; jblk++) {
        __syncthreads();
        for (int e = tid; e < BN * (DK / 4); e += 256) {
            int r = e >> 5;
            int c4 = e & 31;
            size_t rowbase = (size_t)(b * S_LEN + jblk * BN + r) * 3;
            size_t gk = (rowbase + 1) * (size_t)D_MODEL + (size_t)h * DK + c4 * 4;
            size_t gv = (rowbase + 2) * (size_t)D_MODEL + (size_t)h * DK + c4 * 4;
            *(float4*)&Ks[r * PADD + c4 * 4] = *(const float4*)&g_qkv[gk];
            *(float4*)&Vs[r * PADD + c4 * 4] = *(const float4*)&g_qkv[gv];
        }
        __syncthreads();

        float sacc[4][4];
#pragma unroll
        for (int i = 0; i < 4; i++)
#pragma unroll
            for (int j = 0; j < 4; j++) sacc[i][j] = 0.f;

        for (int d4 = 0; d4 < DK / 4; d4++) {
            float4 qa[4], kb[4];
#pragma unroll
            for (int i = 0; i < 4; i++)
                qa[i] = *(const float4*)&Qs[(ty * 4 + i) * PADD + d4 * 4];
#pragma unroll
            for (int j = 0; j < 4; j++)
                kb[j] = *(const float4*)&Ks[(tx * 4 + j) * PADD + d4 * 4];
#pragma unroll
            for (int i = 0; i < 4; i++)
#pragma unroll
                for (int j = 0; j < 4; j++) {
                    sacc[i][j] = fmaf(qa[i].x, kb[j].x, sacc[i][j]);
                    sacc[i][j] = fmaf(qa[i].y, kb[j].y, sacc[i][j]);
                    sacc[i][j] = fmaf(qa[i].z, kb[j].z, sacc[i][j]);
                    sacc[i][j] = fmaf(qa[i].w, kb[j].w, sacc[i][j]);
                }
        }

        const int qbase = qblk * BM + ty * 4;
        const int kbase = jblk * BN + tx * 4;
#pragma unroll
        for (int i = 0; i < 4; i++)
#pragma unroll
            for (int j = 0; j < 4; j++) {
                float sv = sacc[i][j] * scale;
                if (kbase + j > qbase + i) sv = -1e30f;
                sacc[i][j] = sv;
            }

#pragma unroll
        for (int i = 0; i < 4; i++) {
            float mrow = fmaxf(fmaxf(sacc[i][0], sacc[i][1]),
                               fmaxf(sacc[i][2], sacc[i][3]));
#pragma unroll
            for (int off = 8; off >= 1; off >>= 1)
                mrow = fmaxf(mrow, __shfl_xor_sync(0xffffffffu, mrow, off));
            float mnew = fmaxf(m_i[i], mrow);
            float corr = expf(m_i[i] - mnew);
            float psum = 0.f;
#pragma unroll
            for (int j = 0; j < 4; j++) {
                float p = expf(sacc[i][j] - mnew);
                Ps[(ty * 4 + i) * PPAD + tx * 4 + j] = p;
                psum += p;
            }
#pragma unroll
            for (int off = 8; off >= 1; off >>= 1)
                psum += __shfl_xor_sync(0xffffffffu, psum, off);
            l_i[i] = l_i[i] * corr + psum;
            m_i[i] = mnew;
#pragma unroll
            for (int c = 0; c < 8; c++) o[i][c] *= corr;
        }
        __syncthreads();

        for (int k = 0; k < BN; k++) {
            float4 v0 = *(const float4*)&Vs[k * PADD + tx * 8];
            float4 v1 = *(const float4*)&Vs[k * PADD + tx * 8 + 4];
#pragma unroll
            for (int i = 0; i < 4; i++) {
                float p = Ps[(ty * 4 + i) * PPAD + k];
                o[i][0] = fmaf(p, v0.x, o[i][0]);
                o[i][1] = fmaf(p, v0.y, o[i][1]);
                o[i][2] = fmaf(p, v0.z, o[i][2]);
                o[i][3] = fmaf(p, v0.w, o[i][3]);
                o[i][4] = fmaf(p, v1.x, o[i][4]);
                o[i][5] = fmaf(p, v1.y, o[i][5]);
                o[i][6] = fmaf(p, v1.z, o[i][6]);
                o[i][7] = fmaf(p, v1.w, o[i][7]);
            }
        }
    }

    // Epilogue: normalize, split to bf16 hi/lo
#pragma unroll
    for (int i = 0; i < 4; i++) {
        float inv = 1.0f / l_i[i];
        size_t row = (size_t)(b * S_LEN + qblk * BM + ty * 4 + i);
        size_t off = row * D_MODEL + (size_t)h * DK + tx * 8;
        __align__(16) __nv_bfloat16 hv[8];
        __align__(16) __nv_bfloat16 lv[8];
#pragma unroll
        for (int c = 0; c < 8; c++) {
            float v = o[i][c] * inv;
            __nv_bfloat16 h16 = __float2bfloat16(v);
            hv[c] = h16;
            lv[c] = __float2bfloat16(v - __bfloat162float(h16));
        }
        *(uint4*)&g_ahi[off] = *(const uint4*)hv;
        *(uint4*)&g_alo[off] = *(const uint4*)lv;
    }
}

// ===========================================================================
// Launch
// ===========================================================================
extern "C" void kernel_launch(void* const* d_in, const int* in_sizes, int n_in,
                              void* d_out, int out_size) {
    const float* x     = (const float*)d_in[0];
    const float* w_qkv = (const float*)d_in[1];
    const float* w_o   = (const float*)d_in[2];
    float* out = (float*)d_out;

    float* qkv_ptr;
    __nv_bfloat16 *xhi, *xlo, *wqhi, *wqlo, *wohi, *wolo, *ahi, *alo;
    cudaGetSymbolAddress((void**)&qkv_ptr, g_qkv);
    cudaGetSymbolAddress((void**)&xhi, g_xhi);
    cudaGetSymbolAddress((void**)&xlo, g_xlo);
    cudaGetSymbolAddress((void**)&wqhi, g_wqhi);
    cudaGetSymbolAddress((void**)&wqlo, g_wqlo);
    cudaGetSymbolAddress((void**)&wohi, g_wohi);
    cudaGetSymbolAddress((void**)&wolo, g_wolo);
    cudaGetSymbolAddress((void**)&ahi, g_ahi);
    cudaGetSymbolAddress((void**)&alo, g_alo);

    const int M = BATCH * S_LEN;  // 4096

    // 0) Split inputs to bf16 hi/lo
    split_kernel<<<(XN + 255) / 256, 256>>>(x, xhi, xlo, XN);
    split_kernel<<<(WQN + 255) / 256, 256>>>(w_qkv, wqhi, wqlo, WQN);
    split_kernel<<<(WON + 255) / 256, 256>>>(w_o, wohi, wolo, WON);

    cudaFuncSetAttribute(gemm_hmma_x3, cudaFuncAttributeMaxDynamicSharedMemorySize,
                         GEMM_SMEM);

    // 1) QKV projection: [4096,2048] @ [6144,2048]^T -> [4096,6144] fp32
    {
        dim3 grid((3 * D_MODEL) / 128, M / 128);
        gemm_hmma_x3<<<grid, 256, GEMM_SMEM>>>(xhi, xlo, wqhi, wqlo, qkv_ptr,
                                               M, 3 * D_MODEL, D_MODEL);
    }
    // 2) Rotary on Q and K
    {
        int n = BATCH * S_LEN * 2 * NH * 64;
        rotary_kernel<<<(n + 255) / 256, 256>>>();
    }
    // 3) Causal flash attention (fp32), emits bf16 hi/lo
    {
        size_t smem = (size_t)(BM * PADD + 2 * BN * PADD + BM * PPAD) * sizeof(float);
        cudaFuncSetAttribute(flash_kernel, cudaFuncAttributeMaxDynamicSharedMemorySize,
                             (int)smem);
        dim3 grid(S_LEN / BM, NH, BATCH);
        flash_kernel<<<grid, 256, smem>>>();
    }
    // 4) Output projection: [4096,2048] @ [2048,2048]^T -> [4096,2048] fp32
    {
        dim3 grid(D_MODEL / 128, M / 128);
        gemm_hmma_x3<<<grid, 256, GEMM_SMEM>>>(ahi, alo, wohi, wolo, out,
                                               M, D_MODEL, D_MODEL);
    }
}

// round 6
// speedup vs baseline: 3.0723x; 1.8898x over previous
#include <cuda_runtime.h>
#include <cuda_bf16.h>
#include <math.h>
#include <stdint.h>

#define D_MODEL 2048
#define NH 16
#define DK 128
#define S_LEN 2048
#define BATCH 2

#define XN   (4096 * 2048)
#define WQN  (6144 * 2048)
#define WON  (2048 * 2048)
#define QKVN (BATCH * NH * S_LEN * DK)    // 8.4M per tensor

// Scratch (device globals — no allocations allowed)
__device__ float g_qkv[(size_t)BATCH * S_LEN * 3 * D_MODEL];   // [B,S,3,H,dk] fp32
__device__ __nv_bfloat16 g_xhi[XN],  g_xlo[XN];
__device__ __nv_bfloat16 g_wqhi[WQN], g_wqlo[WQN];
__device__ __nv_bfloat16 g_wohi[WON], g_wolo[WON];
__device__ __nv_bfloat16 g_ahi[XN],  g_alo[XN];                // attention out hi/lo
// Rope-split Q/K/V, head-major [B,H,S,dk]
__device__ __nv_bfloat16 g_q_hi[QKVN], g_q_lo[QKVN];
__device__ __nv_bfloat16 g_k_hi[QKVN], g_k_lo[QKVN];
__device__ __nv_bfloat16 g_v_hi[QKVN], g_v_lo[QKVN];

// ===========================================================================
// PTX helpers (sm_100-safe: mma.sync / ldmatrix / cp.async)
// ===========================================================================
__device__ __forceinline__ uint32_t smem_u32(const void* p) {
    uint32_t a;
    asm("{ .reg .u64 t; cvta.to.shared.u64 t, %1; cvt.u32.u64 %0, t; }"
        : "=r"(a) : "l"(p));
    return a;
}
__device__ __forceinline__ void cp16(uint32_t dst, const void* src) {
    asm volatile("cp.async.cg.shared.global [%0], [%1], 16;"
                 :: "r"(dst), "l"(src) : "memory");
}
__device__ __forceinline__ void cp_commit() {
    asm volatile("cp.async.commit_group;" ::: "memory");
}
__device__ __forceinline__ void cp_wait0() {
    asm volatile("cp.async.wait_group 0;" ::: "memory");
}
__device__ __forceinline__ void cp_wait1() {
    asm volatile("cp.async.wait_group 1;" ::: "memory");
}
__device__ __forceinline__ void ldm_x4(uint32_t* r, uint32_t addr) {
    asm volatile("ldmatrix.sync.aligned.m8n8.x4.shared.b16 {%0,%1,%2,%3}, [%4];"
                 : "=r"(r[0]), "=r"(r[1]), "=r"(r[2]), "=r"(r[3]) : "r"(addr));
}
__device__ __forceinline__ void ldm_x4_t(uint32_t* r, uint32_t addr) {
    asm volatile("ldmatrix.sync.aligned.m8n8.x4.trans.shared.b16 {%0,%1,%2,%3}, [%4];"
                 : "=r"(r[0]), "=r"(r[1]), "=r"(r[2]), "=r"(r[3]) : "r"(addr));
}
__device__ __forceinline__ void mma_bf16(float* d, const uint32_t* a, const uint32_t* b) {
    asm volatile(
        "mma.sync.aligned.m16n8k16.row.col.f32.bf16.bf16.f32 "
        "{%0,%1,%2,%3}, {%4,%5,%6,%7}, {%8,%9}, {%0,%1,%2,%3};"
        : "+f"(d[0]), "+f"(d[1]), "+f"(d[2]), "+f"(d[3])
        : "r"(a[0]), "r"(a[1]), "r"(a[2]), "r"(a[3]), "r"(b[0]), "r"(b[1]));
}
__device__ __forceinline__ void pack_hl(float a, float b, uint32_t& h, uint32_t& l) {
    __nv_bfloat162 hb = __floats2bfloat162_rn(a, b);
    h = *(uint32_t*)&hb;
    float ra = a - __bfloat162float(hb.x);
    float rb = b - __bfloat162float(hb.y);
    __nv_bfloat162 lb = __floats2bfloat162_rn(ra, rb);
    l = *(uint32_t*)&lb;
}

// ===========================================================================
// Split fp32 -> bf16 hi + bf16 lo
// ===========================================================================
__global__ void split_kernel(const float* __restrict__ src,
                             __nv_bfloat16* __restrict__ hi,
                             __nv_bfloat16* __restrict__ lo, int n) {
    int i = blockIdx.x * blockDim.x + threadIdx.x;
    if (i >= n) return;
    float v = src[i];
    __nv_bfloat16 h = __float2bfloat16(v);
    hi[i] = h;
    lo[i] = __float2bfloat16(v - __bfloat162float(h));
}

// ===========================================================================
// HMMA GEMM: C[M,N] = A[M,K] @ B[N,K]^T, bf16 hi/lo 3-pass, fp32 accum.
// 128x128 CTA tile, BK=32, 8 warps, 3-stage cp.async pipeline.
// ===========================================================================
#define BK 32
#define ASTRIDE 40                        // bf16 elems per smem row (32 + 8 pad)
#define TILE_B (128 * ASTRIDE * 2)        // 10240 B per tile
#define STAGE_B (4 * TILE_B)              // Ahi,Alo,Bhi,Blo = 40960 B
#define GEMM_SMEM (3 * STAGE_B)           // 122880 B

__global__ __launch_bounds__(256, 1)
void gemm_hmma_x3(const __nv_bfloat16* __restrict__ Ahi, const __nv_bfloat16* __restrict__ Alo,
                  const __nv_bfloat16* __restrict__ Bhi, const __nv_bfloat16* __restrict__ Blo,
                  float* __restrict__ C, int M, int N, int K) {
    extern __shared__ char dynsmem[];
    const uint32_t sbase = smem_u32(dynsmem);

    const int tid  = (int)threadIdx.x;
    const int wid  = tid >> 5;
    const int lane = tid & 31;
    const int bm = blockIdx.y * 128, bn = blockIdx.x * 128;
    const int wm = wid & 1;
    const int wn = wid >> 1;

    const __nv_bfloat16* srcs[4] = {
        Ahi + (size_t)bm * K, Alo + (size_t)bm * K,
        Bhi + (size_t)bn * K, Blo + (size_t)bn * K };

    auto load_stage = [&](int stage, int k0) {
        const uint32_t stg = sbase + stage * STAGE_B;
#pragma unroll
        for (int i = 0; i < 8; i++) {
            int linear = i * 256 + tid;
            int t   = linear >> 9;
            int row = (linear >> 2) & 127;
            int c16 = linear & 3;
            const __nv_bfloat16* src = srcs[t] + (size_t)row * K + k0 + c16 * 8;
            cp16(stg + t * TILE_B + (row * ASTRIDE + c16 * 8) * 2, src);
        }
        cp_commit();
    };

    float acc[4][4][4];
#pragma unroll
    for (int i = 0; i < 4; i++)
#pragma unroll
        for (int j = 0; j < 4; j++)
#pragma unroll
            for (int c = 0; c < 4; c++) acc[i][j][c] = 0.f;

    const int arow = wm * 64 + (lane & 7) + ((lane >> 3) & 1) * 8;
    const int acol = ((lane >> 4) & 1) * 8;
    const int brow = wn * 32 + (lane & 7) + ((lane >> 4) & 1) * 8;
    const int bcol = ((lane >> 3) & 1) * 8;

    const int nk = K / BK;
    load_stage(0, 0);
    if (nk > 1) load_stage(1, BK);

    for (int c = 0; c < nk; c++) {
        if (c < nk - 1) cp_wait1(); else cp_wait0();
        __syncthreads();
        if (c + 2 < nk) load_stage((c + 2) % 3, (c + 2) * BK);

        const uint32_t stg = sbase + (c % 3) * STAGE_B;
        const uint32_t sAhi = stg;
        const uint32_t sAlo = stg + TILE_B;
        const uint32_t sBhi = stg + 2 * TILE_B;
        const uint32_t sBlo = stg + 3 * TILE_B;

#pragma unroll
        for (int ks = 0; ks < 2; ks++) {
            uint32_t ahi[4][4], alo[4][4];
            uint32_t bhi[4][2], blo[4][2];
#pragma unroll
            for (int mt = 0; mt < 4; mt++) {
                uint32_t off = (uint32_t)(((arow + mt * 16) * ASTRIDE) + ks * 16 + acol) * 2;
                ldm_x4(ahi[mt], sAhi + off);
                ldm_x4(alo[mt], sAlo + off);
            }
#pragma unroll
            for (int jp = 0; jp < 2; jp++) {
                uint32_t off = (uint32_t)(((brow + jp * 16) * ASTRIDE) + ks * 16 + bcol) * 2;
                uint32_t r[4];
                ldm_x4(r, sBhi + off);
                bhi[jp * 2][0] = r[0]; bhi[jp * 2][1] = r[1];
                bhi[jp * 2 + 1][0] = r[2]; bhi[jp * 2 + 1][1] = r[3];
                ldm_x4(r, sBlo + off);
                blo[jp * 2][0] = r[0]; blo[jp * 2][1] = r[1];
                blo[jp * 2 + 1][0] = r[2]; blo[jp * 2 + 1][1] = r[3];
            }
#pragma unroll
            for (int mt = 0; mt < 4; mt++)
#pragma unroll
                for (int nt = 0; nt < 4; nt++) {
                    mma_bf16(acc[mt][nt], ahi[mt], bhi[nt]);
                    mma_bf16(acc[mt][nt], ahi[mt], blo[nt]);
                    mma_bf16(acc[mt][nt], alo[mt], bhi[nt]);
                }
        }
        __syncthreads();
    }

    const int g = lane >> 2, t = lane & 3;
#pragma unroll
    for (int mt = 0; mt < 4; mt++) {
#pragma unroll
        for (int nt = 0; nt < 4; nt++) {
            size_t r0 = (size_t)(bm + wm * 64 + mt * 16 + g);
            int col = bn + wn * 32 + nt * 8 + t * 2;
            *(float2*)&C[r0 * N + col] = make_float2(acc[mt][nt][0], acc[mt][nt][1]);
            *(float2*)&C[(r0 + 8) * N + col] = make_float2(acc[mt][nt][2], acc[mt][nt][3]);
        }
    }
}

// ===========================================================================
// Rope + split: g_qkv fp32 -> Q/K (rotated) and V, bf16 hi/lo, [B,H,S,dk].
// ===========================================================================
__global__ void rope_split_kernel() {
    int idx = blockIdx.x * blockDim.x + threadIdx.x;
    const int total = BATCH * NH * S_LEN * 64;   // 2^22
    if (idx >= total) return;
    int j = idx & 63;
    int s = (idx >> 6) & (S_LEN - 1);
    int h = (idx >> 17) & 15;
    int b = idx >> 21;

    float freq = expf((float)j * (-9.210340371976184f / 63.0f));
    float theta = (float)s * freq;
    float sn, cs;
    sincosf(theta, &sn, &cs);

    size_t ibase = ((size_t)(b * S_LEN + s)) * 3 * (size_t)D_MODEL + (size_t)h * DK;
    size_t obase = (((size_t)(b * NH + h)) * S_LEN + s) * (size_t)DK;

    // Q (t=0)
    {
        float x1 = g_qkv[ibase + j], x2 = g_qkv[ibase + 64 + j];
        float y1 = x1 * cs - x2 * sn;
        float y2 = x1 * sn + x2 * cs;
        __nv_bfloat16 h1 = __float2bfloat16(y1), h2 = __float2bfloat16(y2);
        g_q_hi[obase + j] = h1;      g_q_lo[obase + j] = __float2bfloat16(y1 - __bfloat162float(h1));
        g_q_hi[obase + 64 + j] = h2; g_q_lo[obase + 64 + j] = __float2bfloat16(y2 - __bfloat162float(h2));
    }
    // K (t=1)
    {
        float x1 = g_qkv[ibase + D_MODEL + j], x2 = g_qkv[ibase + D_MODEL + 64 + j];
        float y1 = x1 * cs - x2 * sn;
        float y2 = x1 * sn + x2 * cs;
        __nv_bfloat16 h1 = __float2bfloat16(y1), h2 = __float2bfloat16(y2);
        g_k_hi[obase + j] = h1;      g_k_lo[obase + j] = __float2bfloat16(y1 - __bfloat162float(h1));
        g_k_hi[obase + 64 + j] = h2; g_k_lo[obase + 64 + j] = __float2bfloat16(y2 - __bfloat162float(h2));
    }
    // V (t=2), passthrough split
    {
        float x1 = g_qkv[ibase + 2 * D_MODEL + j], x2 = g_qkv[ibase + 2 * D_MODEL + 64 + j];
        __nv_bfloat16 h1 = __float2bfloat16(x1), h2 = __float2bfloat16(x2);
        g_v_hi[obase + j] = h1;      g_v_lo[obase + j] = __float2bfloat16(x1 - __bfloat162float(h1));
        g_v_hi[obase + 64 + j] = h2; g_v_lo[obase + 64 + j] = __float2bfloat16(x2 - __bfloat162float(h2));
    }
}

// ===========================================================================
// HMMA causal flash attention. 128 threads (4 warps), BM=64 (16 q-rows/warp),
// BN=64 kv per iter, dk=128. hi/lo 3-pass for QK and PV. fp32 softmax.
// ===========================================================================
#define FSTR 136                          // smem row stride in bf16 elems (128 + 8)
#define FTILE (64 * FSTR)                 // elems per tile
#define FLASH_SMEM (6 * FTILE * 2)        // 104448 B

__global__ __launch_bounds__(128, 1)
void flash_hmma() {
    extern __shared__ __nv_bfloat16 fsm[];
    const uint32_t sb = smem_u32(fsm);
    const uint32_t sQh = sb;
    const uint32_t sQl = sb + 1 * FTILE * 2;
    const uint32_t sKh = sb + 2 * FTILE * 2;
    const uint32_t sKl = sb + 3 * FTILE * 2;
    const uint32_t sVh = sb + 4 * FTILE * 2;
    const uint32_t sVl = sb + 5 * FTILE * 2;

    const int qblk = blockIdx.x, h = blockIdx.y, b = blockIdx.z;
    const int tid = (int)threadIdx.x;
    const int w = tid >> 5, lane = tid & 31;
    const int g = lane >> 2, t4 = lane & 3;
    const float scale = 0.08838834764831845f;   // 1/sqrt(128)

    const size_t hbase = (((size_t)(b * NH + h)) * S_LEN) * (size_t)DK;

    // Load Q tiles (hi/lo): 64 rows x 128 elems each
    {
        const __nv_bfloat16* qh = g_q_hi + hbase + (size_t)qblk * 64 * DK;
        const __nv_bfloat16* ql = g_q_lo + hbase + (size_t)qblk * 64 * DK;
#pragma unroll
        for (int i = 0; i < 8; i++) {
            int e = i * 128 + tid;
            int row = e >> 4, c16 = e & 15;
            uint4 v = *(const uint4*)(qh + (size_t)row * DK + c16 * 8);
            *(uint4*)(fsm + 0 * FTILE + row * FSTR + c16 * 8) = v;
            v = *(const uint4*)(ql + (size_t)row * DK + c16 * 8);
            *(uint4*)(fsm + 1 * FTILE + row * FSTR + c16 * 8) = v;
        }
    }

    float o[16][4];
    float m_i[2] = {-1e30f, -1e30f}, l_i[2] = {0.f, 0.f};
#pragma unroll
    for (int nb = 0; nb < 16; nb++)
#pragma unroll
        for (int e = 0; e < 4; e++) o[nb][e] = 0.f;

    // ldmatrix address components
    const int aQrow = w * 16 + (lane & 7) + ((lane >> 3) & 1) * 8;
    const int aQcol = ((lane >> 4) & 1) * 8;
    const int bKrow = (lane & 7) + ((lane >> 4) & 1) * 8;   // + jp*16
    const int bKcol = ((lane >> 3) & 1) * 8;                // + k16*16
    const int vRow  = (lane & 7) + ((lane >> 3) & 1) * 8;   // + j*16
    const int vCol  = ((lane >> 4) & 1) * 8;                // + nt2*16

    for (int jblk = 0; jblk <= qblk; jblk++) {
        __syncthreads();
        // Load K/V (hi/lo) for this block
        {
            const size_t base = hbase + (size_t)jblk * 64 * DK;
#pragma unroll
            for (int i = 0; i < 8; i++) {
                int e = i * 128 + tid;
                int row = e >> 4, c16 = e & 15;
                size_t go = base + (size_t)row * DK + c16 * 8;
                int so = row * FSTR + c16 * 8;
                *(uint4*)(fsm + 2 * FTILE + so) = *(const uint4*)(g_k_hi + go);
                *(uint4*)(fsm + 3 * FTILE + so) = *(const uint4*)(g_k_lo + go);
                *(uint4*)(fsm + 4 * FTILE + so) = *(const uint4*)(g_v_hi + go);
                *(uint4*)(fsm + 5 * FTILE + so) = *(const uint4*)(g_v_lo + go);
            }
        }
        __syncthreads();

        // ---- QK^T ----  (each warp covers ALL 64 kv cols: jp = 0..3)
        float sc[8][4];
#pragma unroll
        for (int nt = 0; nt < 8; nt++)
#pragma unroll
            for (int e = 0; e < 4; e++) sc[nt][e] = 0.f;

#pragma unroll
        for (int k16 = 0; k16 < 8; k16++) {
            uint32_t qh[4], ql[4];
            uint32_t qoff = (uint32_t)(aQrow * FSTR + k16 * 16 + aQcol) * 2;
            ldm_x4(qh, sQh + qoff);
            ldm_x4(ql, sQl + qoff);
#pragma unroll
            for (int jp = 0; jp < 4; jp++) {
                uint32_t koff = (uint32_t)((bKrow + jp * 16) * FSTR + k16 * 16 + bKcol) * 2;
                uint32_t kh[4], kl[4];
                ldm_x4(kh, sKh + koff);
                ldm_x4(kl, sKl + koff);
                mma_bf16(sc[jp * 2],     qh, &kh[0]);
                mma_bf16(sc[jp * 2],     qh, &kl[0]);
                mma_bf16(sc[jp * 2],     ql, &kh[0]);
                mma_bf16(sc[jp * 2 + 1], qh, &kh[2]);
                mma_bf16(sc[jp * 2 + 1], qh, &kl[2]);
                mma_bf16(sc[jp * 2 + 1], ql, &kh[2]);
            }
        }

        // ---- scale + causal mask ----
#pragma unroll
        for (int nt = 0; nt < 8; nt++)
#pragma unroll
            for (int e = 0; e < 4; e++) sc[nt][e] *= scale;
        if (jblk == qblk) {
            const int qr0 = w * 16 + g, qr1 = qr0 + 8;
#pragma unroll
            for (int nt = 0; nt < 8; nt++) {
                int kc = nt * 8 + t4 * 2;
                if (kc > qr0)     sc[nt][0] = -1e30f;
                if (kc + 1 > qr0) sc[nt][1] = -1e30f;
                if (kc > qr1)     sc[nt][2] = -1e30f;
                if (kc + 1 > qr1) sc[nt][3] = -1e30f;
            }
        }

        // ---- online softmax (rows g, g+8) ----
        float r0 = -1e30f, r1 = -1e30f;
#pragma unroll
        for (int nt = 0; nt < 8; nt++) {
            r0 = fmaxf(r0, fmaxf(sc[nt][0], sc[nt][1]));
            r1 = fmaxf(r1, fmaxf(sc[nt][2], sc[nt][3]));
        }
        r0 = fmaxf(r0, __shfl_xor_sync(0xffffffffu, r0, 1));
        r0 = fmaxf(r0, __shfl_xor_sync(0xffffffffu, r0, 2));
        r1 = fmaxf(r1, __shfl_xor_sync(0xffffffffu, r1, 1));
        r1 = fmaxf(r1, __shfl_xor_sync(0xffffffffu, r1, 2));
        float mnew0 = fmaxf(m_i[0], r0), mnew1 = fmaxf(m_i[1], r1);
        float corr0 = __expf(m_i[0] - mnew0), corr1 = __expf(m_i[1] - mnew1);
        m_i[0] = mnew0; m_i[1] = mnew1;

        float sum0 = 0.f, sum1 = 0.f;
#pragma unroll
        for (int nt = 0; nt < 8; nt++) {
            sc[nt][0] = __expf(sc[nt][0] - mnew0);
            sc[nt][1] = __expf(sc[nt][1] - mnew0);
            sc[nt][2] = __expf(sc[nt][2] - mnew1);
            sc[nt][3] = __expf(sc[nt][3] - mnew1);
            sum0 += sc[nt][0] + sc[nt][1];
            sum1 += sc[nt][2] + sc[nt][3];
        }
        sum0 += __shfl_xor_sync(0xffffffffu, sum0, 1);
        sum0 += __shfl_xor_sync(0xffffffffu, sum0, 2);
        sum1 += __shfl_xor_sync(0xffffffffu, sum1, 1);
        sum1 += __shfl_xor_sync(0xffffffffu, sum1, 2);
        l_i[0] = l_i[0] * corr0 + sum0;
        l_i[1] = l_i[1] * corr1 + sum1;

#pragma unroll
        for (int nb = 0; nb < 16; nb++) {
            o[nb][0] *= corr0; o[nb][1] *= corr0;
            o[nb][2] *= corr1; o[nb][3] *= corr1;
        }

        // ---- P -> A fragments (register-only, hi/lo) ----
        uint32_t ph[4][4], pl[4][4];
#pragma unroll
        for (int j = 0; j < 4; j++) {
            pack_hl(sc[2 * j][0],     sc[2 * j][1],     ph[j][0], pl[j][0]);
            pack_hl(sc[2 * j][2],     sc[2 * j][3],     ph[j][1], pl[j][1]);
            pack_hl(sc[2 * j + 1][0], sc[2 * j + 1][1], ph[j][2], pl[j][2]);
            pack_hl(sc[2 * j + 1][2], sc[2 * j + 1][3], ph[j][3], pl[j][3]);
        }

        // ---- O += P @ V ----
#pragma unroll
        for (int j = 0; j < 4; j++) {
#pragma unroll
            for (int nt2 = 0; nt2 < 8; nt2++) {
                uint32_t voff = (uint32_t)((j * 16 + vRow) * FSTR + nt2 * 16 + vCol) * 2;
                uint32_t vh[4], vl[4];
                ldm_x4_t(vh, sVh + voff);
                ldm_x4_t(vl, sVl + voff);
                mma_bf16(o[nt2 * 2],     ph[j], &vh[0]);
                mma_bf16(o[nt2 * 2],     ph[j], &vl[0]);
                mma_bf16(o[nt2 * 2],     pl[j], &vh[0]);
                mma_bf16(o[nt2 * 2 + 1], ph[j], &vh[2]);
                mma_bf16(o[nt2 * 2 + 1], ph[j], &vl[2]);
                mma_bf16(o[nt2 * 2 + 1], pl[j], &vh[2]);
            }
        }
    }

    // ---- epilogue: normalize, split to bf16 hi/lo, write [B,S,H*dk] ----
    float inv0 = 1.0f / l_i[0], inv1 = 1.0f / l_i[1];
    size_t row0 = (size_t)(b * S_LEN + qblk * 64 + w * 16 + g);
    size_t row1 = row0 + 8;
#pragma unroll
    for (int nb = 0; nb < 16; nb++) {
        int col = h * DK + nb * 8 + t4 * 2;
        uint32_t hp, lp;
        pack_hl(o[nb][0] * inv0, o[nb][1] * inv0, hp, lp);
        *(uint32_t*)&g_ahi[row0 * D_MODEL + col] = hp;
        *(uint32_t*)&g_alo[row0 * D_MODEL + col] = lp;
        pack_hl(o[nb][2] * inv1, o[nb][3] * inv1, hp, lp);
        *(uint32_t*)&g_ahi[row1 * D_MODEL + col] = hp;
        *(uint32_t*)&g_alo[row1 * D_MODEL + col] = lp;
    }
}

// ===========================================================================
// Launch
// ===========================================================================
extern "C" void kernel_launch(void* const* d_in, const int* in_sizes, int n_in,
                              void* d_out, int out_size) {
    const float* x     = (const float*)d_in[0];
    const float* w_qkv = (const float*)d_in[1];
    const float* w_o   = (const float*)d_in[2];
    float* out = (float*)d_out;

    float* qkv_ptr;
    __nv_bfloat16 *xhi, *xlo, *wqhi, *wqlo, *wohi, *wolo, *ahi, *alo;
    cudaGetSymbolAddress((void**)&qkv_ptr, g_qkv);
    cudaGetSymbolAddress((void**)&xhi, g_xhi);
    cudaGetSymbolAddress((void**)&xlo, g_xlo);
    cudaGetSymbolAddress((void**)&wqhi, g_wqhi);
    cudaGetSymbolAddress((void**)&wqlo, g_wqlo);
    cudaGetSymbolAddress((void**)&wohi, g_wohi);
    cudaGetSymbolAddress((void**)&wolo, g_wolo);
    cudaGetSymbolAddress((void**)&ahi, g_ahi);
    cudaGetSymbolAddress((void**)&alo, g_alo);

    const int M = BATCH * S_LEN;  // 4096

    // 0) Split inputs to bf16 hi/lo
    split_kernel<<<(XN + 255) / 256, 256>>>(x, xhi, xlo, XN);
    split_kernel<<<(WQN + 255) / 256, 256>>>(w_qkv, wqhi, wqlo, WQN);
    split_kernel<<<(WON + 255) / 256, 256>>>(w_o, wohi, wolo, WON);

    cudaFuncSetAttribute(gemm_hmma_x3, cudaFuncAttributeMaxDynamicSharedMemorySize,
                         GEMM_SMEM);

    // 1) QKV projection
    {
        dim3 grid((3 * D_MODEL) / 128, M / 128);
        gemm_hmma_x3<<<grid, 256, GEMM_SMEM>>>(xhi, xlo, wqhi, wqlo, qkv_ptr,
                                               M, 3 * D_MODEL, D_MODEL);
    }
    // 2) Rope + split to head-major bf16 hi/lo
    {
        int n = BATCH * NH * S_LEN * 64;
        rope_split_kernel<<<(n + 255) / 256, 256>>>();
    }
    // 3) HMMA causal flash attention
    {
        cudaFuncSetAttribute(flash_hmma, cudaFuncAttributeMaxDynamicSharedMemorySize,
                             FLASH_SMEM);
        dim3 grid(S_LEN / 64, NH, BATCH);
        flash_hmma<<<grid, 128, FLASH_SMEM>>>();
    }
    // 4) Output projection
    {
        dim3 grid(D_MODEL / 128, M / 128);
        gemm_hmma_x3<<<grid, 256, GEMM_SMEM>>>(ahi, alo, wohi, wolo, out,
                                               M, D_MODEL, D_MODEL);
    }
}

// round 8
// speedup vs baseline: 3.4063x; 1.1087x over previous
#include <cuda_runtime.h>
#include <cuda_bf16.h>
#include <math.h>
#include <stdint.h>

#define D_MODEL 2048
#define NH 16
#define DK 128
#define S_LEN 2048
#define BATCH 2

#define XN   (4096 * 2048)
#define WQN  (6144 * 2048)
#define WON  (2048 * 2048)
#define QKVN (BATCH * NH * S_LEN * DK)    // 8.4M per tensor

// Scratch (device globals — no allocations allowed)
__device__ float g_qkv[(size_t)BATCH * S_LEN * 3 * D_MODEL];   // [B,S,3,H,dk] fp32
__device__ __nv_bfloat16 g_xhi[XN],  g_xlo[XN];
__device__ __nv_bfloat16 g_wqhi[WQN], g_wqlo[WQN];
__device__ __nv_bfloat16 g_wohi[WON], g_wolo[WON];
__device__ __nv_bfloat16 g_ahi[XN],  g_alo[XN];                // attention out hi/lo
// Rope-split Q/K/V, head-major [B,H,S,dk]
__device__ __nv_bfloat16 g_q_hi[QKVN], g_q_lo[QKVN];
__device__ __nv_bfloat16 g_k_hi[QKVN], g_k_lo[QKVN];
__device__ __nv_bfloat16 g_v_hi[QKVN], g_v_lo[QKVN];

// ===========================================================================
// PTX helpers (sm_100-safe: mma.sync / ldmatrix / cp.async)
// ===========================================================================
__device__ __forceinline__ uint32_t smem_u32(const void* p) {
    uint32_t a;
    asm("{ .reg .u64 t; cvta.to.shared.u64 t, %1; cvt.u32.u64 %0, t; }"
        : "=r"(a) : "l"(p));
    return a;
}
__device__ __forceinline__ void cp16(uint32_t dst, const void* src) {
    asm volatile("cp.async.cg.shared.global [%0], [%1], 16;"
                 :: "r"(dst), "l"(src) : "memory");
}
__device__ __forceinline__ void cp_commit() {
    asm volatile("cp.async.commit_group;" ::: "memory");
}
__device__ __forceinline__ void cp_wait0() {
    asm volatile("cp.async.wait_group 0;" ::: "memory");
}
__device__ __forceinline__ void cp_wait1() {
    asm volatile("cp.async.wait_group 1;" ::: "memory");
}
__device__ __forceinline__ void ldm_x4(uint32_t* r, uint32_t addr) {
    asm volatile("ldmatrix.sync.aligned.m8n8.x4.shared.b16 {%0,%1,%2,%3}, [%4];"
                 : "=r"(r[0]), "=r"(r[1]), "=r"(r[2]), "=r"(r[3]) : "r"(addr));
}
__device__ __forceinline__ void ldm_x4_t(uint32_t* r, uint32_t addr) {
    asm volatile("ldmatrix.sync.aligned.m8n8.x4.trans.shared.b16 {%0,%1,%2,%3}, [%4];"
                 : "=r"(r[0]), "=r"(r[1]), "=r"(r[2]), "=r"(r[3]) : "r"(addr));
}
__device__ __forceinline__ void mma_bf16(float* d, const uint32_t* a, const uint32_t* b) {
    asm volatile(
        "mma.sync.aligned.m16n8k16.row.col.f32.bf16.bf16.f32 "
        "{%0,%1,%2,%3}, {%4,%5,%6,%7}, {%8,%9}, {%0,%1,%2,%3};"
        : "+f"(d[0]), "+f"(d[1]), "+f"(d[2]), "+f"(d[3])
        : "r"(a[0]), "r"(a[1]), "r"(a[2]), "r"(a[3]), "r"(b[0]), "r"(b[1]));
}
__device__ __forceinline__ void pack_hl(float a, float b, uint32_t& h, uint32_t& l) {
    __nv_bfloat162 hb = __floats2bfloat162_rn(a, b);
    h = *(uint32_t*)&hb;
    float ra = a - __bfloat162float(hb.x);
    float rb = b - __bfloat162float(hb.y);
    __nv_bfloat162 lb = __floats2bfloat162_rn(ra, rb);
    l = *(uint32_t*)&lb;
}

// ===========================================================================
// Split fp32 -> bf16 hi + bf16 lo
// ===========================================================================
__global__ void split_kernel(const float* __restrict__ src,
                             __nv_bfloat16* __restrict__ hi,
                             __nv_bfloat16* __restrict__ lo, int n) {
    int i = blockIdx.x * blockDim.x + threadIdx.x;
    if (i >= n) return;
    float v = src[i];
    __nv_bfloat16 h = __float2bfloat16(v);
    hi[i] = h;
    lo[i] = __float2bfloat16(v - __bfloat162float(h));
}

// ===========================================================================
// HMMA GEMM: C[M,N] = A[M,K] @ B[N,K]^T, bf16 hi/lo 3-pass, fp32 accum.
// 128x128 CTA tile, BK=32, 8 warps, 2-stage cp.async buffer, 2 CTAs/SM.
// ===========================================================================
#define BK 32
#define ASTRIDE 40                        // bf16 elems per smem row (32 + 8 pad)
#define TILE_B (128 * ASTRIDE * 2)        // 10240 B per tile
#define STAGE_B (4 * TILE_B)              // Ahi,Alo,Bhi,Blo = 40960 B
#define GEMM_SMEM (2 * STAGE_B)           // 81920 B  (x2 CTAs = 163840 <= 227KB)

__global__ __launch_bounds__(256, 2)
void gemm_hmma_x3(const __nv_bfloat16* __restrict__ Ahi, const __nv_bfloat16* __restrict__ Alo,
                  const __nv_bfloat16* __restrict__ Bhi, const __nv_bfloat16* __restrict__ Blo,
                  float* __restrict__ C, int M, int N, int K) {
    extern __shared__ char dynsmem[];
    const uint32_t sbase = smem_u32(dynsmem);

    const int tid  = (int)threadIdx.x;
    const int wid  = tid >> 5;
    const int lane = tid & 31;
    const int bm = blockIdx.y * 128, bn = blockIdx.x * 128;
    const int wm = wid & 1;
    const int wn = wid >> 1;

    const __nv_bfloat16* srcs[4] = {
        Ahi + (size_t)bm * K, Alo + (size_t)bm * K,
        Bhi + (size_t)bn * K, Blo + (size_t)bn * K };

    auto load_stage = [&](int stage, int k0) {
        const uint32_t stg = sbase + stage * STAGE_B;
#pragma unroll
        for (int i = 0; i < 8; i++) {
            int linear = i * 256 + tid;
            int t   = linear >> 9;
            int row = (linear >> 2) & 127;
            int c16 = linear & 3;
            const __nv_bfloat16* src = srcs[t] + (size_t)row * K + k0 + c16 * 8;
            cp16(stg + t * TILE_B + (row * ASTRIDE + c16 * 8) * 2, src);
        }
        cp_commit();
    };

    float acc[4][4][4];
#pragma unroll
    for (int i = 0; i < 4; i++)
#pragma unroll
        for (int j = 0; j < 4; j++)
#pragma unroll
            for (int c = 0; c < 4; c++) acc[i][j][c] = 0.f;

    const int arow = wm * 64 + (lane & 7) + ((lane >> 3) & 1) * 8;
    const int acol = ((lane >> 4) & 1) * 8;
    const int brow = wn * 32 + (lane & 7) + ((lane >> 4) & 1) * 8;
    const int bcol = ((lane >> 3) & 1) * 8;

    const int nk = K / BK;
    load_stage(0, 0);

    for (int c = 0; c < nk; c++) {
        // Issue next-stage load first so it overlaps this stage's compute.
        if (c + 1 < nk) {
            load_stage((c + 1) & 1, (c + 1) * BK);
            cp_wait1();          // wait only for the current stage
        } else {
            cp_wait0();
        }
        __syncthreads();

        const uint32_t stg = sbase + (c & 1) * STAGE_B;
        const uint32_t sAhi = stg;
        const uint32_t sAlo = stg + TILE_B;
        const uint32_t sBhi = stg + 2 * TILE_B;
        const uint32_t sBlo = stg + 3 * TILE_B;

#pragma unroll
        for (int ks = 0; ks < 2; ks++) {
            uint32_t ahi[4][4], alo[4][4];
            uint32_t bhi[4][2], blo[4][2];
#pragma unroll
            for (int mt = 0; mt < 4; mt++) {
                uint32_t off = (uint32_t)(((arow + mt * 16) * ASTRIDE) + ks * 16 + acol) * 2;
                ldm_x4(ahi[mt], sAhi + off);
                ldm_x4(alo[mt], sAlo + off);
            }
#pragma unroll
            for (int jp = 0; jp < 2; jp++) {
                uint32_t off = (uint32_t)(((brow + jp * 16) * ASTRIDE) + ks * 16 + bcol) * 2;
                uint32_t r[4];
                ldm_x4(r, sBhi + off);
                bhi[jp * 2][0] = r[0]; bhi[jp * 2][1] = r[1];
                bhi[jp * 2 + 1][0] = r[2]; bhi[jp * 2 + 1][1] = r[3];
                ldm_x4(r, sBlo + off);
                blo[jp * 2][0] = r[0]; blo[jp * 2][1] = r[1];
                blo[jp * 2 + 1][0] = r[2]; blo[jp * 2 + 1][1] = r[3];
            }
#pragma unroll
            for (int mt = 0; mt < 4; mt++)
#pragma unroll
                for (int nt = 0; nt < 4; nt++) {
                    mma_bf16(acc[mt][nt], ahi[mt], bhi[nt]);
                    mma_bf16(acc[mt][nt], ahi[mt], blo[nt]);
                    mma_bf16(acc[mt][nt], alo[mt], bhi[nt]);
                }
        }
        __syncthreads();   // all reads of this stage done before it is refilled
    }

    const int g = lane >> 2, t = lane & 3;
#pragma unroll
    for (int mt = 0; mt < 4; mt++) {
#pragma unroll
        for (int nt = 0; nt < 4; nt++) {
            size_t r0 = (size_t)(bm + wm * 64 + mt * 16 + g);
            int col = bn + wn * 32 + nt * 8 + t * 2;
            *(float2*)&C[r0 * N + col] = make_float2(acc[mt][nt][0], acc[mt][nt][1]);
            *(float2*)&C[(r0 + 8) * N + col] = make_float2(acc[mt][nt][2], acc[mt][nt][3]);
        }
    }
}

// ===========================================================================
// Rope + split: g_qkv fp32 -> Q/K (rotated) and V, bf16 hi/lo, [B,H,S,dk].
// ===========================================================================
__global__ void rope_split_kernel() {
    int idx = blockIdx.x * blockDim.x + threadIdx.x;
    const int total = BATCH * NH * S_LEN * 64;   // 2^22
    if (idx >= total) return;
    int j = idx & 63;
    int s = (idx >> 6) & (S_LEN - 1);
    int h = (idx >> 17) & 15;
    int b = idx >> 21;

    float freq = expf((float)j * (-9.210340371976184f / 63.0f));
    float theta = (float)s * freq;
    float sn, cs;
    sincosf(theta, &sn, &cs);

    size_t ibase = ((size_t)(b * S_LEN + s)) * 3 * (size_t)D_MODEL + (size_t)h * DK;
    size_t obase = (((size_t)(b * NH + h)) * S_LEN + s) * (size_t)DK;

    // Q (t=0)
    {
        float x1 = g_qkv[ibase + j], x2 = g_qkv[ibase + 64 + j];
        float y1 = x1 * cs - x2 * sn;
        float y2 = x1 * sn + x2 * cs;
        __nv_bfloat16 h1 = __float2bfloat16(y1), h2 = __float2bfloat16(y2);
        g_q_hi[obase + j] = h1;      g_q_lo[obase + j] = __float2bfloat16(y1 - __bfloat162float(h1));
        g_q_hi[obase + 64 + j] = h2; g_q_lo[obase + 64 + j] = __float2bfloat16(y2 - __bfloat162float(h2));
    }
    // K (t=1)
    {
        float x1 = g_qkv[ibase + D_MODEL + j], x2 = g_qkv[ibase + D_MODEL + 64 + j];
        float y1 = x1 * cs - x2 * sn;
        float y2 = x1 * sn + x2 * cs;
        __nv_bfloat16 h1 = __float2bfloat16(y1), h2 = __float2bfloat16(y2);
        g_k_hi[obase + j] = h1;      g_k_lo[obase + j] = __float2bfloat16(y1 - __bfloat162float(h1));
        g_k_hi[obase + 64 + j] = h2; g_k_lo[obase + 64 + j] = __float2bfloat16(y2 - __bfloat162float(h2));
    }
    // V (t=2), passthrough split
    {
        float x1 = g_qkv[ibase + 2 * D_MODEL + j], x2 = g_qkv[ibase + 2 * D_MODEL + 64 + j];
        __nv_bfloat16 h1 = __float2bfloat16(x1), h2 = __float2bfloat16(x2);
        g_v_hi[obase + j] = h1;      g_v_lo[obase + j] = __float2bfloat16(x1 - __bfloat162float(h1));
        g_v_hi[obase + 64 + j] = h2; g_v_lo[obase + 64 + j] = __float2bfloat16(x2 - __bfloat162float(h2));
    }
}

// ===========================================================================
// HMMA causal flash attention. 128 threads (4 warps), BM=64 (16 q-rows/warp),
// BN=64 kv per iter, dk=128. hi/lo 3-pass for QK and PV. fp32 softmax.
// Heavy (large-qblk) blocks launch first to kill the tail wave.
// ===========================================================================
#define FSTR 136                          // smem row stride in bf16 elems (128 + 8)
#define FTILE (64 * FSTR)                 // elems per tile
#define FLASH_SMEM (6 * FTILE * 2)        // 104448 B (x2 CTAs = 208896 <= 227KB)

__global__ __launch_bounds__(128, 2)
void flash_hmma() {
    extern __shared__ __nv_bfloat16 fsm[];
    const uint32_t sb = smem_u32(fsm);
    const uint32_t sQh = sb;
    const uint32_t sQl = sb + 1 * FTILE * 2;
    const uint32_t sKh = sb + 2 * FTILE * 2;
    const uint32_t sKl = sb + 3 * FTILE * 2;
    const uint32_t sVh = sb + 4 * FTILE * 2;
    const uint32_t sVl = sb + 5 * FTILE * 2;

    const int qblk = (int)gridDim.x - 1 - (int)blockIdx.x;   // heavy blocks first
    const int h = blockIdx.y, b = blockIdx.z;
    const int tid = (int)threadIdx.x;
    const int w = tid >> 5, lane = tid & 31;
    const int g = lane >> 2, t4 = lane & 3;
    const float scale = 0.08838834764831845f;   // 1/sqrt(128)

    const size_t hbase = (((size_t)(b * NH + h)) * S_LEN) * (size_t)DK;

    // Load Q tiles (hi/lo): 64 rows x 128 elems each
    {
        const __nv_bfloat16* qh = g_q_hi + hbase + (size_t)qblk * 64 * DK;
        const __nv_bfloat16* ql = g_q_lo + hbase + (size_t)qblk * 64 * DK;
#pragma unroll
        for (int i = 0; i < 8; i++) {
            int e = i * 128 + tid;
            int row = e >> 4, c16 = e & 15;
            uint4 v = *(const uint4*)(qh + (size_t)row * DK + c16 * 8);
            *(uint4*)(fsm + 0 * FTILE + row * FSTR + c16 * 8) = v;
            v = *(const uint4*)(ql + (size_t)row * DK + c16 * 8);
            *(uint4*)(fsm + 1 * FTILE + row * FSTR + c16 * 8) = v;
        }
    }

    float o[16][4];
    float m_i[2] = {-1e30f, -1e30f}, l_i[2] = {0.f, 0.f};
#pragma unroll
    for (int nb = 0; nb < 16; nb++)
#pragma unroll
        for (int e = 0; e < 4; e++) o[nb][e] = 0.f;

    // ldmatrix address components
    const int aQrow = w * 16 + (lane & 7) + ((lane >> 3) & 1) * 8;
    const int aQcol = ((lane >> 4) & 1) * 8;
    const int bKrow = (lane & 7) + ((lane >> 4) & 1) * 8;   // + jp*16
    const int bKcol = ((lane >> 3) & 1) * 8;                // + k16*16
    const int vRow  = (lane & 7) + ((lane >> 3) & 1) * 8;   // + j*16
    const int vCol  = ((lane >> 4) & 1) * 8;                // + nt2*16

    for (int jblk = 0; jblk <= qblk; jblk++) {
        __syncthreads();
        // Load K/V (hi/lo) for this block
        {
            const size_t base = hbase + (size_t)jblk * 64 * DK;
#pragma unroll
            for (int i = 0; i < 8; i++) {
                int e = i * 128 + tid;
                int row = e >> 4, c16 = e & 15;
                size_t go = base + (size_t)row * DK + c16 * 8;
                int so = row * FSTR + c16 * 8;
                *(uint4*)(fsm + 2 * FTILE + so) = *(const uint4*)(g_k_hi + go);
                *(uint4*)(fsm + 3 * FTILE + so) = *(const uint4*)(g_k_lo + go);
                *(uint4*)(fsm + 4 * FTILE + so) = *(const uint4*)(g_v_hi + go);
                *(uint4*)(fsm + 5 * FTILE + so) = *(const uint4*)(g_v_lo + go);
            }
        }
        __syncthreads();

        // ---- QK^T ----  (each warp covers ALL 64 kv cols: jp = 0..3)
        float sc[8][4];
#pragma unroll
        for (int nt = 0; nt < 8; nt++)
#pragma unroll
            for (int e = 0; e < 4; e++) sc[nt][e] = 0.f;

#pragma unroll
        for (int k16 = 0; k16 < 8; k16++) {
            uint32_t qh[4], ql[4];
            uint32_t qoff = (uint32_t)(aQrow * FSTR + k16 * 16 + aQcol) * 2;
            ldm_x4(qh, sQh + qoff);
            ldm_x4(ql, sQl + qoff);
#pragma unroll
            for (int jp = 0; jp < 4; jp++) {
                uint32_t koff = (uint32_t)((bKrow + jp * 16) * FSTR + k16 * 16 + bKcol) * 2;
                uint32_t kh[4], kl[4];
                ldm_x4(kh, sKh + koff);
                ldm_x4(kl, sKl + koff);
                mma_bf16(sc[jp * 2],     qh, &kh[0]);
                mma_bf16(sc[jp * 2],     qh, &kl[0]);
                mma_bf16(sc[jp * 2],     ql, &kh[0]);
                mma_bf16(sc[jp * 2 + 1], qh, &kh[2]);
                mma_bf16(sc[jp * 2 + 1], qh, &kl[2]);
                mma_bf16(sc[jp * 2 + 1], ql, &kh[2]);
            }
        }

        // ---- scale + causal mask ----
#pragma unroll
        for (int nt = 0; nt < 8; nt++)
#pragma unroll
            for (int e = 0; e < 4; e++) sc[nt][e] *= scale;
        if (jblk == qblk) {
            const int qr0 = w * 16 + g, qr1 = qr0 + 8;
#pragma unroll
            for (int nt = 0; nt < 8; nt++) {
                int kc = nt * 8 + t4 * 2;
                if (kc > qr0)     sc[nt][0] = -1e30f;
                if (kc + 1 > qr0) sc[nt][1] = -1e30f;
                if (kc > qr1)     sc[nt][2] = -1e30f;
                if (kc + 1 > qr1) sc[nt][3] = -1e30f;
            }
        }

        // ---- online softmax (rows g, g+8) ----
        float r0 = -1e30f, r1 = -1e30f;
#pragma unroll
        for (int nt = 0; nt < 8; nt++) {
            r0 = fmaxf(r0, fmaxf(sc[nt][0], sc[nt][1]));
            r1 = fmaxf(r1, fmaxf(sc[nt][2], sc[nt][3]));
        }
        r0 = fmaxf(r0, __shfl_xor_sync(0xffffffffu, r0, 1));
        r0 = fmaxf(r0, __shfl_xor_sync(0xffffffffu, r0, 2));
        r1 = fmaxf(r1, __shfl_xor_sync(0xffffffffu, r1, 1));
        r1 = fmaxf(r1, __shfl_xor_sync(0xffffffffu, r1, 2));
        float mnew0 = fmaxf(m_i[0], r0), mnew1 = fmaxf(m_i[1], r1);
        float corr0 = __expf(m_i[0] - mnew0), corr1 = __expf(m_i[1] - mnew1);
        m_i[0] = mnew0; m_i[1] = mnew1;

        float sum0 = 0.f, sum1 = 0.f;
#pragma unroll
        for (int nt = 0; nt < 8; nt++) {
            sc[nt][0] = __expf(sc[nt][0] - mnew0);
            sc[nt][1] = __expf(sc[nt][1] - mnew0);
            sc[nt][2] = __expf(sc[nt][2] - mnew1);
            sc[nt][3] = __expf(sc[nt][3] - mnew1);
            sum0 += sc[nt][0] + sc[nt][1];
            sum1 += sc[nt][2] + sc[nt][3];
        }
        sum0 += __shfl_xor_sync(0xffffffffu, sum0, 1);
        sum0 += __shfl_xor_sync(0xffffffffu, sum0, 2);
        sum1 += __shfl_xor_sync(0xffffffffu, sum1, 1);
        sum1 += __shfl_xor_sync(0xffffffffu, sum1, 2);
        l_i[0] = l_i[0] * corr0 + sum0;
        l_i[1] = l_i[1] * corr1 + sum1;

#pragma unroll
        for (int nb = 0; nb < 16; nb++) {
            o[nb][0] *= corr0; o[nb][1] *= corr0;
            o[nb][2] *= corr1; o[nb][3] *= corr1;
        }

        // ---- P -> A fragments (register-only, hi/lo) ----
        uint32_t ph[4][4], pl[4][4];
#pragma unroll
        for (int j = 0; j < 4; j++) {
            pack_hl(sc[2 * j][0],     sc[2 * j][1],     ph[j][0], pl[j][0]);
            pack_hl(sc[2 * j][2],     sc[2 * j][3],     ph[j][1], pl[j][1]);
            pack_hl(sc[2 * j + 1][0], sc[2 * j + 1][1], ph[j][2], pl[j][2]);
            pack_hl(sc[2 * j + 1][2], sc[2 * j + 1][3], ph[j][3], pl[j][3]);
        }

        // ---- O += P @ V ----
#pragma unroll
        for (int j = 0; j < 4; j++) {
#pragma unroll
            for (int nt2 = 0; nt2 < 8; nt2++) {
                uint32_t voff = (uint32_t)((j * 16 + vRow) * FSTR + nt2 * 16 + vCol) * 2;
                uint32_t vh[4], vl[4];
                ldm_x4_t(vh, sVh + voff);
                ldm_x4_t(vl, sVl + voff);
                mma_bf16(o[nt2 * 2],     ph[j], &vh[0]);
                mma_bf16(o[nt2 * 2],     ph[j], &vl[0]);
                mma_bf16(o[nt2 * 2],     pl[j], &vh[0]);
                mma_bf16(o[nt2 * 2 + 1], ph[j], &vh[2]);
                mma_bf16(o[nt2 * 2 + 1], ph[j], &vl[2]);
                mma_bf16(o[nt2 * 2 + 1], pl[j], &vh[2]);
            }
        }
    }

    // ---- epilogue: normalize, split to bf16 hi/lo, write [B,S,H*dk] ----
    float inv0 = 1.0f / l_i[0], inv1 = 1.0f / l_i[1];
    size_t row0 = (size_t)(b * S_LEN + qblk * 64 + w * 16 + g);
    size_t row1 = row0 + 8;
#pragma unroll
    for (int nb = 0; nb < 16; nb++) {
        int col = h * DK + nb * 8 + t4 * 2;
        uint32_t hp, lp;
        pack_hl(o[nb][0] * inv0, o[nb][1] * inv0, hp, lp);
        *(uint32_t*)&g_ahi[row0 * D_MODEL + col] = hp;
        *(uint32_t*)&g_alo[row0 * D_MODEL + col] = lp;
        pack_hl(o[nb][2] * inv1, o[nb][3] * inv1, hp, lp);
        *(uint32_t*)&g_ahi[row1 * D_MODEL + col] = hp;
        *(uint32_t*)&g_alo[row1 * D_MODEL + col] = lp;
    }
}

// ===========================================================================
// Launch
// ===========================================================================
extern "C" void kernel_launch(void* const* d_in, const int* in_sizes, int n_in,
                              void* d_out, int out_size) {
    const float* x     = (const float*)d_in[0];
    const float* w_qkv = (const float*)d_in[1];
    const float* w_o   = (const float*)d_in[2];
    float* out = (float*)d_out;

    float* qkv_ptr;
    __nv_bfloat16 *xhi, *xlo, *wqhi, *wqlo, *wohi, *wolo, *ahi, *alo;
    cudaGetSymbolAddress((void**)&qkv_ptr, g_qkv);
    cudaGetSymbolAddress((void**)&xhi, g_xhi);
    cudaGetSymbolAddress((void**)&xlo, g_xlo);
    cudaGetSymbolAddress((void**)&wqhi, g_wqhi);
    cudaGetSymbolAddress((void**)&wqlo, g_wqlo);
    cudaGetSymbolAddress((void**)&wohi, g_wohi);
    cudaGetSymbolAddress((void**)&wolo, g_wolo);
    cudaGetSymbolAddress((void**)&ahi, g_ahi);
    cudaGetSymbolAddress((void**)&alo, g_alo);

    const int M = BATCH * S_LEN;  // 4096

    // 0) Split inputs to bf16 hi/lo
    split_kernel<<<(XN + 255) / 256, 256>>>(x, xhi, xlo, XN);
    split_kernel<<<(WQN + 255) / 256, 256>>>(w_qkv, wqhi, wqlo, WQN);
    split_kernel<<<(WON + 255) / 256, 256>>>(w_o, wohi, wolo, WON);

    cudaFuncSetAttribute(gemm_hmma_x3, cudaFuncAttributeMaxDynamicSharedMemorySize,
                         GEMM_SMEM);

    // 1) QKV projection
    {
        dim3 grid((3 * D_MODEL) / 128, M / 128);
        gemm_hmma_x3<<<grid, 256, GEMM_SMEM>>>(xhi, xlo, wqhi, wqlo, qkv_ptr,
                                               M, 3 * D_MODEL, D_MODEL);
    }
    // 2) Rope + split to head-major bf16 hi/lo
    {
        int n = BATCH * NH * S_LEN * 64;
        rope_split_kernel<<<(n + 255) / 256, 256>>>();
    }
    // 3) HMMA causal flash attention
    {
        cudaFuncSetAttribute(flash_hmma, cudaFuncAttributeMaxDynamicSharedMemorySize,
                             FLASH_SMEM);
        dim3 grid(S_LEN / 64, NH, BATCH);
        flash_hmma<<<grid, 128, FLASH_SMEM>>>();
    }
    // 4) Output projection
    {
        dim3 grid(D_MODEL / 128, M / 128);
        gemm_hmma_x3<<<grid, 256, GEMM_SMEM>>>(ahi, alo, wohi, wolo, out,
                                               M, D_MODEL, D_MODEL);
    }
}

// round 10
// speedup vs baseline: 3.5216x; 1.0339x over previous
#include <cuda_runtime.h>
#include <cuda_bf16.h>
#include <math.h>
#include <stdint.h>

#define D_MODEL 2048
#define NH 16
#define DK 128
#define S_LEN 2048
#define BATCH 2

#define XN   (4096 * 2048)
#define WQN  (6144 * 2048)
#define WON  (2048 * 2048)
#define QKVN (BATCH * NH * S_LEN * DK)    // 8.4M per tensor

// Scratch (device globals — no allocations allowed)
__device__ float g_qkv[(size_t)BATCH * S_LEN * 3 * D_MODEL];   // [B,S,3,H,dk] fp32
__device__ __nv_bfloat16 g_xhi[XN],  g_xlo[XN];
__device__ __nv_bfloat16 g_wqhi[WQN], g_wqlo[WQN];
__device__ __nv_bfloat16 g_wohi[WON], g_wolo[WON];
__device__ __nv_bfloat16 g_ahi[XN],  g_alo[XN];                // attention out hi/lo
// Rope-split Q/K/V, head-major [B,H,S,dk]
__device__ __nv_bfloat16 g_q_hi[QKVN], g_q_lo[QKVN];
__device__ __nv_bfloat16 g_k_hi[QKVN], g_k_lo[QKVN];
__device__ __nv_bfloat16 g_v_hi[QKVN], g_v_lo[QKVN];

// ===========================================================================
// PTX helpers (sm_100-safe: mma.sync / ldmatrix / cp.async)
// ===========================================================================
__device__ __forceinline__ uint32_t smem_u32(const void* p) {
    uint32_t a;
    asm("{ .reg .u64 t; cvta.to.shared.u64 t, %1; cvt.u32.u64 %0, t; }"
        : "=r"(a) : "l"(p));
    return a;
}
__device__ __forceinline__ void cp16(uint32_t dst, const void* src) {
    asm volatile("cp.async.cg.shared.global [%0], [%1], 16;"
                 :: "r"(dst), "l"(src) : "memory");
}
__device__ __forceinline__ void cp_commit() {
    asm volatile("cp.async.commit_group;" ::: "memory");
}
__device__ __forceinline__ void cp_wait0() {
    asm volatile("cp.async.wait_group 0;" ::: "memory");
}
__device__ __forceinline__ void cp_wait1() {
    asm volatile("cp.async.wait_group 1;" ::: "memory");
}
__device__ __forceinline__ void ldm_x4(uint32_t* r, uint32_t addr) {
    asm volatile("ldmatrix.sync.aligned.m8n8.x4.shared.b16 {%0,%1,%2,%3}, [%4];"
                 : "=r"(r[0]), "=r"(r[1]), "=r"(r[2]), "=r"(r[3]) : "r"(addr));
}
__device__ __forceinline__ void ldm_x4_t(uint32_t* r, uint32_t addr) {
    asm volatile("ldmatrix.sync.aligned.m8n8.x4.trans.shared.b16 {%0,%1,%2,%3}, [%4];"
                 : "=r"(r[0]), "=r"(r[1]), "=r"(r[2]), "=r"(r[3]) : "r"(addr));
}
__device__ __forceinline__ void mma_bf16(float* d, const uint32_t* a, const uint32_t* b) {
    asm volatile(
        "mma.sync.aligned.m16n8k16.row.col.f32.bf16.bf16.f32 "
        "{%0,%1,%2,%3}, {%4,%5,%6,%7}, {%8,%9}, {%0,%1,%2,%3};"
        : "+f"(d[0]), "+f"(d[1]), "+f"(d[2]), "+f"(d[3])
        : "r"(a[0]), "r"(a[1]), "r"(a[2]), "r"(a[3]), "r"(b[0]), "r"(b[1]));
}
__device__ __forceinline__ void pack_hl(float a, float b, uint32_t& h, uint32_t& l) {
    __nv_bfloat162 hb = __floats2bfloat162_rn(a, b);
    h = *(uint32_t*)&hb;
    float ra = a - __bfloat162float(hb.x);
    float rb = b - __bfloat162float(hb.y);
    __nv_bfloat162 lb = __floats2bfloat162_rn(ra, rb);
    l = *(uint32_t*)&lb;
}

// ===========================================================================
// Split fp32 -> bf16 hi + bf16 lo
// ===========================================================================
__global__ void split_kernel(const float* __restrict__ src,
                             __nv_bfloat16* __restrict__ hi,
                             __nv_bfloat16* __restrict__ lo, int n) {
    int i = blockIdx.x * blockDim.x + threadIdx.x;
    if (i >= n) return;
    float v = src[i];
    __nv_bfloat16 h = __float2bfloat16(v);
    hi[i] = h;
    lo[i] = __float2bfloat16(v - __bfloat162float(h));
}

// ===========================================================================
// HMMA GEMM: C[M,N] = A[M,K] @ B[N,K]^T, bf16 hi/lo 3-pass, fp32 accum.
// 128x128 CTA tile, 4 warps (64x64 warp tile), BK=32, 2-stage, 2 CTAs/SM.
// 85 B smem per MMA (vs 128 at 64x32) -> tensor-bound, not smem-bound.
// ===========================================================================
#define BK 32
#define ASTRIDE 40                        // bf16 elems per smem row (32 + 8 pad)
#define TILE_B (128 * ASTRIDE * 2)        // 10240 B per tile
#define STAGE_B (4 * TILE_B)              // Ahi,Alo,Bhi,Blo = 40960 B
#define GEMM_SMEM (2 * STAGE_B)           // 81920 B  (x2 CTAs = 163840 <= 227KB)

__global__ __launch_bounds__(128, 2)
void gemm_hmma_x3(const __nv_bfloat16* __restrict__ Ahi, const __nv_bfloat16* __restrict__ Alo,
                  const __nv_bfloat16* __restrict__ Bhi, const __nv_bfloat16* __restrict__ Blo,
                  float* __restrict__ C, int M, int N, int K) {
    extern __shared__ char dynsmem[];
    const uint32_t sbase = smem_u32(dynsmem);

    const int tid  = (int)threadIdx.x;
    const int wid  = tid >> 5;
    const int lane = tid & 31;
    const int bm = blockIdx.y * 128, bn = blockIdx.x * 128;
    const int wm = wid & 1;               // 0..1 -> 64-row half
    const int wn = wid >> 1;              // 0..1 -> 64-col half

    const __nv_bfloat16* srcs[4] = {
        Ahi + (size_t)bm * K, Alo + (size_t)bm * K,
        Bhi + (size_t)bn * K, Blo + (size_t)bn * K };

    auto load_stage = [&](int stage, int k0) {
        const uint32_t stg = sbase + stage * STAGE_B;
#pragma unroll
        for (int i = 0; i < 16; i++) {
            int linear = i * 128 + tid;           // 0..2047
            int t   = linear >> 9;                // tile 0..3
            int row = (linear >> 2) & 127;        // row 0..127
            int c16 = linear & 3;                 // 16B chunk 0..3
            const __nv_bfloat16* src = srcs[t] + (size_t)row * K + k0 + c16 * 8;
            cp16(stg + t * TILE_B + (row * ASTRIDE + c16 * 8) * 2, src);
        }
        cp_commit();
    };

    float acc[4][8][4];
#pragma unroll
    for (int i = 0; i < 4; i++)
#pragma unroll
        for (int j = 0; j < 8; j++)
#pragma unroll
            for (int c = 0; c < 4; c++) acc[i][j][c] = 0.f;

    const int arow = wm * 64 + (lane & 7) + ((lane >> 3) & 1) * 8;   // + mt*16
    const int acol = ((lane >> 4) & 1) * 8;                          // + ks*16
    const int brow = wn * 64 + (lane & 7) + ((lane >> 4) & 1) * 8;   // + jp*16
    const int bcol = ((lane >> 3) & 1) * 8;                          // + ks*16

    const int nk = K / BK;
    load_stage(0, 0);

    for (int c = 0; c < nk; c++) {
        // Issue next-stage load first so it overlaps this stage's compute.
        if (c + 1 < nk) {
            load_stage((c + 1) & 1, (c + 1) * BK);
            cp_wait1();          // wait only for the current stage
        } else {
            cp_wait0();
        }
        __syncthreads();

        const uint32_t stg = sbase + (c & 1) * STAGE_B;
        const uint32_t sAhi = stg;
        const uint32_t sAlo = stg + TILE_B;
        const uint32_t sBhi = stg + 2 * TILE_B;
        const uint32_t sBlo = stg + 3 * TILE_B;

#pragma unroll
        for (int ks = 0; ks < 2; ks++) {
            uint32_t ahi[4][4], alo[4][4];
            uint32_t bhi[8][2], blo[8][2];
#pragma unroll
            for (int mt = 0; mt < 4; mt++) {
                uint32_t off = (uint32_t)(((arow + mt * 16) * ASTRIDE) + ks * 16 + acol) * 2;
                ldm_x4(ahi[mt], sAhi + off);
                ldm_x4(alo[mt], sAlo + off);
            }
#pragma unroll
            for (int jp = 0; jp < 4; jp++) {
                uint32_t off = (uint32_t)(((brow + jp * 16) * ASTRIDE) + ks * 16 + bcol) * 2;
                uint32_t r[4];
                ldm_x4(r, sBhi + off);
                bhi[jp * 2][0] = r[0]; bhi[jp * 2][1] = r[1];
                bhi[jp * 2 + 1][0] = r[2]; bhi[jp * 2 + 1][1] = r[3];
                ldm_x4(r, sBlo + off);
                blo[jp * 2][0] = r[0]; blo[jp * 2][1] = r[1];
                blo[jp * 2 + 1][0] = r[2]; blo[jp * 2 + 1][1] = r[3];
            }
#pragma unroll
            for (int mt = 0; mt < 4; mt++)
#pragma unroll
                for (int nt = 0; nt < 8; nt++) {
                    mma_bf16(acc[mt][nt], ahi[mt], bhi[nt]);
                    mma_bf16(acc[mt][nt], ahi[mt], blo[nt]);
                    mma_bf16(acc[mt][nt], alo[mt], bhi[nt]);
                }
        }
        __syncthreads();   // all reads of this stage done before it is refilled
    }

    const int g = lane >> 2, t = lane & 3;
#pragma unroll
    for (int mt = 0; mt < 4; mt++) {
#pragma unroll
        for (int nt = 0; nt < 8; nt++) {
            size_t r0 = (size_t)(bm + wm * 64 + mt * 16 + g);
            int col = bn + wn * 64 + nt * 8 + t * 2;
            *(float2*)&C[r0 * N + col] = make_float2(acc[mt][nt][0], acc[mt][nt][1]);
            *(float2*)&C[(r0 + 8) * N + col] = make_float2(acc[mt][nt][2], acc[mt][nt][3]);
        }
    }
}

// ===========================================================================
// Rope + split: g_qkv fp32 -> Q/K (rotated) and V, bf16 hi/lo, [B,H,S,dk].
// ===========================================================================
__global__ void rope_split_kernel() {
    int idx = blockIdx.x * blockDim.x + threadIdx.x;
    const int total = BATCH * NH * S_LEN * 64;   // 2^22
    if (idx >= total) return;
    int j = idx & 63;
    int s = (idx >> 6) & (S_LEN - 1);
    int h = (idx >> 17) & 15;
    int b = idx >> 21;

    float freq = expf((float)j * (-9.210340371976184f / 63.0f));
    float theta = (float)s * freq;
    float sn, cs;
    sincosf(theta, &sn, &cs);

    size_t ibase = ((size_t)(b * S_LEN + s)) * 3 * (size_t)D_MODEL + (size_t)h * DK;
    size_t obase = (((size_t)(b * NH + h)) * S_LEN + s) * (size_t)DK;

    // Q (t=0)
    {
        float x1 = g_qkv[ibase + j], x2 = g_qkv[ibase + 64 + j];
        float y1 = x1 * cs - x2 * sn;
        float y2 = x1 * sn + x2 * cs;
        __nv_bfloat16 h1 = __float2bfloat16(y1), h2 = __float2bfloat16(y2);
        g_q_hi[obase + j] = h1;      g_q_lo[obase + j] = __float2bfloat16(y1 - __bfloat162float(h1));
        g_q_hi[obase + 64 + j] = h2; g_q_lo[obase + 64 + j] = __float2bfloat16(y2 - __bfloat162float(h2));
    }
    // K (t=1)
    {
        float x1 = g_qkv[ibase + D_MODEL + j], x2 = g_qkv[ibase + D_MODEL + 64 + j];
        float y1 = x1 * cs - x2 * sn;
        float y2 = x1 * sn + x2 * cs;
        __nv_bfloat16 h1 = __float2bfloat16(y1), h2 = __float2bfloat16(y2);
        g_k_hi[obase + j] = h1;      g_k_lo[obase + j] = __float2bfloat16(y1 - __bfloat162float(h1));
        g_k_hi[obase + 64 + j] = h2; g_k_lo[obase + 64 + j] = __float2bfloat16(y2 - __bfloat162float(h2));
    }
    // V (t=2), passthrough split
    {
        float x1 = g_qkv[ibase + 2 * D_MODEL + j], x2 = g_qkv[ibase + 2 * D_MODEL + 64 + j];
        __nv_bfloat16 h1 = __float2bfloat16(x1), h2 = __float2bfloat16(x2);
        g_v_hi[obase + j] = h1;      g_v_lo[obase + j] = __float2bfloat16(x1 - __bfloat162float(h1));
        g_v_hi[obase + 64 + j] = h2; g_v_lo[obase + 64 + j] = __float2bfloat16(x2 - __bfloat162float(h2));
    }
}

// ===========================================================================
// HMMA causal flash attention. 128 threads (4 warps), BM=64 (16 q-rows/warp),
// BN=64 kv per iter, dk=128. hi/lo 3-pass for QK and PV. fp32 softmax.
// Heavy (large-qblk) blocks launch first to kill the tail wave.
// ===========================================================================
#define FSTR 136                          // smem row stride in bf16 elems (128 + 8)
#define FTILE (64 * FSTR)                 // elems per tile
#define FLASH_SMEM (6 * FTILE * 2)        // 104448 B (x2 CTAs = 208896 <= 227KB)

__global__ __launch_bounds__(128, 2)
void flash_hmma() {
    extern __shared__ __nv_bfloat16 fsm[];
    const uint32_t sb = smem_u32(fsm);
    const uint32_t sQh = sb;
    const uint32_t sQl = sb + 1 * FTILE * 2;
    const uint32_t sKh = sb + 2 * FTILE * 2;
    const uint32_t sKl = sb + 3 * FTILE * 2;
    const uint32_t sVh = sb + 4 * FTILE * 2;
    const uint32_t sVl = sb + 5 * FTILE * 2;

    const int qblk = (int)gridDim.x - 1 - (int)blockIdx.x;   // heavy blocks first
    const int h = blockIdx.y, b = blockIdx.z;
    const int tid = (int)threadIdx.x;
    const int w = tid >> 5, lane = tid & 31;
    const int g = lane >> 2, t4 = lane & 3;
    const float scale = 0.08838834764831845f;   // 1/sqrt(128)

    const size_t hbase = (((size_t)(b * NH + h)) * S_LEN) * (size_t)DK;

    // Load Q tiles (hi/lo): 64 rows x 128 elems each
    {
        const __nv_bfloat16* qh = g_q_hi + hbase + (size_t)qblk * 64 * DK;
        const __nv_bfloat16* ql = g_q_lo + hbase + (size_t)qblk * 64 * DK;
#pragma unroll
        for (int i = 0; i < 8; i++) {
            int e = i * 128 + tid;
            int row = e >> 4, c16 = e & 15;
            uint4 v = *(const uint4*)(qh + (size_t)row * DK + c16 * 8);
            *(uint4*)(fsm + 0 * FTILE + row * FSTR + c16 * 8) = v;
            v = *(const uint4*)(ql + (size_t)row * DK + c16 * 8);
            *(uint4*)(fsm + 1 * FTILE + row * FSTR + c16 * 8) = v;
        }
    }

    float o[16][4];
    float m_i[2] = {-1e30f, -1e30f}, l_i[2] = {0.f, 0.f};
#pragma unroll
    for (int nb = 0; nb < 16; nb++)
#pragma unroll
        for (int e = 0; e < 4; e++) o[nb][e] = 0.f;

    // ldmatrix address components
    const int aQrow = w * 16 + (lane & 7) + ((lane >> 3) & 1) * 8;
    const int aQcol = ((lane >> 4) & 1) * 8;
    const int bKrow = (lane & 7) + ((lane >> 4) & 1) * 8;   // + jp*16
    const int bKcol = ((lane >> 3) & 1) * 8;                // + k16*16
    const int vRow  = (lane & 7) + ((lane >> 3) & 1) * 8;   // + j*16
    const int vCol  = ((lane >> 4) & 1) * 8;                // + nt2*16

    for (int jblk = 0; jblk <= qblk; jblk++) {
        __syncthreads();
        // Load K/V (hi/lo) for this block
        {
            const size_t base = hbase + (size_t)jblk * 64 * DK;
#pragma unroll
            for (int i = 0; i < 8; i++) {
                int e = i * 128 + tid;
                int row = e >> 4, c16 = e & 15;
                size_t go = base + (size_t)row * DK + c16 * 8;
                int so = row * FSTR + c16 * 8;
                *(uint4*)(fsm + 2 * FTILE + so) = *(const uint4*)(g_k_hi + go);
                *(uint4*)(fsm + 3 * FTILE + so) = *(const uint4*)(g_k_lo + go);
                *(uint4*)(fsm + 4 * FTILE + so) = *(const uint4*)(g_v_hi + go);
                *(uint4*)(fsm + 5 * FTILE + so) = *(const uint4*)(g_v_lo + go);
            }
        }
        __syncthreads();

        // ---- QK^T ----  (each warp covers ALL 64 kv cols: jp = 0..3)
        float sc[8][4];
#pragma unroll
        for (int nt = 0; nt < 8; nt++)
#pragma unroll
            for (int e = 0; e < 4; e++) sc[nt][e] = 0.f;

#pragma unroll
        for (int k16 = 0; k16 < 8; k16++) {
            uint32_t qh[4], ql[4];
            uint32_t qoff = (uint32_t)(aQrow * FSTR + k16 * 16 + aQcol) * 2;
            ldm_x4(qh, sQh + qoff);
            ldm_x4(ql, sQl + qoff);
#pragma unroll
            for (int jp = 0; jp < 4; jp++) {
                uint32_t koff = (uint32_t)((bKrow + jp * 16) * FSTR + k16 * 16 + bKcol) * 2;
                uint32_t kh[4], kl[4];
                ldm_x4(kh, sKh + koff);
                ldm_x4(kl, sKl + koff);
                mma_bf16(sc[jp * 2],     qh, &kh[0]);
                mma_bf16(sc[jp * 2],     qh, &kl[0]);
                mma_bf16(sc[jp * 2],     ql, &kh[0]);
                mma_bf16(sc[jp * 2 + 1], qh, &kh[2]);
                mma_bf16(sc[jp * 2 + 1], qh, &kl[2]);
                mma_bf16(sc[jp * 2 + 1], ql, &kh[2]);
            }
        }

        // ---- scale + causal mask ----
#pragma unroll
        for (int nt = 0; nt < 8; nt++)
#pragma unroll
            for (int e = 0; e < 4; e++) sc[nt][e] *= scale;
        if (jblk == qblk) {
            const int qr0 = w * 16 + g, qr1 = qr0 + 8;
#pragma unroll
            for (int nt = 0; nt < 8; nt++) {
                int kc = nt * 8 + t4 * 2;
                if (kc > qr0)     sc[nt][0] = -1e30f;
                if (kc + 1 > qr0) sc[nt][1] = -1e30f;
                if (kc > qr1)     sc[nt][2] = -1e30f;
                if (kc + 1 > qr1) sc[nt][3] = -1e30f;
            }
        }

        // ---- online softmax (rows g, g+8) ----
        float r0 = -1e30f, r1 = -1e30f;
#pragma unroll
        for (int nt = 0; nt < 8; nt++) {
            r0 = fmaxf(r0, fmaxf(sc[nt][0], sc[nt][1]));
            r1 = fmaxf(r1, fmaxf(sc[nt][2], sc[nt][3]));
        }
        r0 = fmaxf(r0, __shfl_xor_sync(0xffffffffu, r0, 1));
        r0 = fmaxf(r0, __shfl_xor_sync(0xffffffffu, r0, 2));
        r1 = fmaxf(r1, __shfl_xor_sync(0xffffffffu, r1, 1));
        r1 = fmaxf(r1, __shfl_xor_sync(0xffffffffu, r1, 2));
        float mnew0 = fmaxf(m_i[0], r0), mnew1 = fmaxf(m_i[1], r1);
        float corr0 = __expf(m_i[0] - mnew0), corr1 = __expf(m_i[1] - mnew1);
        m_i[0] = mnew0; m_i[1] = mnew1;

        float sum0 = 0.f, sum1 = 0.f;
#pragma unroll
        for (int nt = 0; nt < 8; nt++) {
            sc[nt][0] = __expf(sc[nt][0] - mnew0);
            sc[nt][1] = __expf(sc[nt][1] - mnew0);
            sc[nt][2] = __expf(sc[nt][2] - mnew1);
            sc[nt][3] = __expf(sc[nt][3] - mnew1);
            sum0 += sc[nt][0] + sc[nt][1];
            sum1 += sc[nt][2] + sc[nt][3];
        }
        sum0 += __shfl_xor_sync(0xffffffffu, sum0, 1);
        sum0 += __shfl_xor_sync(0xffffffffu, sum0, 2);
        sum1 += __shfl_xor_sync(0xffffffffu, sum1, 1);
        sum1 += __shfl_xor_sync(0xffffffffu, sum1, 2);
        l_i[0] = l_i[0] * corr0 + sum0;
        l_i[1] = l_i[1] * corr1 + sum1;

#pragma unroll
        for (int nb = 0; nb < 16; nb++) {
            o[nb][0] *= corr0; o[nb][1] *= corr0;
            o[nb][2] *= corr1; o[nb][3] *= corr1;
        }

        // ---- P -> A fragments (register-only, hi/lo) ----
        uint32_t ph[4][4], pl[4][4];
#pragma unroll
        for (int j = 0; j < 4; j++) {
            pack_hl(sc[2 * j][0],     sc[2 * j][1],     ph[j][0], pl[j][0]);
            pack_hl(sc[2 * j][2],     sc[2 * j][3],     ph[j][1], pl[j][1]);
            pack_hl(sc[2 * j + 1][0], sc[2 * j + 1][1], ph[j][2], pl[j][2]);
            pack_hl(sc[2 * j + 1][2], sc[2 * j + 1][3], ph[j][3], pl[j][3]);
        }

        // ---- O += P @ V ----
#pragma unroll
        for (int j = 0; j < 4; j++) {
#pragma unroll
            for (int nt2 = 0; nt2 < 8; nt2++) {
                uint32_t voff = (uint32_t)((j * 16 + vRow) * FSTR + nt2 * 16 + vCol) * 2;
                uint32_t vh[4], vl[4];
                ldm_x4_t(vh, sVh + voff);
                ldm_x4_t(vl, sVl + voff);
                mma_bf16(o[nt2 * 2],     ph[j], &vh[0]);
                mma_bf16(o[nt2 * 2],     ph[j], &vl[0]);
                mma_bf16(o[nt2 * 2],     pl[j], &vh[0]);
                mma_bf16(o[nt2 * 2 + 1], ph[j], &vh[2]);
                mma_bf16(o[nt2 * 2 + 1], ph[j], &vl[2]);
                mma_bf16(o[nt2 * 2 + 1], pl[j], &vh[2]);
            }
        }
    }

    // ---- epilogue: normalize, split to bf16 hi/lo, write [B,S,H*dk] ----
    float inv0 = 1.0f / l_i[0], inv1 = 1.0f / l_i[1];
    size_t row0 = (size_t)(b * S_LEN + qblk * 64 + w * 16 + g);
    size_t row1 = row0 + 8;
#pragma unroll
    for (int nb = 0; nb < 16; nb++) {
        int col = h * DK + nb * 8 + t4 * 2;
        uint32_t hp, lp;
        pack_hl(o[nb][0] * inv0, o[nb][1] * inv0, hp, lp);
        *(uint32_t*)&g_ahi[row0 * D_MODEL + col] = hp;
        *(uint32_t*)&g_alo[row0 * D_MODEL + col] = lp;
        pack_hl(o[nb][2] * inv1, o[nb][3] * inv1, hp, lp);
        *(uint32_t*)&g_ahi[row1 * D_MODEL + col] = hp;
        *(uint32_t*)&g_alo[row1 * D_MODEL + col] = lp;
    }
}

// ===========================================================================
// Launch
// ===========================================================================
extern "C" void kernel_launch(void* const* d_in, const int* in_sizes, int n_in,
                              void* d_out, int out_size) {
    const float* x     = (const float*)d_in[0];
    const float* w_qkv = (const float*)d_in[1];
    const float* w_o   = (const float*)d_in[2];
    float* out = (float*)d_out;

    float* qkv_ptr;
    __nv_bfloat16 *xhi, *xlo, *wqhi, *wqlo, *wohi, *wolo, *ahi, *alo;
    cudaGetSymbolAddress((void**)&qkv_ptr, g_qkv);
    cudaGetSymbolAddress((void**)&xhi, g_xhi);
    cudaGetSymbolAddress((void**)&xlo, g_xlo);
    cudaGetSymbolAddress((void**)&wqhi, g_wqhi);
    cudaGetSymbolAddress((void**)&wqlo, g_wqlo);
    cudaGetSymbolAddress((void**)&wohi, g_wohi);
    cudaGetSymbolAddress((void**)&wolo, g_wolo);
    cudaGetSymbolAddress((void**)&ahi, g_ahi);
    cudaGetSymbolAddress((void**)&alo, g_alo);

    const int M = BATCH * S_LEN;  // 4096

    // 0) Split inputs to bf16 hi/lo
    split_kernel<<<(XN + 255) / 256, 256>>>(x, xhi, xlo, XN);
    split_kernel<<<(WQN + 255) / 256, 256>>>(w_qkv, wqhi, wqlo, WQN);
    split_kernel<<<(WON + 255) / 256, 256>>>(w_o, wohi, wolo, WON);

    cudaFuncSetAttribute(gemm_hmma_x3, cudaFuncAttributeMaxDynamicSharedMemorySize,
                         GEMM_SMEM);

    // 1) QKV projection
    {
        dim3 grid((3 * D_MODEL) / 128, M / 128);
        gemm_hmma_x3<<<grid, 128, GEMM_SMEM>>>(xhi, xlo, wqhi, wqlo, qkv_ptr,
                                               M, 3 * D_MODEL, D_MODEL);
    }
    // 2) Rope + split to head-major bf16 hi/lo
    {
        int n = BATCH * NH * S_LEN * 64;
        rope_split_kernel<<<(n + 255) / 256, 256>>>();
    }
    // 3) HMMA causal flash attention
    {
        cudaFuncSetAttribute(flash_hmma, cudaFuncAttributeMaxDynamicSharedMemorySize,
                             FLASH_SMEM);
        dim3 grid(S_LEN / 64, NH, BATCH);
        flash_hmma<<<grid, 128, FLASH_SMEM>>>();
    }
    // 4) Output projection
    {
        dim3 grid(D_MODEL / 128, M / 128);
        gemm_hmma_x3<<<grid, 128, GEMM_SMEM>>>(ahi, alo, wohi, wolo, out,
                                               M, D_MODEL, D_MODEL);
    }
}

// round 12
// speedup vs baseline: 3.5429x; 1.0061x over previous
#include <cuda_runtime.h>
#include <cuda_bf16.h>
#include <math.h>
#include <stdint.h>

#define D_MODEL 2048
#define NH 16
#define DK 128
#define S_LEN 2048
#define BATCH 2

#define XN   (4096 * 2048)
#define WQN  (6144 * 2048)
#define WON  (2048 * 2048)
#define QKVN (BATCH * NH * S_LEN * DK)    // 8.4M per tensor

// Scratch (device globals — no allocations allowed)
__device__ float g_qkv[(size_t)BATCH * S_LEN * 3 * D_MODEL];   // [B,S,3,H,dk] fp32
__device__ __nv_bfloat16 g_xhi[XN],  g_xlo[XN];
__device__ __nv_bfloat16 g_wqhi[WQN], g_wqlo[WQN];
__device__ __nv_bfloat16 g_wohi[WON], g_wolo[WON];
__device__ __nv_bfloat16 g_ahi[XN],  g_alo[XN];                // attention out hi/lo
// Rope-split Q/K/V, head-major [B,H,S,dk]
__device__ __nv_bfloat16 g_q_hi[QKVN], g_q_lo[QKVN];
__device__ __nv_bfloat16 g_k_hi[QKVN], g_k_lo[QKVN];
__device__ __nv_bfloat16 g_v_hi[QKVN], g_v_lo[QKVN];

// ===========================================================================
// PTX helpers (sm_100-safe: mma.sync / ldmatrix / cp.async)
// ===========================================================================
__device__ __forceinline__ uint32_t smem_u32(const void* p) {
    uint32_t a;
    asm("{ .reg .u64 t; cvta.to.shared.u64 t, %1; cvt.u32.u64 %0, t; }"
        : "=r"(a) : "l"(p));
    return a;
}
__device__ __forceinline__ void cp16(uint32_t dst, const void* src) {
    asm volatile("cp.async.cg.shared.global [%0], [%1], 16;"
                 :: "r"(dst), "l"(src) : "memory");
}
__device__ __forceinline__ void cp_commit() {
    asm volatile("cp.async.commit_group;" ::: "memory");
}
__device__ __forceinline__ void cp_wait0() {
    asm volatile("cp.async.wait_group 0;" ::: "memory");
}
__device__ __forceinline__ void cp_wait1() {
    asm volatile("cp.async.wait_group 1;" ::: "memory");
}
__device__ __forceinline__ void ldm_x4(uint32_t* r, uint32_t addr) {
    asm volatile("ldmatrix.sync.aligned.m8n8.x4.shared.b16 {%0,%1,%2,%3}, [%4];"
                 : "=r"(r[0]), "=r"(r[1]), "=r"(r[2]), "=r"(r[3]) : "r"(addr));
}
__device__ __forceinline__ void ldm_x4_t(uint32_t* r, uint32_t addr) {
    asm volatile("ldmatrix.sync.aligned.m8n8.x4.trans.shared.b16 {%0,%1,%2,%3}, [%4];"
                 : "=r"(r[0]), "=r"(r[1]), "=r"(r[2]), "=r"(r[3]) : "r"(addr));
}
__device__ __forceinline__ void mma_bf16(float* d, const uint32_t* a, const uint32_t* b) {
    asm volatile(
        "mma.sync.aligned.m16n8k16.row.col.f32.bf16.bf16.f32 "
        "{%0,%1,%2,%3}, {%4,%5,%6,%7}, {%8,%9}, {%0,%1,%2,%3};"
        : "+f"(d[0]), "+f"(d[1]), "+f"(d[2]), "+f"(d[3])
        : "r"(a[0]), "r"(a[1]), "r"(a[2]), "r"(a[3]), "r"(b[0]), "r"(b[1]));
}
__device__ __forceinline__ void pack_hl(float a, float b, uint32_t& h, uint32_t& l) {
    __nv_bfloat162 hb = __floats2bfloat162_rn(a, b);
    h = *(uint32_t*)&hb;
    float ra = a - __bfloat162float(hb.x);
    float rb = b - __bfloat162float(hb.y);
    __nv_bfloat162 lb = __floats2bfloat162_rn(ra, rb);
    l = *(uint32_t*)&lb;
}

// ===========================================================================
// Split fp32 -> bf16 hi + bf16 lo
// ===========================================================================
__global__ void split_kernel(const float* __restrict__ src,
                             __nv_bfloat16* __restrict__ hi,
                             __nv_bfloat16* __restrict__ lo, int n) {
    int i = blockIdx.x * blockDim.x + threadIdx.x;
    if (i >= n) return;
    float v = src[i];
    __nv_bfloat16 h = __float2bfloat16(v);
    hi[i] = h;
    lo[i] = __float2bfloat16(v - __bfloat162float(h));
}

// ===========================================================================
// HMMA GEMM: C[M,N] = A[M,K] @ B[N,K]^T, bf16 hi/lo 3-pass, fp32 accum.
// 128x128 CTA tile, 4 warps (64x64 warp tile), BK=32, 2-stage, 2 CTAs/SM.
// PASS-MAJOR MMA ordering: 32 independent MMAs between writes to the same
// accumulator -> no RAW issue stalls (asm volatile fixes instruction order).
// ===========================================================================
#define BK 32
#define ASTRIDE 40                        // bf16 elems per smem row (32 + 8 pad)
#define TILE_B (128 * ASTRIDE * 2)        // 10240 B per tile
#define STAGE_B (4 * TILE_B)              // Ahi,Alo,Bhi,Blo = 40960 B
#define GEMM_SMEM (2 * STAGE_B)           // 81920 B  (x2 CTAs = 163840 <= 227KB)

__global__ __launch_bounds__(128, 2)
void gemm_hmma_x3(const __nv_bfloat16* __restrict__ Ahi, const __nv_bfloat16* __restrict__ Alo,
                  const __nv_bfloat16* __restrict__ Bhi, const __nv_bfloat16* __restrict__ Blo,
                  float* __restrict__ C, int M, int N, int K) {
    extern __shared__ char dynsmem[];
    const uint32_t sbase = smem_u32(dynsmem);

    const int tid  = (int)threadIdx.x;
    const int wid  = tid >> 5;
    const int lane = tid & 31;
    const int bm = blockIdx.y * 128, bn = blockIdx.x * 128;
    const int wm = wid & 1;               // 0..1 -> 64-row half
    const int wn = wid >> 1;              // 0..1 -> 64-col half

    const __nv_bfloat16* srcs[4] = {
        Ahi + (size_t)bm * K, Alo + (size_t)bm * K,
        Bhi + (size_t)bn * K, Blo + (size_t)bn * K };

    auto load_stage = [&](int stage, int k0) {
        const uint32_t stg = sbase + stage * STAGE_B;
#pragma unroll
        for (int i = 0; i < 16; i++) {
            int linear = i * 128 + tid;           // 0..2047
            int t   = linear >> 9;                // tile 0..3
            int row = (linear >> 2) & 127;        // row 0..127
            int c16 = linear & 3;                 // 16B chunk 0..3
            const __nv_bfloat16* src = srcs[t] + (size_t)row * K + k0 + c16 * 8;
            cp16(stg + t * TILE_B + (row * ASTRIDE + c16 * 8) * 2, src);
        }
        cp_commit();
    };

    float acc[4][8][4];
#pragma unroll
    for (int i = 0; i < 4; i++)
#pragma unroll
        for (int j = 0; j < 8; j++)
#pragma unroll
            for (int c = 0; c < 4; c++) acc[i][j][c] = 0.f;

    const int arow = wm * 64 + (lane & 7) + ((lane >> 3) & 1) * 8;   // + mt*16
    const int acol = ((lane >> 4) & 1) * 8;                          // + ks*16
    const int brow = wn * 64 + (lane & 7) + ((lane >> 4) & 1) * 8;   // + jp*16
    const int bcol = ((lane >> 3) & 1) * 8;                          // + ks*16

    const int nk = K / BK;
    load_stage(0, 0);

    for (int c = 0; c < nk; c++) {
        // Issue next-stage load first so it overlaps this stage's compute.
        if (c + 1 < nk) {
            load_stage((c + 1) & 1, (c + 1) * BK);
            cp_wait1();          // wait only for the current stage
        } else {
            cp_wait0();
        }
        __syncthreads();

        const uint32_t stg = sbase + (c & 1) * STAGE_B;
        const uint32_t sAhi = stg;
        const uint32_t sAlo = stg + TILE_B;
        const uint32_t sBhi = stg + 2 * TILE_B;
        const uint32_t sBlo = stg + 3 * TILE_B;

#pragma unroll
        for (int ks = 0; ks < 2; ks++) {
            uint32_t ahi[4][4], alo[4][4];
            uint32_t bhi[8][2], blo[8][2];
#pragma unroll
            for (int mt = 0; mt < 4; mt++) {
                uint32_t off = (uint32_t)(((arow + mt * 16) * ASTRIDE) + ks * 16 + acol) * 2;
                ldm_x4(ahi[mt], sAhi + off);
                ldm_x4(alo[mt], sAlo + off);
            }
#pragma unroll
            for (int jp = 0; jp < 4; jp++) {
                uint32_t off = (uint32_t)(((brow + jp * 16) * ASTRIDE) + ks * 16 + bcol) * 2;
                uint32_t r[4];
                ldm_x4(r, sBhi + off);
                bhi[jp * 2][0] = r[0]; bhi[jp * 2][1] = r[1];
                bhi[jp * 2 + 1][0] = r[2]; bhi[jp * 2 + 1][1] = r[3];
                ldm_x4(r, sBlo + off);
                blo[jp * 2][0] = r[0]; blo[jp * 2][1] = r[1];
                blo[jp * 2 + 1][0] = r[2]; blo[jp * 2 + 1][1] = r[3];
            }
            // Pass-major: per-acc order is hh -> hl -> lh (identical numerics),
            // but consecutive instructions target different accumulators.
#pragma unroll
            for (int mt = 0; mt < 4; mt++)
#pragma unroll
                for (int nt = 0; nt < 8; nt++)
                    mma_bf16(acc[mt][nt], ahi[mt], bhi[nt]);
#pragma unroll
            for (int mt = 0; mt < 4; mt++)
#pragma unroll
                for (int nt = 0; nt < 8; nt++)
                    mma_bf16(acc[mt][nt], ahi[mt], blo[nt]);
#pragma unroll
            for (int mt = 0; mt < 4; mt++)
#pragma unroll
                for (int nt = 0; nt < 8; nt++)
                    mma_bf16(acc[mt][nt], alo[mt], bhi[nt]);
        }
        __syncthreads();   // all reads of this stage done before it is refilled
    }

    const int g = lane >> 2, t = lane & 3;
#pragma unroll
    for (int mt = 0; mt < 4; mt++) {
#pragma unroll
        for (int nt = 0; nt < 8; nt++) {
            size_t r0 = (size_t)(bm + wm * 64 + mt * 16 + g);
            int col = bn + wn * 64 + nt * 8 + t * 2;
            *(float2*)&C[r0 * N + col] = make_float2(acc[mt][nt][0], acc[mt][nt][1]);
            *(float2*)&C[(r0 + 8) * N + col] = make_float2(acc[mt][nt][2], acc[mt][nt][3]);
        }
    }
}

// ===========================================================================
// Rope + split: g_qkv fp32 -> Q/K (rotated) and V, bf16 hi/lo, [B,H,S,dk].
// ===========================================================================
__global__ void rope_split_kernel() {
    int idx = blockIdx.x * blockDim.x + threadIdx.x;
    const int total = BATCH * NH * S_LEN * 64;   // 2^22
    if (idx >= total) return;
    int j = idx & 63;
    int s = (idx >> 6) & (S_LEN - 1);
    int h = (idx >> 17) & 15;
    int b = idx >> 21;

    float freq = expf((float)j * (-9.210340371976184f / 63.0f));
    float theta = (float)s * freq;
    float sn, cs;
    sincosf(theta, &sn, &cs);

    size_t ibase = ((size_t)(b * S_LEN + s)) * 3 * (size_t)D_MODEL + (size_t)h * DK;
    size_t obase = (((size_t)(b * NH + h)) * S_LEN + s) * (size_t)DK;

    // Q (t=0)
    {
        float x1 = g_qkv[ibase + j], x2 = g_qkv[ibase + 64 + j];
        float y1 = x1 * cs - x2 * sn;
        float y2 = x1 * sn + x2 * cs;
        __nv_bfloat16 h1 = __float2bfloat16(y1), h2 = __float2bfloat16(y2);
        g_q_hi[obase + j] = h1;      g_q_lo[obase + j] = __float2bfloat16(y1 - __bfloat162float(h1));
        g_q_hi[obase + 64 + j] = h2; g_q_lo[obase + 64 + j] = __float2bfloat16(y2 - __bfloat162float(h2));
    }
    // K (t=1)
    {
        float x1 = g_qkv[ibase + D_MODEL + j], x2 = g_qkv[ibase + D_MODEL + 64 + j];
        float y1 = x1 * cs - x2 * sn;
        float y2 = x1 * sn + x2 * cs;
        __nv_bfloat16 h1 = __float2bfloat16(y1), h2 = __float2bfloat16(y2);
        g_k_hi[obase + j] = h1;      g_k_lo[obase + j] = __float2bfloat16(y1 - __bfloat162float(h1));
        g_k_hi[obase + 64 + j] = h2; g_k_lo[obase + 64 + j] = __float2bfloat16(y2 - __bfloat162float(h2));
    }
    // V (t=2), passthrough split
    {
        float x1 = g_qkv[ibase + 2 * D_MODEL + j], x2 = g_qkv[ibase + 2 * D_MODEL + 64 + j];
        __nv_bfloat16 h1 = __float2bfloat16(x1), h2 = __float2bfloat16(x2);
        g_v_hi[obase + j] = h1;      g_v_lo[obase + j] = __float2bfloat16(x1 - __bfloat162float(h1));
        g_v_hi[obase + 64 + j] = h2; g_v_lo[obase + 64 + j] = __float2bfloat16(x2 - __bfloat162float(h2));
    }
}

// ===========================================================================
// HMMA causal flash attention. 128 threads (4 warps), BM=64 (16 q-rows/warp),
// BN=64 kv per iter, dk=128. hi/lo 3-pass for QK and PV. fp32 softmax.
// Pass-major / interleaved MMA ordering to avoid RAW issue stalls.
// ===========================================================================
#define FSTR 136                          // smem row stride in bf16 elems (128 + 8)
#define FTILE (64 * FSTR)                 // elems per tile
#define FLASH_SMEM (6 * FTILE * 2)        // 104448 B (x2 CTAs = 208896 <= 227KB)

__global__ __launch_bounds__(128, 2)
void flash_hmma() {
    extern __shared__ __nv_bfloat16 fsm[];
    const uint32_t sb = smem_u32(fsm);
    const uint32_t sQh = sb;
    const uint32_t sQl = sb + 1 * FTILE * 2;
    const uint32_t sKh = sb + 2 * FTILE * 2;
    const uint32_t sKl = sb + 3 * FTILE * 2;
    const uint32_t sVh = sb + 4 * FTILE * 2;
    const uint32_t sVl = sb + 5 * FTILE * 2;

    const int qblk = (int)gridDim.x - 1 - (int)blockIdx.x;   // heavy blocks first
    const int h = blockIdx.y, b = blockIdx.z;
    const int tid = (int)threadIdx.x;
    const int w = tid >> 5, lane = tid & 31;
    const int g = lane >> 2, t4 = lane & 3;
    const float scale = 0.08838834764831845f;   // 1/sqrt(128)

    const size_t hbase = (((size_t)(b * NH + h)) * S_LEN) * (size_t)DK;

    // Load Q tiles (hi/lo): 64 rows x 128 elems each
    {
        const __nv_bfloat16* qh = g_q_hi + hbase + (size_t)qblk * 64 * DK;
        const __nv_bfloat16* ql = g_q_lo + hbase + (size_t)qblk * 64 * DK;
#pragma unroll
        for (int i = 0; i < 8; i++) {
            int e = i * 128 + tid;
            int row = e >> 4, c16 = e & 15;
            uint4 v = *(const uint4*)(qh + (size_t)row * DK + c16 * 8);
            *(uint4*)(fsm + 0 * FTILE + row * FSTR + c16 * 8) = v;
            v = *(const uint4*)(ql + (size_t)row * DK + c16 * 8);
            *(uint4*)(fsm + 1 * FTILE + row * FSTR + c16 * 8) = v;
        }
    }

    float o[16][4];
    float m_i[2] = {-1e30f, -1e30f}, l_i[2] = {0.f, 0.f};
#pragma unroll
    for (int nb = 0; nb < 16; nb++)
#pragma unroll
        for (int e = 0; e < 4; e++) o[nb][e] = 0.f;

    // ldmatrix address components
    const int aQrow = w * 16 + (lane & 7) + ((lane >> 3) & 1) * 8;
    const int aQcol = ((lane >> 4) & 1) * 8;
    const int bKrow = (lane & 7) + ((lane >> 4) & 1) * 8;   // + jp*16
    const int bKcol = ((lane >> 3) & 1) * 8;                // + k16*16
    const int vRow  = (lane & 7) + ((lane >> 3) & 1) * 8;   // + j*16
    const int vCol  = ((lane >> 4) & 1) * 8;                // + nt2*16

    for (int jblk = 0; jblk <= qblk; jblk++) {
        __syncthreads();
        // Load K/V (hi/lo) for this block
        {
            const size_t base = hbase + (size_t)jblk * 64 * DK;
#pragma unroll
            for (int i = 0; i < 8; i++) {
                int e = i * 128 + tid;
                int row = e >> 4, c16 = e & 15;
                size_t go = base + (size_t)row * DK + c16 * 8;
                int so = row * FSTR + c16 * 8;
                *(uint4*)(fsm + 2 * FTILE + so) = *(const uint4*)(g_k_hi + go);
                *(uint4*)(fsm + 3 * FTILE + so) = *(const uint4*)(g_k_lo + go);
                *(uint4*)(fsm + 4 * FTILE + so) = *(const uint4*)(g_v_hi + go);
                *(uint4*)(fsm + 5 * FTILE + so) = *(const uint4*)(g_v_lo + go);
            }
        }
        __syncthreads();

        // ---- QK^T ----  pass-major: all K frags preloaded, 8 independent
        // MMAs between writes to the same sc accumulator.
        float sc[8][4];
#pragma unroll
        for (int nt = 0; nt < 8; nt++)
#pragma unroll
            for (int e = 0; e < 4; e++) sc[nt][e] = 0.f;

#pragma unroll
        for (int k16 = 0; k16 < 8; k16++) {
            uint32_t qh[4], ql[4];
            uint32_t qoff = (uint32_t)(aQrow * FSTR + k16 * 16 + aQcol) * 2;
            ldm_x4(qh, sQh + qoff);
            ldm_x4(ql, sQl + qoff);
            uint32_t kh[4][4], kl[4][4];
#pragma unroll
            for (int jp = 0; jp < 4; jp++) {
                uint32_t koff = (uint32_t)((bKrow + jp * 16) * FSTR + k16 * 16 + bKcol) * 2;
                ldm_x4(kh[jp], sKh + koff);
                ldm_x4(kl[jp], sKl + koff);
            }
#pragma unroll
            for (int jp = 0; jp < 4; jp++) {
                mma_bf16(sc[jp * 2],     qh, &kh[jp][0]);
                mma_bf16(sc[jp * 2 + 1], qh, &kh[jp][2]);
            }
#pragma unroll
            for (int jp = 0; jp < 4; jp++) {
                mma_bf16(sc[jp * 2],     qh, &kl[jp][0]);
                mma_bf16(sc[jp * 2 + 1], qh, &kl[jp][2]);
            }
#pragma unroll
            for (int jp = 0; jp < 4; jp++) {
                mma_bf16(sc[jp * 2],     ql, &kh[jp][0]);
                mma_bf16(sc[jp * 2 + 1], ql, &kh[jp][2]);
            }
        }

        // ---- scale + causal mask ----
#pragma unroll
        for (int nt = 0; nt < 8; nt++)
#pragma unroll
            for (int e = 0; e < 4; e++) sc[nt][e] *= scale;
        if (jblk == qblk) {
            const int qr0 = w * 16 + g, qr1 = qr0 + 8;
#pragma unroll
            for (int nt = 0; nt < 8; nt++) {
                int kc = nt * 8 + t4 * 2;
                if (kc > qr0)     sc[nt][0] = -1e30f;
                if (kc + 1 > qr0) sc[nt][1] = -1e30f;
                if (kc > qr1)     sc[nt][2] = -1e30f;
                if (kc + 1 > qr1) sc[nt][3] = -1e30f;
            }
        }

        // ---- online softmax (rows g, g+8) ----
        float r0 = -1e30f, r1 = -1e30f;
#pragma unroll
        for (int nt = 0; nt < 8; nt++) {
            r0 = fmaxf(r0, fmaxf(sc[nt][0], sc[nt][1]));
            r1 = fmaxf(r1, fmaxf(sc[nt][2], sc[nt][3]));
        }
        r0 = fmaxf(r0, __shfl_xor_sync(0xffffffffu, r0, 1));
        r0 = fmaxf(r0, __shfl_xor_sync(0xffffffffu, r0, 2));
        r1 = fmaxf(r1, __shfl_xor_sync(0xffffffffu, r1, 1));
        r1 = fmaxf(r1, __shfl_xor_sync(0xffffffffu, r1, 2));
        float mnew0 = fmaxf(m_i[0], r0), mnew1 = fmaxf(m_i[1], r1);
        float corr0 = __expf(m_i[0] - mnew0), corr1 = __expf(m_i[1] - mnew1);
        m_i[0] = mnew0; m_i[1] = mnew1;

        float sum0 = 0.f, sum1 = 0.f;
#pragma unroll
        for (int nt = 0; nt < 8; nt++) {
            sc[nt][0] = __expf(sc[nt][0] - mnew0);
            sc[nt][1] = __expf(sc[nt][1] - mnew0);
            sc[nt][2] = __expf(sc[nt][2] - mnew1);
            sc[nt][3] = __expf(sc[nt][3] - mnew1);
            sum0 += sc[nt][0] + sc[nt][1];
            sum1 += sc[nt][2] + sc[nt][3];
        }
        sum0 += __shfl_xor_sync(0xffffffffu, sum0, 1);
        sum0 += __shfl_xor_sync(0xffffffffu, sum0, 2);
        sum1 += __shfl_xor_sync(0xffffffffu, sum1, 1);
        sum1 += __shfl_xor_sync(0xffffffffu, sum1, 2);
        l_i[0] = l_i[0] * corr0 + sum0;
        l_i[1] = l_i[1] * corr1 + sum1;

#pragma unroll
        for (int nb = 0; nb < 16; nb++) {
            o[nb][0] *= corr0; o[nb][1] *= corr0;
            o[nb][2] *= corr1; o[nb][3] *= corr1;
        }

        // ---- P -> A fragments (register-only, hi/lo) ----
        uint32_t ph[4][4], pl[4][4];
#pragma unroll
        for (int j = 0; j < 4; j++) {
            pack_hl(sc[2 * j][0],     sc[2 * j][1],     ph[j][0], pl[j][0]);
            pack_hl(sc[2 * j][2],     sc[2 * j][3],     ph[j][1], pl[j][1]);
            pack_hl(sc[2 * j + 1][0], sc[2 * j + 1][1], ph[j][2], pl[j][2]);
            pack_hl(sc[2 * j + 1][2], sc[2 * j + 1][3], ph[j][3], pl[j][3]);
        }

        // ---- O += P @ V ----  nt2 processed in pairs -> 4 interleaved
        // accumulator chains, dependency distance 4 (~latency).
#pragma unroll
        for (int j = 0; j < 4; j++) {
#pragma unroll
            for (int p2 = 0; p2 < 4; p2++) {
                const int nt2a = 2 * p2, nt2b = 2 * p2 + 1;
                uint32_t voffa = (uint32_t)((j * 16 + vRow) * FSTR + nt2a * 16 + vCol) * 2;
                uint32_t voffb = (uint32_t)((j * 16 + vRow) * FSTR + nt2b * 16 + vCol) * 2;
                uint32_t vha[4], vla[4], vhb[4], vlb[4];
                ldm_x4_t(vha, sVh + voffa);
                ldm_x4_t(vla, sVl + voffa);
                ldm_x4_t(vhb, sVh + voffb);
                ldm_x4_t(vlb, sVl + voffb);
                // per-o order preserved: ph*vh, ph*vl, pl*vh
                mma_bf16(o[nt2a * 2],     ph[j], &vha[0]);
                mma_bf16(o[nt2a * 2 + 1], ph[j], &vha[2]);
                mma_bf16(o[nt2b * 2],     ph[j], &vhb[0]);
                mma_bf16(o[nt2b * 2 + 1], ph[j], &vhb[2]);
                mma_bf16(o[nt2a * 2],     ph[j], &vla[0]);
                mma_bf16(o[nt2a * 2 + 1], ph[j], &vla[2]);
                mma_bf16(o[nt2b * 2],     ph[j], &vlb[0]);
                mma_bf16(o[nt2b * 2 + 1], ph[j], &vlb[2]);
                mma_bf16(o[nt2a * 2],     pl[j], &vha[0]);
                mma_bf16(o[nt2a * 2 + 1], pl[j], &vha[2]);
                mma_bf16(o[nt2b * 2],     pl[j], &vhb[0]);
                mma_bf16(o[nt2b * 2 + 1], pl[j], &vhb[2]);
            }
        }
    }

    // ---- epilogue: normalize, split to bf16 hi/lo, write [B,S,H*dk] ----
    float inv0 = 1.0f / l_i[0], inv1 = 1.0f / l_i[1];
    size_t row0 = (size_t)(b * S_LEN + qblk * 64 + w * 16 + g);
    size_t row1 = row0 + 8;
#pragma unroll
    for (int nb = 0; nb < 16; nb++) {
        int col = h * DK + nb * 8 + t4 * 2;
        uint32_t hp, lp;
        pack_hl(o[nb][0] * inv0, o[nb][1] * inv0, hp, lp);
        *(uint32_t*)&g_ahi[row0 * D_MODEL + col] = hp;
        *(uint32_t*)&g_alo[row0 * D_MODEL + col] = lp;
        pack_hl(o[nb][2] * inv1, o[nb][3] * inv1, hp, lp);
        *(uint32_t*)&g_ahi[row1 * D_MODEL + col] = hp;
        *(uint32_t*)&g_alo[row1 * D_MODEL + col] = lp;
    }
}

// ===========================================================================
// Launch
// ===========================================================================
extern "C" void kernel_launch(void* const* d_in, const int* in_sizes, int n_in,
                              void* d_out, int out_size) {
    const float* x     = (const float*)d_in[0];
    const float* w_qkv = (const float*)d_in[1];
    const float* w_o   = (const float*)d_in[2];
    float* out = (float*)d_out;

    float* qkv_ptr;
    __nv_bfloat16 *xhi, *xlo, *wqhi, *wqlo, *wohi, *wolo, *ahi, *alo;
    cudaGetSymbolAddress((void**)&qkv_ptr, g_qkv);
    cudaGetSymbolAddress((void**)&xhi, g_xhi);
    cudaGetSymbolAddress((void**)&xlo, g_xlo);
    cudaGetSymbolAddress((void**)&wqhi, g_wqhi);
    cudaGetSymbolAddress((void**)&wqlo, g_wqlo);
    cudaGetSymbolAddress((void**)&wohi, g_wohi);
    cudaGetSymbolAddress((void**)&wolo, g_wolo);
    cudaGetSymbolAddress((void**)&ahi, g_ahi);
    cudaGetSymbolAddress((void**)&alo, g_alo);

    const int M = BATCH * S_LEN;  // 4096

    // 0) Split inputs to bf16 hi/lo
    split_kernel<<<(XN + 255) / 256, 256>>>(x, xhi, xlo, XN);
    split_kernel<<<(WQN + 255) / 256, 256>>>(w_qkv, wqhi, wqlo, WQN);
    split_kernel<<<(WON + 255) / 256, 256>>>(w_o, wohi, wolo, WON);

    cudaFuncSetAttribute(gemm_hmma_x3, cudaFuncAttributeMaxDynamicSharedMemorySize,
                         GEMM_SMEM);

    // 1) QKV projection
    {
        dim3 grid((3 * D_MODEL) / 128, M / 128);
        gemm_hmma_x3<<<grid, 128, GEMM_SMEM>>>(xhi, xlo, wqhi, wqlo, qkv_ptr,
                                               M, 3 * D_MODEL, D_MODEL);
    }
    // 2) Rope + split to head-major bf16 hi/lo
    {
        int n = BATCH * NH * S_LEN * 64;
        rope_split_kernel<<<(n + 255) / 256, 256>>>();
    }
    // 3) HMMA causal flash attention
    {
        cudaFuncSetAttribute(flash_hmma, cudaFuncAttributeMaxDynamicSharedMemorySize,
                             FLASH_SMEM);
        dim3 grid(S_LEN / 64, NH, BATCH);
        flash_hmma<<<grid, 128, FLASH_SMEM>>>();
    }
    // 4) Output projection
    {
        dim3 grid(D_MODEL / 128, M / 128);
        gemm_hmma_x3<<<grid, 128, GEMM_SMEM>>>(ahi, alo, wohi, wolo, out,
                                               M, D_MODEL, D_MODEL);
    }
}

// round 13
// speedup vs baseline: 4.7110x; 1.3297x over previous
#include <cuda_runtime.h>
#include <cuda_fp16.h>
#include <math.h>
#include <stdint.h>

#define D_MODEL 2048
#define NH 16
#define DK 128
#define S_LEN 2048
#define BATCH 2

#define XN   (4096 * 2048)
#define WQN  (6144 * 2048)
#define WON  (2048 * 2048)
#define QKVN (BATCH * NH * S_LEN * DK)    // 8.4M per tensor

// Scratch (device globals — no allocations allowed)
__device__ float g_qkv[(size_t)BATCH * S_LEN * 3 * D_MODEL];   // [B,S,3,H,dk] fp32
__device__ __half g_xh[XN];                       // x, fp16 (A-side: no lo needed)
__device__ __half g_wqh[WQN], g_wql[WQN];         // w_qkv hi/lo
__device__ __half g_woh[WON], g_wol[WON];         // w_o hi/lo
__device__ __half g_ah[XN];                       // attention out, fp16 (A-side)
// Rope Q/K/V, head-major [B,H,S,dk]; Q is A-side (hi only), K/V are B-side (hi+lo)
__device__ __half g_qh[QKVN];
__device__ __half g_kh[QKVN], g_kl[QKVN];
__device__ __half g_vh[QKVN], g_vl[QKVN];

// ===========================================================================
// PTX helpers (sm_100-safe: mma.sync / ldmatrix / cp.async)
// ===========================================================================
__device__ __forceinline__ uint32_t smem_u32(const void* p) {
    uint32_t a;
    asm("{ .reg .u64 t; cvta.to.shared.u64 t, %1; cvt.u32.u64 %0, t; }"
        : "=r"(a) : "l"(p));
    return a;
}
__device__ __forceinline__ void cp16(uint32_t dst, const void* src) {
    asm volatile("cp.async.cg.shared.global [%0], [%1], 16;"
                 :: "r"(dst), "l"(src) : "memory");
}
__device__ __forceinline__ void cp_commit() {
    asm volatile("cp.async.commit_group;" ::: "memory");
}
__device__ __forceinline__ void cp_wait0() {
    asm volatile("cp.async.wait_group 0;" ::: "memory");
}
__device__ __forceinline__ void cp_wait1() {
    asm volatile("cp.async.wait_group 1;" ::: "memory");
}
__device__ __forceinline__ void ldm_x4(uint32_t* r, uint32_t addr) {
    asm volatile("ldmatrix.sync.aligned.m8n8.x4.shared.b16 {%0,%1,%2,%3}, [%4];"
                 : "=r"(r[0]), "=r"(r[1]), "=r"(r[2]), "=r"(r[3]) : "r"(addr));
}
__device__ __forceinline__ void ldm_x4_t(uint32_t* r, uint32_t addr) {
    asm volatile("ldmatrix.sync.aligned.m8n8.x4.trans.shared.b16 {%0,%1,%2,%3}, [%4];"
                 : "=r"(r[0]), "=r"(r[1]), "=r"(r[2]), "=r"(r[3]) : "r"(addr));
}
__device__ __forceinline__ void mma_f16(float* d, const uint32_t* a, const uint32_t* b) {
    asm volatile(
        "mma.sync.aligned.m16n8k16.row.col.f32.f16.f16.f32 "
        "{%0,%1,%2,%3}, {%4,%5,%6,%7}, {%8,%9}, {%0,%1,%2,%3};"
        : "+f"(d[0]), "+f"(d[1]), "+f"(d[2]), "+f"(d[3])
        : "r"(a[0]), "r"(a[1]), "r"(a[2]), "r"(a[3]), "r"(b[0]), "r"(b[1]));
}
__device__ __forceinline__ uint32_t pack_h2(float a, float b) {
    __half2 hv = __floats2half2_rn(a, b);
    return *(uint32_t*)&hv;
}

// ===========================================================================
// Conversions
// ===========================================================================
__global__ void conv_h_kernel(const float* __restrict__ src,
                              __half* __restrict__ hi, int n) {
    int i = blockIdx.x * blockDim.x + threadIdx.x;
    if (i >= n) return;
    hi[i] = __float2half_rn(src[i]);
}
__global__ void split_h_kernel(const float* __restrict__ src,
                               __half* __restrict__ hi,
                               __half* __restrict__ lo, int n) {
    int i = blockIdx.x * blockDim.x + threadIdx.x;
    if (i >= n) return;
    float v = src[i];
    __half h = __float2half_rn(v);
    hi[i] = h;
    lo[i] = __float2half_rn(v - __half2float(h));
}

// ===========================================================================
// HMMA GEMM: C[M,N] = A_hi[M,K] @ (B_hi + B_lo)[N,K]^T, fp16, fp32 accum.
// 2-pass (A_lo·B_hi dropped, err ~2^-12). 128x128 CTA, 4 warps (64x64 each),
// BK=32, 2-stage cp.async, 2 CTAs/SM. 3 smem tiles/stage.
// ===========================================================================
#define BK 32
#define ASTRIDE 40                        // halfs per smem row (32 + 8 pad)
#define TILE_B (128 * ASTRIDE * 2)        // 10240 B per tile
#define STAGE_B (3 * TILE_B)              // Ah, Bh, Bl = 30720 B
#define GEMM_SMEM (2 * STAGE_B)           // 61440 B (x2 CTAs = 122880)

__global__ __launch_bounds__(128, 2)
void gemm_hmma_x2(const __half* __restrict__ Ah, const __half* __restrict__ Bh,
                  const __half* __restrict__ Bl,
                  float* __restrict__ C, int M, int N, int K) {
    extern __shared__ char dynsmem[];
    const uint32_t sbase = smem_u32(dynsmem);

    const int tid  = (int)threadIdx.x;
    const int wid  = tid >> 5;
    const int lane = tid & 31;
    const int bm = blockIdx.y * 128, bn = blockIdx.x * 128;
    const int wm = wid & 1;
    const int wn = wid >> 1;

    const __half* srcs[3] = {
        Ah + (size_t)bm * K, Bh + (size_t)bn * K, Bl + (size_t)bn * K };

    auto load_stage = [&](int stage, int k0) {
        const uint32_t stg = sbase + stage * STAGE_B;
#pragma unroll
        for (int i = 0; i < 12; i++) {
            int linear = i * 128 + tid;           // 0..1535
            int t   = linear >> 9;                // tile 0..2
            int row = (linear >> 2) & 127;        // row 0..127
            int c16 = linear & 3;                 // 16B chunk 0..3
            const __half* src = srcs[t] + (size_t)row * K + k0 + c16 * 8;
            cp16(stg + t * TILE_B + (row * ASTRIDE + c16 * 8) * 2, src);
        }
        cp_commit();
    };

    float acc[4][8][4];
#pragma unroll
    for (int i = 0; i < 4; i++)
#pragma unroll
        for (int j = 0; j < 8; j++)
#pragma unroll
            for (int c = 0; c < 4; c++) acc[i][j][c] = 0.f;

    const int arow = wm * 64 + (lane & 7) + ((lane >> 3) & 1) * 8;   // + mt*16
    const int acol = ((lane >> 4) & 1) * 8;                          // + ks*16
    const int brow = wn * 64 + (lane & 7) + ((lane >> 4) & 1) * 8;   // + jp*16
    const int bcol = ((lane >> 3) & 1) * 8;                          // + ks*16

    const int nk = K / BK;
    load_stage(0, 0);

    for (int c = 0; c < nk; c++) {
        if (c + 1 < nk) {
            load_stage((c + 1) & 1, (c + 1) * BK);
            cp_wait1();
        } else {
            cp_wait0();
        }
        __syncthreads();

        const uint32_t stg = sbase + (c & 1) * STAGE_B;
        const uint32_t sA  = stg;
        const uint32_t sBh = stg + TILE_B;
        const uint32_t sBl = stg + 2 * TILE_B;

#pragma unroll
        for (int ks = 0; ks < 2; ks++) {
            uint32_t ah[4][4];
            uint32_t bhi[8][2], blo[8][2];
#pragma unroll
            for (int mt = 0; mt < 4; mt++) {
                uint32_t off = (uint32_t)(((arow + mt * 16) * ASTRIDE) + ks * 16 + acol) * 2;
                ldm_x4(ah[mt], sA + off);
            }
#pragma unroll
            for (int jp = 0; jp < 4; jp++) {
                uint32_t off = (uint32_t)(((brow + jp * 16) * ASTRIDE) + ks * 16 + bcol) * 2;
                uint32_t r[4];
                ldm_x4(r, sBh + off);
                bhi[jp * 2][0] = r[0]; bhi[jp * 2][1] = r[1];
                bhi[jp * 2 + 1][0] = r[2]; bhi[jp * 2 + 1][1] = r[3];
                ldm_x4(r, sBl + off);
                blo[jp * 2][0] = r[0]; blo[jp * 2][1] = r[1];
                blo[jp * 2 + 1][0] = r[2]; blo[jp * 2 + 1][1] = r[3];
            }
            // Pass-major: per-acc order hh -> hl.
#pragma unroll
            for (int mt = 0; mt < 4; mt++)
#pragma unroll
                for (int nt = 0; nt < 8; nt++)
                    mma_f16(acc[mt][nt], ah[mt], bhi[nt]);
#pragma unroll
            for (int mt = 0; mt < 4; mt++)
#pragma unroll
                for (int nt = 0; nt < 8; nt++)
                    mma_f16(acc[mt][nt], ah[mt], blo[nt]);
        }
        __syncthreads();
    }

    const int g = lane >> 2, t = lane & 3;
#pragma unroll
    for (int mt = 0; mt < 4; mt++) {
#pragma unroll
        for (int nt = 0; nt < 8; nt++) {
            size_t r0 = (size_t)(bm + wm * 64 + mt * 16 + g);
            int col = bn + wn * 64 + nt * 8 + t * 2;
            *(float2*)&C[r0 * N + col] = make_float2(acc[mt][nt][0], acc[mt][nt][1]);
            *(float2*)&C[(r0 + 8) * N + col] = make_float2(acc[mt][nt][2], acc[mt][nt][3]);
        }
    }
}

// ===========================================================================
// Rope + convert: g_qkv fp32 -> Q (hi), K/V (hi+lo), fp16, [B,H,S,dk].
// ===========================================================================
__global__ void rope_split_kernel() {
    int idx = blockIdx.x * blockDim.x + threadIdx.x;
    const int total = BATCH * NH * S_LEN * 64;   // 2^22
    if (idx >= total) return;
    int j = idx & 63;
    int s = (idx >> 6) & (S_LEN - 1);
    int h = (idx >> 17) & 15;
    int b = idx >> 21;

    float freq = expf((float)j * (-9.210340371976184f / 63.0f));
    float theta = (float)s * freq;
    float sn, cs;
    sincosf(theta, &sn, &cs);

    size_t ibase = ((size_t)(b * S_LEN + s)) * 3 * (size_t)D_MODEL + (size_t)h * DK;
    size_t obase = (((size_t)(b * NH + h)) * S_LEN + s) * (size_t)DK;

    // Q (t=0): hi only
    {
        float x1 = g_qkv[ibase + j], x2 = g_qkv[ibase + 64 + j];
        float y1 = x1 * cs - x2 * sn;
        float y2 = x1 * sn + x2 * cs;
        g_qh[obase + j]      = __float2half_rn(y1);
        g_qh[obase + 64 + j] = __float2half_rn(y2);
    }
    // K (t=1): hi + lo
    {
        float x1 = g_qkv[ibase + D_MODEL + j], x2 = g_qkv[ibase + D_MODEL + 64 + j];
        float y1 = x1 * cs - x2 * sn;
        float y2 = x1 * sn + x2 * cs;
        __half h1 = __float2half_rn(y1), h2 = __float2half_rn(y2);
        g_kh[obase + j] = h1;      g_kl[obase + j] = __float2half_rn(y1 - __half2float(h1));
        g_kh[obase + 64 + j] = h2; g_kl[obase + 64 + j] = __float2half_rn(y2 - __half2float(h2));
    }
    // V (t=2): hi + lo
    {
        float x1 = g_qkv[ibase + 2 * D_MODEL + j], x2 = g_qkv[ibase + 2 * D_MODEL + 64 + j];
        __half h1 = __float2half_rn(x1), h2 = __float2half_rn(x2);
        g_vh[obase + j] = h1;      g_vl[obase + j] = __float2half_rn(x1 - __half2float(h1));
        g_vh[obase + 64 + j] = h2; g_vl[obase + 64 + j] = __float2half_rn(x2 - __half2float(h2));
    }
}

// ===========================================================================
// HMMA causal flash attention, fp16 2-pass. 128 threads (4 warps), BM=64,
// BN=64, dk=128. QK: Qh·(Kh+Kl); PV: Ph·(Vh+Vl). fp32 softmax.
// 5 smem tiles. Heavy (large-qblk) blocks launch first.
// ===========================================================================
#define FSTR 136                          // smem row stride in halfs (128 + 8)
#define FTILE (64 * FSTR)                 // elems per tile
#define FLASH_SMEM (5 * FTILE * 2)        // 87040 B (x2 CTAs = 174080)

__global__ __launch_bounds__(128, 2)
void flash_hmma() {
    extern __shared__ __half fsm[];
    const uint32_t sb = smem_u32(fsm);
    const uint32_t sQh = sb;
    const uint32_t sKh = sb + 1 * FTILE * 2;
    const uint32_t sKl = sb + 2 * FTILE * 2;
    const uint32_t sVh = sb + 3 * FTILE * 2;
    const uint32_t sVl = sb + 4 * FTILE * 2;

    const int qblk = (int)gridDim.x - 1 - (int)blockIdx.x;   // heavy blocks first
    const int h = blockIdx.y, b = blockIdx.z;
    const int tid = (int)threadIdx.x;
    const int w = tid >> 5, lane = tid & 31;
    const int g = lane >> 2, t4 = lane & 3;
    const float scale = 0.08838834764831845f;   // 1/sqrt(128)

    const size_t hbase = (((size_t)(b * NH + h)) * S_LEN) * (size_t)DK;

    // Load Q tile (hi): 64 rows x 128 halfs
    {
        const __half* qh = g_qh + hbase + (size_t)qblk * 64 * DK;
#pragma unroll
        for (int i = 0; i < 8; i++) {
            int e = i * 128 + tid;
            int row = e >> 4, c16 = e & 15;
            *(uint4*)(fsm + row * FSTR + c16 * 8) =
                *(const uint4*)(qh + (size_t)row * DK + c16 * 8);
        }
    }

    float o[16][4];
    float m_i[2] = {-1e30f, -1e30f}, l_i[2] = {0.f, 0.f};
#pragma unroll
    for (int nb = 0; nb < 16; nb++)
#pragma unroll
        for (int e = 0; e < 4; e++) o[nb][e] = 0.f;

    const int aQrow = w * 16 + (lane & 7) + ((lane >> 3) & 1) * 8;
    const int aQcol = ((lane >> 4) & 1) * 8;
    const int bKrow = (lane & 7) + ((lane >> 4) & 1) * 8;   // + jp*16
    const int bKcol = ((lane >> 3) & 1) * 8;                // + k16*16
    const int vRow  = (lane & 7) + ((lane >> 3) & 1) * 8;   // + j*16
    const int vCol  = ((lane >> 4) & 1) * 8;                // + nt2*16

    for (int jblk = 0; jblk <= qblk; jblk++) {
        __syncthreads();
        // Load K/V (hi/lo) for this block
        {
            const size_t base = hbase + (size_t)jblk * 64 * DK;
#pragma unroll
            for (int i = 0; i < 8; i++) {
                int e = i * 128 + tid;
                int row = e >> 4, c16 = e & 15;
                size_t go = base + (size_t)row * DK + c16 * 8;
                int so = row * FSTR + c16 * 8;
                *(uint4*)(fsm + 1 * FTILE + so) = *(const uint4*)(g_kh + go);
                *(uint4*)(fsm + 2 * FTILE + so) = *(const uint4*)(g_kl + go);
                *(uint4*)(fsm + 3 * FTILE + so) = *(const uint4*)(g_vh + go);
                *(uint4*)(fsm + 4 * FTILE + so) = *(const uint4*)(g_vl + go);
            }
        }
        __syncthreads();

        // ---- QK^T ----  2 passes: qh*kh, qh*kl; pass-major.
        float sc[8][4];
#pragma unroll
        for (int nt = 0; nt < 8; nt++)
#pragma unroll
            for (int e = 0; e < 4; e++) sc[nt][e] = 0.f;

#pragma unroll
        for (int k16 = 0; k16 < 8; k16++) {
            uint32_t qh[4];
            uint32_t qoff = (uint32_t)(aQrow * FSTR + k16 * 16 + aQcol) * 2;
            ldm_x4(qh, sQh + qoff);
            uint32_t kh[4][4], kl[4][4];
#pragma unroll
            for (int jp = 0; jp < 4; jp++) {
                uint32_t koff = (uint32_t)((bKrow + jp * 16) * FSTR + k16 * 16 + bKcol) * 2;
                ldm_x4(kh[jp], sKh + koff);
                ldm_x4(kl[jp], sKl + koff);
            }
#pragma unroll
            for (int jp = 0; jp < 4; jp++) {
                mma_f16(sc[jp * 2],     qh, &kh[jp][0]);
                mma_f16(sc[jp * 2 + 1], qh, &kh[jp][2]);
            }
#pragma unroll
            for (int jp = 0; jp < 4; jp++) {
                mma_f16(sc[jp * 2],     qh, &kl[jp][0]);
                mma_f16(sc[jp * 2 + 1], qh, &kl[jp][2]);
            }
        }

        // ---- scale + causal mask ----
#pragma unroll
        for (int nt = 0; nt < 8; nt++)
#pragma unroll
            for (int e = 0; e < 4; e++) sc[nt][e] *= scale;
        if (jblk == qblk) {
            const int qr0 = w * 16 + g, qr1 = qr0 + 8;
#pragma unroll
            for (int nt = 0; nt < 8; nt++) {
                int kc = nt * 8 + t4 * 2;
                if (kc > qr0)     sc[nt][0] = -1e30f;
                if (kc + 1 > qr0) sc[nt][1] = -1e30f;
                if (kc > qr1)     sc[nt][2] = -1e30f;
                if (kc + 1 > qr1) sc[nt][3] = -1e30f;
            }
        }

        // ---- online softmax (rows g, g+8) ----
        float r0 = -1e30f, r1 = -1e30f;
#pragma unroll
        for (int nt = 0; nt < 8; nt++) {
            r0 = fmaxf(r0, fmaxf(sc[nt][0], sc[nt][1]));
            r1 = fmaxf(r1, fmaxf(sc[nt][2], sc[nt][3]));
        }
        r0 = fmaxf(r0, __shfl_xor_sync(0xffffffffu, r0, 1));
        r0 = fmaxf(r0, __shfl_xor_sync(0xffffffffu, r0, 2));
        r1 = fmaxf(r1, __shfl_xor_sync(0xffffffffu, r1, 1));
        r1 = fmaxf(r1, __shfl_xor_sync(0xffffffffu, r1, 2));
        float mnew0 = fmaxf(m_i[0], r0), mnew1 = fmaxf(m_i[1], r1);
        float corr0 = __expf(m_i[0] - mnew0), corr1 = __expf(m_i[1] - mnew1);
        m_i[0] = mnew0; m_i[1] = mnew1;

        float sum0 = 0.f, sum1 = 0.f;
#pragma unroll
        for (int nt = 0; nt < 8; nt++) {
            sc[nt][0] = __expf(sc[nt][0] - mnew0);
            sc[nt][1] = __expf(sc[nt][1] - mnew0);
            sc[nt][2] = __expf(sc[nt][2] - mnew1);
            sc[nt][3] = __expf(sc[nt][3] - mnew1);
            sum0 += sc[nt][0] + sc[nt][1];
            sum1 += sc[nt][2] + sc[nt][3];
        }
        sum0 += __shfl_xor_sync(0xffffffffu, sum0, 1);
        sum0 += __shfl_xor_sync(0xffffffffu, sum0, 2);
        sum1 += __shfl_xor_sync(0xffffffffu, sum1, 1);
        sum1 += __shfl_xor_sync(0xffffffffu, sum1, 2);
        l_i[0] = l_i[0] * corr0 + sum0;
        l_i[1] = l_i[1] * corr1 + sum1;

#pragma unroll
        for (int nb = 0; nb < 16; nb++) {
            o[nb][0] *= corr0; o[nb][1] *= corr0;
            o[nb][2] *= corr1; o[nb][3] *= corr1;
        }

        // ---- P -> A fragments (fp16 hi only) ----
        uint32_t ph[4][4];
#pragma unroll
        for (int j = 0; j < 4; j++) {
            ph[j][0] = pack_h2(sc[2 * j][0],     sc[2 * j][1]);
            ph[j][1] = pack_h2(sc[2 * j][2],     sc[2 * j][3]);
            ph[j][2] = pack_h2(sc[2 * j + 1][0], sc[2 * j + 1][1]);
            ph[j][3] = pack_h2(sc[2 * j + 1][2], sc[2 * j + 1][3]);
        }

        // ---- O += P @ V ----  2 passes per nt2-pair, interleaved chains.
#pragma unroll
        for (int j = 0; j < 4; j++) {
#pragma unroll
            for (int p2 = 0; p2 < 4; p2++) {
                const int nt2a = 2 * p2, nt2b = 2 * p2 + 1;
                uint32_t voffa = (uint32_t)((j * 16 + vRow) * FSTR + nt2a * 16 + vCol) * 2;
                uint32_t voffb = (uint32_t)((j * 16 + vRow) * FSTR + nt2b * 16 + vCol) * 2;
                uint32_t vha[4], vla[4], vhb[4], vlb[4];
                ldm_x4_t(vha, sVh + voffa);
                ldm_x4_t(vla, sVl + voffa);
                ldm_x4_t(vhb, sVh + voffb);
                ldm_x4_t(vlb, sVl + voffb);
                mma_f16(o[nt2a * 2],     ph[j], &vha[0]);
                mma_f16(o[nt2a * 2 + 1], ph[j], &vha[2]);
                mma_f16(o[nt2b * 2],     ph[j], &vhb[0]);
                mma_f16(o[nt2b * 2 + 1], ph[j], &vhb[2]);
                mma_f16(o[nt2a * 2],     ph[j], &vla[0]);
                mma_f16(o[nt2a * 2 + 1], ph[j], &vla[2]);
                mma_f16(o[nt2b * 2],     ph[j], &vlb[0]);
                mma_f16(o[nt2b * 2 + 1], ph[j], &vlb[2]);
            }
        }
    }

    // ---- epilogue: normalize, fp16 hi only, write [B,S,H*dk] ----
    float inv0 = 1.0f / l_i[0], inv1 = 1.0f / l_i[1];
    size_t row0 = (size_t)(b * S_LEN + qblk * 64 + w * 16 + g);
    size_t row1 = row0 + 8;
#pragma unroll
    for (int nb = 0; nb < 16; nb++) {
        int col = h * DK + nb * 8 + t4 * 2;
        *(uint32_t*)&g_ah[row0 * D_MODEL + col] = pack_h2(o[nb][0] * inv0, o[nb][1] * inv0);
        *(uint32_t*)&g_ah[row1 * D_MODEL + col] = pack_h2(o[nb][2] * inv1, o[nb][3] * inv1);
    }
}

// ===========================================================================
// Launch
// ===========================================================================
extern "C" void kernel_launch(void* const* d_in, const int* in_sizes, int n_in,
                              void* d_out, int out_size) {
    const float* x     = (const float*)d_in[0];
    const float* w_qkv = (const float*)d_in[1];
    const float* w_o   = (const float*)d_in[2];
    float* out = (float*)d_out;

    float* qkv_ptr;
    __half *xh, *wqh, *wql, *woh, *wol, *ah;
    cudaGetSymbolAddress((void**)&qkv_ptr, g_qkv);
    cudaGetSymbolAddress((void**)&xh, g_xh);
    cudaGetSymbolAddress((void**)&wqh, g_wqh);
    cudaGetSymbolAddress((void**)&wql, g_wql);
    cudaGetSymbolAddress((void**)&woh, g_woh);
    cudaGetSymbolAddress((void**)&wol, g_wol);
    cudaGetSymbolAddress((void**)&ah, g_ah);

    const int M = BATCH * S_LEN;  // 4096

    // 0) Convert x (hi only) and split weights (hi/lo) to fp16
    conv_h_kernel<<<(XN + 255) / 256, 256>>>(x, xh, XN);
    split_h_kernel<<<(WQN + 255) / 256, 256>>>(w_qkv, wqh, wql, WQN);
    split_h_kernel<<<(WON + 255) / 256, 256>>>(w_o, woh, wol, WON);

    cudaFuncSetAttribute(gemm_hmma_x2, cudaFuncAttributeMaxDynamicSharedMemorySize,
                         GEMM_SMEM);

    // 1) QKV projection
    {
        dim3 grid((3 * D_MODEL) / 128, M / 128);
        gemm_hmma_x2<<<grid, 128, GEMM_SMEM>>>(xh, wqh, wql, qkv_ptr,
                                               M, 3 * D_MODEL, D_MODEL);
    }
    // 2) Rope + convert to head-major fp16
    {
        int n = BATCH * NH * S_LEN * 64;
        rope_split_kernel<<<(n + 255) / 256, 256>>>();
    }
    // 3) HMMA causal flash attention
    {
        cudaFuncSetAttribute(flash_hmma, cudaFuncAttributeMaxDynamicSharedMemorySize,
                             FLASH_SMEM);
        dim3 grid(S_LEN / 64, NH, BATCH);
        flash_hmma<<<grid, 128, FLASH_SMEM>>>();
    }
    // 4) Output projection
    {
        dim3 grid(D_MODEL / 128, M / 128);
        gemm_hmma_x2<<<grid, 128, GEMM_SMEM>>>(ah, woh, wol, out,
                                               M, D_MODEL, D_MODEL);
    }
}

// round 14
// speedup vs baseline: 4.8017x; 1.0193x over previous
#include <cuda_runtime.h>
#include <cuda_fp16.h>
#include <math.h>
#include <stdint.h>

#define D_MODEL 2048
#define NH 16
#define DK 128
#define S_LEN 2048
#define BATCH 2

#define XN   (4096 * 2048)
#define WQN  (6144 * 2048)
#define WON  (2048 * 2048)
#define QKVN (BATCH * NH * S_LEN * DK)    // 8.4M per tensor

#define NSM_SLOTS 296                     // 148 SMs x 2 CTAs

// Scratch (device globals — no allocations allowed)
__device__ float g_qkv[(size_t)BATCH * S_LEN * 3 * D_MODEL];   // [B,S,3,H,dk] fp32
__device__ __half g_xh[XN];                       // x, fp16 (A-side: no lo needed)
__device__ __half g_wqh[WQN], g_wql[WQN];         // w_qkv hi/lo
__device__ __half g_woh[WON], g_wol[WON];         // w_o hi/lo
__device__ __half g_ah[XN];                       // attention out, fp16 (A-side)
// Rope Q/K/V, head-major [B,H,S,dk]; Q is A-side (hi only), K/V are B-side (hi+lo)
__device__ __half g_qh[QKVN];
__device__ __half g_kh[QKVN], g_kl[QKVN];
__device__ __half g_vh[QKVN], g_vl[QKVN];

// ===========================================================================
// PTX helpers (sm_100-safe: mma.sync / ldmatrix / cp.async)
// ===========================================================================
__device__ __forceinline__ uint32_t smem_u32(const void* p) {
    uint32_t a;
    asm("{ .reg .u64 t; cvta.to.shared.u64 t, %1; cvt.u32.u64 %0, t; }"
        : "=r"(a) : "l"(p));
    return a;
}
__device__ __forceinline__ void cp16(uint32_t dst, const void* src) {
    asm volatile("cp.async.cg.shared.global [%0], [%1], 16;"
                 :: "r"(dst), "l"(src) : "memory");
}
__device__ __forceinline__ void cp_commit() {
    asm volatile("cp.async.commit_group;" ::: "memory");
}
__device__ __forceinline__ void cp_wait0() {
    asm volatile("cp.async.wait_group 0;" ::: "memory");
}
__device__ __forceinline__ void cp_wait1() {
    asm volatile("cp.async.wait_group 1;" ::: "memory");
}
__device__ __forceinline__ void ldm_x4(uint32_t* r, uint32_t addr) {
    asm volatile("ldmatrix.sync.aligned.m8n8.x4.shared.b16 {%0,%1,%2,%3}, [%4];"
                 : "=r"(r[0]), "=r"(r[1]), "=r"(r[2]), "=r"(r[3]) : "r"(addr));
}
__device__ __forceinline__ void ldm_x4_t(uint32_t* r, uint32_t addr) {
    asm volatile("ldmatrix.sync.aligned.m8n8.x4.trans.shared.b16 {%0,%1,%2,%3}, [%4];"
                 : "=r"(r[0]), "=r"(r[1]), "=r"(r[2]), "=r"(r[3]) : "r"(addr));
}
__device__ __forceinline__ void mma_f16(float* d, const uint32_t* a, const uint32_t* b) {
    asm volatile(
        "mma.sync.aligned.m16n8k16.row.col.f32.f16.f16.f32 "
        "{%0,%1,%2,%3}, {%4,%5,%6,%7}, {%8,%9}, {%0,%1,%2,%3};"
        : "+f"(d[0]), "+f"(d[1]), "+f"(d[2]), "+f"(d[3])
        : "r"(a[0]), "r"(a[1]), "r"(a[2]), "r"(a[3]), "r"(b[0]), "r"(b[1]));
}
__device__ __forceinline__ uint32_t pack_h2(float a, float b) {
    __half2 hv = __floats2half2_rn(a, b);
    return *(uint32_t*)&hv;
}

// ===========================================================================
// Conversions
// ===========================================================================
__global__ void conv_h_kernel(const float* __restrict__ src,
                              __half* __restrict__ hi, int n) {
    int i = blockIdx.x * blockDim.x + threadIdx.x;
    if (i >= n) return;
    hi[i] = __float2half_rn(src[i]);
}
__global__ void split_h_kernel(const float* __restrict__ src,
                               __half* __restrict__ hi,
                               __half* __restrict__ lo, int n) {
    int i = blockIdx.x * blockDim.x + threadIdx.x;
    if (i >= n) return;
    float v = src[i];
    __half h = __float2half_rn(v);
    hi[i] = h;
    lo[i] = __float2half_rn(v - __half2float(h));
}

// ===========================================================================
// Persistent HMMA GEMM: C[M,N] = A_hi[M,K] @ (B_hi + B_lo)[N,K]^T, fp16,
// fp32 accum, 2-pass. 128x128 tiles looped over a fixed 296-CTA grid
// (no wave quantization). 4 warps (64x64 each), BK=32, 2-stage cp.async.
// ===========================================================================
#define BK 32
#define ASTRIDE 40                        // halfs per smem row (32 + 8 pad)
#define TILE_B (128 * ASTRIDE * 2)        // 10240 B per tile
#define STAGE_B (3 * TILE_B)              // Ah, Bh, Bl = 30720 B
#define GEMM_SMEM (2 * STAGE_B)           // 61440 B (x2 CTAs = 122880)

__global__ __launch_bounds__(128, 2)
void gemm_hmma_x2(const __half* __restrict__ Ah, const __half* __restrict__ Bh,
                  const __half* __restrict__ Bl,
                  float* __restrict__ C, int M, int N, int K) {
    extern __shared__ char dynsmem[];
    const uint32_t sbase = smem_u32(dynsmem);

    const int tid  = (int)threadIdx.x;
    const int wid  = tid >> 5;
    const int lane = tid & 31;
    const int wm = wid & 1;
    const int wn = wid >> 1;

    const int arow = wm * 64 + (lane & 7) + ((lane >> 3) & 1) * 8;   // + mt*16
    const int acol = ((lane >> 4) & 1) * 8;                          // + ks*16
    const int brow = wn * 64 + (lane & 7) + ((lane >> 4) & 1) * 8;   // + jp*16
    const int bcol = ((lane >> 3) & 1) * 8;                          // + ks*16
    const int g = lane >> 2, t = lane & 3;

    const int nx = N / 128;
    const int ntiles = (M / 128) * nx;
    const int nk = K / BK;

    for (int tile = (int)blockIdx.x; tile < ntiles; tile += (int)gridDim.x) {
        const int bm = (tile / nx) * 128;
        const int bn = (tile % nx) * 128;

        const __half* srcs[3] = {
            Ah + (size_t)bm * K, Bh + (size_t)bn * K, Bl + (size_t)bn * K };

        auto load_stage = [&](int stage, int k0) {
            const uint32_t stg = sbase + stage * STAGE_B;
#pragma unroll
            for (int i = 0; i < 12; i++) {
                int linear = i * 128 + tid;           // 0..1535
                int tt  = linear >> 9;                // tile 0..2
                int row = (linear >> 2) & 127;        // row 0..127
                int c16 = linear & 3;                 // 16B chunk 0..3
                const __half* src = srcs[tt] + (size_t)row * K + k0 + c16 * 8;
                cp16(stg + tt * TILE_B + (row * ASTRIDE + c16 * 8) * 2, src);
            }
            cp_commit();
        };

        float acc[4][8][4];
#pragma unroll
        for (int i = 0; i < 4; i++)
#pragma unroll
            for (int j = 0; j < 8; j++)
#pragma unroll
                for (int c = 0; c < 4; c++) acc[i][j][c] = 0.f;

        load_stage(0, 0);

        for (int c = 0; c < nk; c++) {
            if (c + 1 < nk) {
                load_stage((c + 1) & 1, (c + 1) * BK);
                cp_wait1();
            } else {
                cp_wait0();
            }
            __syncthreads();

            const uint32_t stg = sbase + (c & 1) * STAGE_B;
            const uint32_t sA  = stg;
            const uint32_t sBh = stg + TILE_B;
            const uint32_t sBl = stg + 2 * TILE_B;

#pragma unroll
            for (int ks = 0; ks < 2; ks++) {
                uint32_t ah[4][4];
                uint32_t bhi[8][2], blo[8][2];
#pragma unroll
                for (int mt = 0; mt < 4; mt++) {
                    uint32_t off = (uint32_t)(((arow + mt * 16) * ASTRIDE) + ks * 16 + acol) * 2;
                    ldm_x4(ah[mt], sA + off);
                }
#pragma unroll
                for (int jp = 0; jp < 4; jp++) {
                    uint32_t off = (uint32_t)(((brow + jp * 16) * ASTRIDE) + ks * 16 + bcol) * 2;
                    uint32_t r[4];
                    ldm_x4(r, sBh + off);
                    bhi[jp * 2][0] = r[0]; bhi[jp * 2][1] = r[1];
                    bhi[jp * 2 + 1][0] = r[2]; bhi[jp * 2 + 1][1] = r[3];
                    ldm_x4(r, sBl + off);
                    blo[jp * 2][0] = r[0]; blo[jp * 2][1] = r[1];
                    blo[jp * 2 + 1][0] = r[2]; blo[jp * 2 + 1][1] = r[3];
                }
                // Pass-major: per-acc order hh -> hl.
#pragma unroll
                for (int mt = 0; mt < 4; mt++)
#pragma unroll
                    for (int nt = 0; nt < 8; nt++)
                        mma_f16(acc[mt][nt], ah[mt], bhi[nt]);
#pragma unroll
                for (int mt = 0; mt < 4; mt++)
#pragma unroll
                    for (int nt = 0; nt < 8; nt++)
                        mma_f16(acc[mt][nt], ah[mt], blo[nt]);
            }
            __syncthreads();
        }

#pragma unroll
        for (int mt = 0; mt < 4; mt++) {
#pragma unroll
            for (int nt = 0; nt < 8; nt++) {
                size_t r0 = (size_t)(bm + wm * 64 + mt * 16 + g);
                int col = bn + wn * 64 + nt * 8 + t * 2;
                *(float2*)&C[r0 * N + col] = make_float2(acc[mt][nt][0], acc[mt][nt][1]);
                *(float2*)&C[(r0 + 8) * N + col] = make_float2(acc[mt][nt][2], acc[mt][nt][3]);
            }
        }
    }
}

// ===========================================================================
// Rope + convert: g_qkv fp32 -> Q (hi), K/V (hi+lo), fp16, [B,H,S,dk].
// ===========================================================================
__global__ void rope_split_kernel() {
    int idx = blockIdx.x * blockDim.x + threadIdx.x;
    const int total = BATCH * NH * S_LEN * 64;   // 2^22
    if (idx >= total) return;
    int j = idx & 63;
    int s = (idx >> 6) & (S_LEN - 1);
    int h = (idx >> 17) & 15;
    int b = idx >> 21;

    float freq = expf((float)j * (-9.210340371976184f / 63.0f));
    float theta = (float)s * freq;
    float sn, cs;
    sincosf(theta, &sn, &cs);

    size_t ibase = ((size_t)(b * S_LEN + s)) * 3 * (size_t)D_MODEL + (size_t)h * DK;
    size_t obase = (((size_t)(b * NH + h)) * S_LEN + s) * (size_t)DK;

    // Q (t=0): hi only
    {
        float x1 = g_qkv[ibase + j], x2 = g_qkv[ibase + 64 + j];
        float y1 = x1 * cs - x2 * sn;
        float y2 = x1 * sn + x2 * cs;
        g_qh[obase + j]      = __float2half_rn(y1);
        g_qh[obase + 64 + j] = __float2half_rn(y2);
    }
    // K (t=1): hi + lo
    {
        float x1 = g_qkv[ibase + D_MODEL + j], x2 = g_qkv[ibase + D_MODEL + 64 + j];
        float y1 = x1 * cs - x2 * sn;
        float y2 = x1 * sn + x2 * cs;
        __half h1 = __float2half_rn(y1), h2 = __float2half_rn(y2);
        g_kh[obase + j] = h1;      g_kl[obase + j] = __float2half_rn(y1 - __half2float(h1));
        g_kh[obase + 64 + j] = h2; g_kl[obase + 64 + j] = __float2half_rn(y2 - __half2float(h2));
    }
    // V (t=2): hi + lo
    {
        float x1 = g_qkv[ibase + 2 * D_MODEL + j], x2 = g_qkv[ibase + 2 * D_MODEL + 64 + j];
        __half h1 = __float2half_rn(x1), h2 = __float2half_rn(x2);
        g_vh[obase + j] = h1;      g_vl[obase + j] = __float2half_rn(x1 - __half2float(h1));
        g_vh[obase + 64 + j] = h2; g_vl[obase + 64 + j] = __float2half_rn(x2 - __half2float(h2));
    }
}

// ===========================================================================
// HMMA causal flash attention, fp16 2-pass. 128 threads (4 warps), BM=64,
// BN=64, dk=128. QK: Qh·(Kh+Kl); PV: Ph·(Vh+Vl). fp32 softmax.
// 5 smem tiles. Heavy (large-qblk) blocks launch first.
// ===========================================================================
#define FSTR 136                          // smem row stride in halfs (128 + 8)
#define FTILE (64 * FSTR)                 // elems per tile
#define FLASH_SMEM (5 * FTILE * 2)        // 87040 B (x2 CTAs = 174080)

__global__ __launch_bounds__(128, 2)
void flash_hmma() {
    extern __shared__ __half fsm[];
    const uint32_t sb = smem_u32(fsm);
    const uint32_t sQh = sb;
    const uint32_t sKh = sb + 1 * FTILE * 2;
    const uint32_t sKl = sb + 2 * FTILE * 2;
    const uint32_t sVh = sb + 3 * FTILE * 2;
    const uint32_t sVl = sb + 4 * FTILE * 2;

    const int qblk = (int)gridDim.x - 1 - (int)blockIdx.x;   // heavy blocks first
    const int h = blockIdx.y, b = blockIdx.z;
    const int tid = (int)threadIdx.x;
    const int w = tid >> 5, lane = tid & 31;
    const int g = lane >> 2, t4 = lane & 3;
    const float scale = 0.08838834764831845f;   // 1/sqrt(128)

    const size_t hbase = (((size_t)(b * NH + h)) * S_LEN) * (size_t)DK;

    // Load Q tile (hi): 64 rows x 128 halfs
    {
        const __half* qh = g_qh + hbase + (size_t)qblk * 64 * DK;
#pragma unroll
        for (int i = 0; i < 8; i++) {
            int e = i * 128 + tid;
            int row = e >> 4, c16 = e & 15;
            *(uint4*)(fsm + row * FSTR + c16 * 8) =
                *(const uint4*)(qh + (size_t)row * DK + c16 * 8);
        }
    }

    float o[16][4];
    float m_i[2] = {-1e30f, -1e30f}, l_i[2] = {0.f, 0.f};
#pragma unroll
    for (int nb = 0; nb < 16; nb++)
#pragma unroll
        for (int e = 0; e < 4; e++) o[nb][e] = 0.f;

    const int aQrow = w * 16 + (lane & 7) + ((lane >> 3) & 1) * 8;
    const int aQcol = ((lane >> 4) & 1) * 8;
    const int bKrow = (lane & 7) + ((lane >> 4) & 1) * 8;   // + jp*16
    const int bKcol = ((lane >> 3) & 1) * 8;                // + k16*16
    const int vRow  = (lane & 7) + ((lane >> 3) & 1) * 8;   // + j*16
    const int vCol  = ((lane >> 4) & 1) * 8;                // + nt2*16

    for (int jblk = 0; jblk <= qblk; jblk++) {
        __syncthreads();
        // Load K/V (hi/lo) for this block
        {
            const size_t base = hbase + (size_t)jblk * 64 * DK;
#pragma unroll
            for (int i = 0; i < 8; i++) {
                int e = i * 128 + tid;
                int row = e >> 4, c16 = e & 15;
                size_t go = base + (size_t)row * DK + c16 * 8;
                int so = row * FSTR + c16 * 8;
                *(uint4*)(fsm + 1 * FTILE + so) = *(const uint4*)(g_kh + go);
                *(uint4*)(fsm + 2 * FTILE + so) = *(const uint4*)(g_kl + go);
                *(uint4*)(fsm + 3 * FTILE + so) = *(const uint4*)(g_vh + go);
                *(uint4*)(fsm + 4 * FTILE + so) = *(const uint4*)(g_vl + go);
            }
        }
        __syncthreads();

        // ---- QK^T ----  2 passes: qh*kh, qh*kl; pass-major.
        float sc[8][4];
#pragma unroll
        for (int nt = 0; nt < 8; nt++)
#pragma unroll
            for (int e = 0; e < 4; e++) sc[nt][e] = 0.f;

#pragma unroll
        for (int k16 = 0; k16 < 8; k16++) {
            uint32_t qh[4];
            uint32_t qoff = (uint32_t)(aQrow * FSTR + k16 * 16 + aQcol) * 2;
            ldm_x4(qh, sQh + qoff);
            uint32_t kh[4][4], kl[4][4];
#pragma unroll
            for (int jp = 0; jp < 4; jp++) {
                uint32_t koff = (uint32_t)((bKrow + jp * 16) * FSTR + k16 * 16 + bKcol) * 2;
                ldm_x4(kh[jp], sKh + koff);
                ldm_x4(kl[jp], sKl + koff);
            }
#pragma unroll
            for (int jp = 0; jp < 4; jp++) {
                mma_f16(sc[jp * 2],     qh, &kh[jp][0]);
                mma_f16(sc[jp * 2 + 1], qh, &kh[jp][2]);
            }
#pragma unroll
            for (int jp = 0; jp < 4; jp++) {
                mma_f16(sc[jp * 2],     qh, &kl[jp][0]);
                mma_f16(sc[jp * 2 + 1], qh, &kl[jp][2]);
            }
        }

        // ---- scale + causal mask ----
#pragma unroll
        for (int nt = 0; nt < 8; nt++)
#pragma unroll
            for (int e = 0; e < 4; e++) sc[nt][e] *= scale;
        if (jblk == qblk) {
            const int qr0 = w * 16 + g, qr1 = qr0 + 8;
#pragma unroll
            for (int nt = 0; nt < 8; nt++) {
                int kc = nt * 8 + t4 * 2;
                if (kc > qr0)     sc[nt][0] = -1e30f;
                if (kc + 1 > qr0) sc[nt][1] = -1e30f;
                if (kc > qr1)     sc[nt][2] = -1e30f;
                if (kc + 1 > qr1) sc[nt][3] = -1e30f;
            }
        }

        // ---- online softmax (rows g, g+8) ----
        float r0 = -1e30f, r1 = -1e30f;
#pragma unroll
        for (int nt = 0; nt < 8; nt++) {
            r0 = fmaxf(r0, fmaxf(sc[nt][0], sc[nt][1]));
            r1 = fmaxf(r1, fmaxf(sc[nt][2], sc[nt][3]));
        }
        r0 = fmaxf(r0, __shfl_xor_sync(0xffffffffu, r0, 1));
        r0 = fmaxf(r0, __shfl_xor_sync(0xffffffffu, r0, 2));
        r1 = fmaxf(r1, __shfl_xor_sync(0xffffffffu, r1, 1));
        r1 = fmaxf(r1, __shfl_xor_sync(0xffffffffu, r1, 2));
        float mnew0 = fmaxf(m_i[0], r0), mnew1 = fmaxf(m_i[1], r1);
        float corr0 = __expf(m_i[0] - mnew0), corr1 = __expf(m_i[1] - mnew1);
        m_i[0] = mnew0; m_i[1] = mnew1;

        float sum0 = 0.f, sum1 = 0.f;
#pragma unroll
        for (int nt = 0; nt < 8; nt++) {
            sc[nt][0] = __expf(sc[nt][0] - mnew0);
            sc[nt][1] = __expf(sc[nt][1] - mnew0);
            sc[nt][2] = __expf(sc[nt][2] - mnew1);
            sc[nt][3] = __expf(sc[nt][3] - mnew1);
            sum0 += sc[nt][0] + sc[nt][1];
            sum1 += sc[nt][2] + sc[nt][3];
        }
        sum0 += __shfl_xor_sync(0xffffffffu, sum0, 1);
        sum0 += __shfl_xor_sync(0xffffffffu, sum0, 2);
        sum1 += __shfl_xor_sync(0xffffffffu, sum1, 1);
        sum1 += __shfl_xor_sync(0xffffffffu, sum1, 2);
        l_i[0] = l_i[0] * corr0 + sum0;
        l_i[1] = l_i[1] * corr1 + sum1;

#pragma unroll
        for (int nb = 0; nb < 16; nb++) {
            o[nb][0] *= corr0; o[nb][1] *= corr0;
            o[nb][2] *= corr1; o[nb][3] *= corr1;
        }

        // ---- P -> A fragments (fp16 hi only) ----
        uint32_t ph[4][4];
#pragma unroll
        for (int j = 0; j < 4; j++) {
            ph[j][0] = pack_h2(sc[2 * j][0],     sc[2 * j][1]);
            ph[j][1] = pack_h2(sc[2 * j][2],     sc[2 * j][3]);
            ph[j][2] = pack_h2(sc[2 * j + 1][0], sc[2 * j + 1][1]);
            ph[j][3] = pack_h2(sc[2 * j + 1][2], sc[2 * j + 1][3]);
        }

        // ---- O += P @ V ----  2 passes per nt2-pair, interleaved chains.
#pragma unroll
        for (int j = 0; j < 4; j++) {
#pragma unroll
            for (int p2 = 0; p2 < 4; p2++) {
                const int nt2a = 2 * p2, nt2b = 2 * p2 + 1;
                uint32_t voffa = (uint32_t)((j * 16 + vRow) * FSTR + nt2a * 16 + vCol) * 2;
                uint32_t voffb = (uint32_t)((j * 16 + vRow) * FSTR + nt2b * 16 + vCol) * 2;
                uint32_t vha[4], vla[4], vhb[4], vlb[4];
                ldm_x4_t(vha, sVh + voffa);
                ldm_x4_t(vla, sVl + voffa);
                ldm_x4_t(vhb, sVh + voffb);
                ldm_x4_t(vlb, sVl + voffb);
                mma_f16(o[nt2a * 2],     ph[j], &vha[0]);
                mma_f16(o[nt2a * 2 + 1], ph[j], &vha[2]);
                mma_f16(o[nt2b * 2],     ph[j], &vhb[0]);
                mma_f16(o[nt2b * 2 + 1], ph[j], &vhb[2]);
                mma_f16(o[nt2a * 2],     ph[j], &vla[0]);
                mma_f16(o[nt2a * 2 + 1], ph[j], &vla[2]);
                mma_f16(o[nt2b * 2],     ph[j], &vlb[0]);
                mma_f16(o[nt2b * 2 + 1], ph[j], &vlb[2]);
            }
        }
    }

    // ---- epilogue: normalize, fp16 hi only, write [B,S,H*dk] ----
    float inv0 = 1.0f / l_i[0], inv1 = 1.0f / l_i[1];
    size_t row0 = (size_t)(b * S_LEN + qblk * 64 + w * 16 + g);
    size_t row1 = row0 + 8;
#pragma unroll
    for (int nb = 0; nb < 16; nb++) {
        int col = h * DK + nb * 8 + t4 * 2;
        *(uint32_t*)&g_ah[row0 * D_MODEL + col] = pack_h2(o[nb][0] * inv0, o[nb][1] * inv0);
        *(uint32_t*)&g_ah[row1 * D_MODEL + col] = pack_h2(o[nb][2] * inv1, o[nb][3] * inv1);
    }
}

// ===========================================================================
// Launch
// ===========================================================================
extern "C" void kernel_launch(void* const* d_in, const int* in_sizes, int n_in,
                              void* d_out, int out_size) {
    const float* x     = (const float*)d_in[0];
    const float* w_qkv = (const float*)d_in[1];
    const float* w_o   = (const float*)d_in[2];
    float* out = (float*)d_out;

    float* qkv_ptr;
    __half *xh, *wqh, *wql, *woh, *wol, *ah;
    cudaGetSymbolAddress((void**)&qkv_ptr, g_qkv);
    cudaGetSymbolAddress((void**)&xh, g_xh);
    cudaGetSymbolAddress((void**)&wqh, g_wqh);
    cudaGetSymbolAddress((void**)&wql, g_wql);
    cudaGetSymbolAddress((void**)&woh, g_woh);
    cudaGetSymbolAddress((void**)&wol, g_wol);
    cudaGetSymbolAddress((void**)&ah, g_ah);

    const int M = BATCH * S_LEN;  // 4096

    // 0) Convert x (hi only) and split weights (hi/lo) to fp16
    conv_h_kernel<<<(XN + 255) / 256, 256>>>(x, xh, XN);
    split_h_kernel<<<(WQN + 255) / 256, 256>>>(w_qkv, wqh, wql, WQN);
    split_h_kernel<<<(WON + 255) / 256, 256>>>(w_o, woh, wol, WON);

    cudaFuncSetAttribute(gemm_hmma_x2, cudaFuncAttributeMaxDynamicSharedMemorySize,
                         GEMM_SMEM);

    // 1) QKV projection: persistent grid, 1536 tiles over 296 CTAs
    {
        gemm_hmma_x2<<<NSM_SLOTS, 128, GEMM_SMEM>>>(xh, wqh, wql, qkv_ptr,
                                                    M, 3 * D_MODEL, D_MODEL);
    }
    // 2) Rope + convert to head-major fp16
    {
        int n = BATCH * NH * S_LEN * 64;
        rope_split_kernel<<<(n + 255) / 256, 256>>>();
    }
    // 3) HMMA causal flash attention
    {
        cudaFuncSetAttribute(flash_hmma, cudaFuncAttributeMaxDynamicSharedMemorySize,
                             FLASH_SMEM);
        dim3 grid(S_LEN / 64, NH, BATCH);
        flash_hmma<<<grid, 128, FLASH_SMEM>>>();
    }
    // 4) Output projection: persistent grid, 512 tiles over 296 CTAs
    {
        gemm_hmma_x2<<<NSM_SLOTS, 128, GEMM_SMEM>>>(ah, woh, wol, out,
                                                    M, D_MODEL, D_MODEL);
    }
}

// round 15
// speedup vs baseline: 4.8066x; 1.0010x over previous
#include <cuda_runtime.h>
#include <cuda_fp16.h>
#include <math.h>
#include <stdint.h>

#define D_MODEL 2048
#define NH 16
#define DK 128
#define S_LEN 2048
#define BATCH 2

#define XN   (4096 * 2048)
#define WQN  (6144 * 2048)
#define WON  (2048 * 2048)
#define QKVN (BATCH * NH * S_LEN * DK)    // 8.4M per tensor

#define NSM_SLOTS 296                     // 148 SMs x 2 CTAs

// Scratch (device globals — no allocations allowed)
__device__ float g_qkv[(size_t)BATCH * S_LEN * 3 * D_MODEL];   // [B,S,3,H,dk] fp32
__device__ __half g_xh[XN];                       // x, fp16 (A-side: no lo needed)
__device__ __half g_wqh[WQN], g_wql[WQN];         // w_qkv hi/lo
__device__ __half g_woh[WON], g_wol[WON];         // w_o hi/lo
__device__ __half g_ah[XN];                       // attention out, fp16 (A-side)
// Rope Q/K/V, head-major [B,H,S,dk]; Q is A-side (hi only), K/V are B-side (hi+lo)
__device__ __half g_qh[QKVN];
__device__ __half g_kh[QKVN], g_kl[QKVN];
__device__ __half g_vh[QKVN], g_vl[QKVN];

// ===========================================================================
// PTX helpers (sm_100-safe: mma.sync / ldmatrix / cp.async)
// ===========================================================================
__device__ __forceinline__ uint32_t smem_u32(const void* p) {
    uint32_t a;
    asm("{ .reg .u64 t; cvta.to.shared.u64 t, %1; cvt.u32.u64 %0, t; }"
        : "=r"(a) : "l"(p));
    return a;
}
__device__ __forceinline__ void cp16(uint32_t dst, const void* src) {
    asm volatile("cp.async.cg.shared.global [%0], [%1], 16;"
                 :: "r"(dst), "l"(src) : "memory");
}
__device__ __forceinline__ void cp_commit() {
    asm volatile("cp.async.commit_group;" ::: "memory");
}
__device__ __forceinline__ void cp_wait0() {
    asm volatile("cp.async.wait_group 0;" ::: "memory");
}
__device__ __forceinline__ void cp_wait1() {
    asm volatile("cp.async.wait_group 1;" ::: "memory");
}
__device__ __forceinline__ void ldm_x4(uint32_t* r, uint32_t addr) {
    asm volatile("ldmatrix.sync.aligned.m8n8.x4.shared.b16 {%0,%1,%2,%3}, [%4];"
                 : "=r"(r[0]), "=r"(r[1]), "=r"(r[2]), "=r"(r[3]) : "r"(addr));
}
__device__ __forceinline__ void ldm_x4_t(uint32_t* r, uint32_t addr) {
    asm volatile("ldmatrix.sync.aligned.m8n8.x4.trans.shared.b16 {%0,%1,%2,%3}, [%4];"
                 : "=r"(r[0]), "=r"(r[1]), "=r"(r[2]), "=r"(r[3]) : "r"(addr));
}
__device__ __forceinline__ void mma_f16(float* d, const uint32_t* a, const uint32_t* b) {
    asm volatile(
        "mma.sync.aligned.m16n8k16.row.col.f32.f16.f16.f32 "
        "{%0,%1,%2,%3}, {%4,%5,%6,%7}, {%8,%9}, {%0,%1,%2,%3};"
        : "+f"(d[0]), "+f"(d[1]), "+f"(d[2]), "+f"(d[3])
        : "r"(a[0]), "r"(a[1]), "r"(a[2]), "r"(a[3]), "r"(b[0]), "r"(b[1]));
}
__device__ __forceinline__ uint32_t pack_h2(float a, float b) {
    __half2 hv = __floats2half2_rn(a, b);
    return *(uint32_t*)&hv;
}

// ===========================================================================
// Conversions
// ===========================================================================
__global__ void conv_h_kernel(const float* __restrict__ src,
                              __half* __restrict__ hi, int n) {
    int i = blockIdx.x * blockDim.x + threadIdx.x;
    if (i >= n) return;
    hi[i] = __float2half_rn(src[i]);
}
__global__ void split_h_kernel(const float* __restrict__ src,
                               __half* __restrict__ hi,
                               __half* __restrict__ lo, int n) {
    int i = blockIdx.x * blockDim.x + threadIdx.x;
    if (i >= n) return;
    float v = src[i];
    __half h = __float2half_rn(v);
    hi[i] = h;
    lo[i] = __float2half_rn(v - __half2float(h));
}

// ===========================================================================
// Persistent HMMA GEMM: C[M,N] = A_hi[M,K] @ (B_hi + B_lo)[N,K]^T, fp16,
// fp32 accum, 2-pass. 128x128 tiles looped over a fixed 296-CTA grid
// (no wave quantization). 4 warps (64x64 each), BK=32, 2-stage cp.async.
// ===========================================================================
#define BK 32
#define ASTRIDE 40                        // halfs per smem row (32 + 8 pad)
#define TILE_B (128 * ASTRIDE * 2)        // 10240 B per tile
#define STAGE_B (3 * TILE_B)              // Ah, Bh, Bl = 30720 B
#define GEMM_SMEM (2 * STAGE_B)           // 61440 B (x2 CTAs = 122880)

__global__ __launch_bounds__(128, 2)
void gemm_hmma_x2(const __half* __restrict__ Ah, const __half* __restrict__ Bh,
                  const __half* __restrict__ Bl,
                  float* __restrict__ C, int M, int N, int K) {
    extern __shared__ char dynsmem[];
    const uint32_t sbase = smem_u32(dynsmem);

    const int tid  = (int)threadIdx.x;
    const int wid  = tid >> 5;
    const int lane = tid & 31;
    const int wm = wid & 1;
    const int wn = wid >> 1;

    const int arow = wm * 64 + (lane & 7) + ((lane >> 3) & 1) * 8;   // + mt*16
    const int acol = ((lane >> 4) & 1) * 8;                          // + ks*16
    const int brow = wn * 64 + (lane & 7) + ((lane >> 4) & 1) * 8;   // + jp*16
    const int bcol = ((lane >> 3) & 1) * 8;                          // + ks*16
    const int g = lane >> 2, t = lane & 3;

    const int nx = N / 128;
    const int ntiles = (M / 128) * nx;
    const int nk = K / BK;

    for (int tile = (int)blockIdx.x; tile < ntiles; tile += (int)gridDim.x) {
        const int bm = (tile / nx) * 128;
        const int bn = (tile % nx) * 128;

        const __half* srcs[3] = {
            Ah + (size_t)bm * K, Bh + (size_t)bn * K, Bl + (size_t)bn * K };

        auto load_stage = [&](int stage, int k0) {
            const uint32_t stg = sbase + stage * STAGE_B;
#pragma unroll
            for (int i = 0; i < 12; i++) {
                int linear = i * 128 + tid;           // 0..1535
                int tt  = linear >> 9;                // tile 0..2
                int row = (linear >> 2) & 127;        // row 0..127
                int c16 = linear & 3;                 // 16B chunk 0..3
                const __half* src = srcs[tt] + (size_t)row * K + k0 + c16 * 8;
                cp16(stg + tt * TILE_B + (row * ASTRIDE + c16 * 8) * 2, src);
            }
            cp_commit();
        };

        float acc[4][8][4];
#pragma unroll
        for (int i = 0; i < 4; i++)
#pragma unroll
            for (int j = 0; j < 8; j++)
#pragma unroll
                for (int c = 0; c < 4; c++) acc[i][j][c] = 0.f;

        load_stage(0, 0);

        for (int c = 0; c < nk; c++) {
            if (c + 1 < nk) {
                load_stage((c + 1) & 1, (c + 1) * BK);
                cp_wait1();
            } else {
                cp_wait0();
            }
            __syncthreads();

            const uint32_t stg = sbase + (c & 1) * STAGE_B;
            const uint32_t sA  = stg;
            const uint32_t sBh = stg + TILE_B;
            const uint32_t sBl = stg + 2 * TILE_B;

#pragma unroll
            for (int ks = 0; ks < 2; ks++) {
                uint32_t ah[4][4];
                uint32_t bhi[8][2], blo[8][2];
#pragma unroll
                for (int mt = 0; mt < 4; mt++) {
                    uint32_t off = (uint32_t)(((arow + mt * 16) * ASTRIDE) + ks * 16 + acol) * 2;
                    ldm_x4(ah[mt], sA + off);
                }
#pragma unroll
                for (int jp = 0; jp < 4; jp++) {
                    uint32_t off = (uint32_t)(((brow + jp * 16) * ASTRIDE) + ks * 16 + bcol) * 2;
                    uint32_t r[4];
                    ldm_x4(r, sBh + off);
                    bhi[jp * 2][0] = r[0]; bhi[jp * 2][1] = r[1];
                    bhi[jp * 2 + 1][0] = r[2]; bhi[jp * 2 + 1][1] = r[3];
                    ldm_x4(r, sBl + off);
                    blo[jp * 2][0] = r[0]; blo[jp * 2][1] = r[1];
                    blo[jp * 2 + 1][0] = r[2]; blo[jp * 2 + 1][1] = r[3];
                }
                // Pass-major: per-acc order hh -> hl.
#pragma unroll
                for (int mt = 0; mt < 4; mt++)
#pragma unroll
                    for (int nt = 0; nt < 8; nt++)
                        mma_f16(acc[mt][nt], ah[mt], bhi[nt]);
#pragma unroll
                for (int mt = 0; mt < 4; mt++)
#pragma unroll
                    for (int nt = 0; nt < 8; nt++)
                        mma_f16(acc[mt][nt], ah[mt], blo[nt]);
            }
            __syncthreads();
        }

#pragma unroll
        for (int mt = 0; mt < 4; mt++) {
#pragma unroll
            for (int nt = 0; nt < 8; nt++) {
                size_t r0 = (size_t)(bm + wm * 64 + mt * 16 + g);
                int col = bn + wn * 64 + nt * 8 + t * 2;
                *(float2*)&C[r0 * N + col] = make_float2(acc[mt][nt][0], acc[mt][nt][1]);
                *(float2*)&C[(r0 + 8) * N + col] = make_float2(acc[mt][nt][2], acc[mt][nt][3]);
            }
        }
    }
}

// ===========================================================================
// Rope + convert: g_qkv fp32 -> Q (hi), K/V (hi+lo), fp16, [B,H,S,dk].
// ===========================================================================
__global__ void rope_split_kernel() {
    int idx = blockIdx.x * blockDim.x + threadIdx.x;
    const int total = BATCH * NH * S_LEN * 64;   // 2^22
    if (idx >= total) return;
    int j = idx & 63;
    int s = (idx >> 6) & (S_LEN - 1);
    int h = (idx >> 17) & 15;
    int b = idx >> 21;

    float freq = expf((float)j * (-9.210340371976184f / 63.0f));
    float theta = (float)s * freq;
    float sn, cs;
    sincosf(theta, &sn, &cs);

    size_t ibase = ((size_t)(b * S_LEN + s)) * 3 * (size_t)D_MODEL + (size_t)h * DK;
    size_t obase = (((size_t)(b * NH + h)) * S_LEN + s) * (size_t)DK;

    // Q (t=0): hi only
    {
        float x1 = g_qkv[ibase + j], x2 = g_qkv[ibase + 64 + j];
        float y1 = x1 * cs - x2 * sn;
        float y2 = x1 * sn + x2 * cs;
        g_qh[obase + j]      = __float2half_rn(y1);
        g_qh[obase + 64 + j] = __float2half_rn(y2);
    }
    // K (t=1): hi + lo
    {
        float x1 = g_qkv[ibase + D_MODEL + j], x2 = g_qkv[ibase + D_MODEL + 64 + j];
        float y1 = x1 * cs - x2 * sn;
        float y2 = x1 * sn + x2 * cs;
        __half h1 = __float2half_rn(y1), h2 = __float2half_rn(y2);
        g_kh[obase + j] = h1;      g_kl[obase + j] = __float2half_rn(y1 - __half2float(h1));
        g_kh[obase + 64 + j] = h2; g_kl[obase + 64 + j] = __float2half_rn(y2 - __half2float(h2));
    }
    // V (t=2): hi + lo
    {
        float x1 = g_qkv[ibase + 2 * D_MODEL + j], x2 = g_qkv[ibase + 2 * D_MODEL + 64 + j];
        __half h1 = __float2half_rn(x1), h2 = __float2half_rn(x2);
        g_vh[obase + j] = h1;      g_vl[obase + j] = __float2half_rn(x1 - __half2float(h1));
        g_vh[obase + 64 + j] = h2; g_vl[obase + 64 + j] = __float2half_rn(x2 - __half2float(h2));
    }
}

// ===========================================================================
// HMMA causal flash attention, fp16 2-pass. 128 threads (4 warps), BM=64,
// BN=64, dk=128. QK: Qh·(Kh+Kl); PV: Ph·(Vh+Vl). fp32 softmax.
// 5 smem tiles. Heavy (large-qblk) blocks launch first.
// ===========================================================================
#define FSTR 136                          // smem row stride in halfs (128 + 8)
#define FTILE (64 * FSTR)                 // elems per tile
#define FLASH_SMEM (5 * FTILE * 2)        // 87040 B (x2 CTAs = 174080)

__global__ __launch_bounds__(128, 2)
void flash_hmma() {
    extern __shared__ __half fsm[];
    const uint32_t sb = smem_u32(fsm);
    const uint32_t sQh = sb;
    const uint32_t sKh = sb + 1 * FTILE * 2;
    const uint32_t sKl = sb + 2 * FTILE * 2;
    const uint32_t sVh = sb + 3 * FTILE * 2;
    const uint32_t sVl = sb + 4 * FTILE * 2;

    const int qblk = (int)gridDim.x - 1 - (int)blockIdx.x;   // heavy blocks first
    const int h = blockIdx.y, b = blockIdx.z;
    const int tid = (int)threadIdx.x;
    const int w = tid >> 5, lane = tid & 31;
    const int g = lane >> 2, t4 = lane & 3;
    const float scale = 0.08838834764831845f;   // 1/sqrt(128)

    const size_t hbase = (((size_t)(b * NH + h)) * S_LEN) * (size_t)DK;

    // Load Q tile (hi): 64 rows x 128 halfs
    {
        const __half* qh = g_qh + hbase + (size_t)qblk * 64 * DK;
#pragma unroll
        for (int i = 0; i < 8; i++) {
            int e = i * 128 + tid;
            int row = e >> 4, c16 = e & 15;
            *(uint4*)(fsm + row * FSTR + c16 * 8) =
                *(const uint4*)(qh + (size_t)row * DK + c16 * 8);
        }
    }

    float o[16][4];
    float m_i[2] = {-1e30f, -1e30f}, l_i[2] = {0.f, 0.f};
#pragma unroll
    for (int nb = 0; nb < 16; nb++)
#pragma unroll
        for (int e = 0; e < 4; e++) o[nb][e] = 0.f;

    const int aQrow = w * 16 + (lane & 7) + ((lane >> 3) & 1) * 8;
    const int aQcol = ((lane >> 4) & 1) * 8;
    const int bKrow = (lane & 7) + ((lane >> 4) & 1) * 8;   // + jp*16
    const int bKcol = ((lane >> 3) & 1) * 8;                // + k16*16
    const int vRow  = (lane & 7) + ((lane >> 3) & 1) * 8;   // + j*16
    const int vCol  = ((lane >> 4) & 1) * 8;                // + nt2*16

    for (int jblk = 0; jblk <= qblk; jblk++) {
        __syncthreads();
        // Load K/V (hi/lo) for this block
        {
            const size_t base = hbase + (size_t)jblk * 64 * DK;
#pragma unroll
            for (int i = 0; i < 8; i++) {
                int e = i * 128 + tid;
                int row = e >> 4, c16 = e & 15;
                size_t go = base + (size_t)row * DK + c16 * 8;
                int so = row * FSTR + c16 * 8;
                *(uint4*)(fsm + 1 * FTILE + so) = *(const uint4*)(g_kh + go);
                *(uint4*)(fsm + 2 * FTILE + so) = *(const uint4*)(g_kl + go);
                *(uint4*)(fsm + 3 * FTILE + so) = *(const uint4*)(g_vh + go);
                *(uint4*)(fsm + 4 * FTILE + so) = *(const uint4*)(g_vl + go);
            }
        }
        __syncthreads();

        // ---- QK^T ----  2 passes: qh*kh, qh*kl; pass-major.
        float sc[8][4];
#pragma unroll
        for (int nt = 0; nt < 8; nt++)
#pragma unroll
            for (int e = 0; e < 4; e++) sc[nt][e] = 0.f;

#pragma unroll
        for (int k16 = 0; k16 < 8; k16++) {
            uint32_t qh[4];
            uint32_t qoff = (uint32_t)(aQrow * FSTR + k16 * 16 + aQcol) * 2;
            ldm_x4(qh, sQh + qoff);
            uint32_t kh[4][4], kl[4][4];
#pragma unroll
            for (int jp = 0; jp < 4; jp++) {
                uint32_t koff = (uint32_t)((bKrow + jp * 16) * FSTR + k16 * 16 + bKcol) * 2;
                ldm_x4(kh[jp], sKh + koff);
                ldm_x4(kl[jp], sKl + koff);
            }
#pragma unroll
            for (int jp = 0; jp < 4; jp++) {
                mma_f16(sc[jp * 2],     qh, &kh[jp][0]);
                mma_f16(sc[jp * 2 + 1], qh, &kh[jp][2]);
            }
#pragma unroll
            for (int jp = 0; jp < 4; jp++) {
                mma_f16(sc[jp * 2],     qh, &kl[jp][0]);
                mma_f16(sc[jp * 2 + 1], qh, &kl[jp][2]);
            }
        }

        // ---- scale + causal mask ----
#pragma unroll
        for (int nt = 0; nt < 8; nt++)
#pragma unroll
            for (int e = 0; e < 4; e++) sc[nt][e] *= scale;
        if (jblk == qblk) {
            const int qr0 = w * 16 + g, qr1 = qr0 + 8;
#pragma unroll
            for (int nt = 0; nt < 8; nt++) {
                int kc = nt * 8 + t4 * 2;
                if (kc > qr0)     sc[nt][0] = -1e30f;
                if (kc + 1 > qr0) sc[nt][1] = -1e30f;
                if (kc > qr1)     sc[nt][2] = -1e30f;
                if (kc + 1 > qr1) sc[nt][3] = -1e30f;
            }
        }

        // ---- online softmax (rows g, g+8) ----
        float r0 = -1e30f, r1 = -1e30f;
#pragma unroll
        for (int nt = 0; nt < 8; nt++) {
            r0 = fmaxf(r0, fmaxf(sc[nt][0], sc[nt][1]));
            r1 = fmaxf(r1, fmaxf(sc[nt][2], sc[nt][3]));
        }
        r0 = fmaxf(r0, __shfl_xor_sync(0xffffffffu, r0, 1));
        r0 = fmaxf(r0, __shfl_xor_sync(0xffffffffu, r0, 2));
        r1 = fmaxf(r1, __shfl_xor_sync(0xffffffffu, r1, 1));
        r1 = fmaxf(r1, __shfl_xor_sync(0xffffffffu, r1, 2));
        float mnew0 = fmaxf(m_i[0], r0), mnew1 = fmaxf(m_i[1], r1);
        float corr0 = __expf(m_i[0] - mnew0), corr1 = __expf(m_i[1] - mnew1);
        m_i[0] = mnew0; m_i[1] = mnew1;

        float sum0 = 0.f, sum1 = 0.f;
#pragma unroll
        for (int nt = 0; nt < 8; nt++) {
            sc[nt][0] = __expf(sc[nt][0] - mnew0);
            sc[nt][1] = __expf(sc[nt][1] - mnew0);
            sc[nt][2] = __expf(sc[nt][2] - mnew1);
            sc[nt][3] = __expf(sc[nt][3] - mnew1);
            sum0 += sc[nt][0] + sc[nt][1];
            sum1 += sc[nt][2] + sc[nt][3];
        }
        sum0 += __shfl_xor_sync(0xffffffffu, sum0, 1);
        sum0 += __shfl_xor_sync(0xffffffffu, sum0, 2);
        sum1 += __shfl_xor_sync(0xffffffffu, sum1, 1);
        sum1 += __shfl_xor_sync(0xffffffffu, sum1, 2);
        l_i[0] = l_i[0] * corr0 + sum0;
        l_i[1] = l_i[1] * corr1 + sum1;

#pragma unroll
        for (int nb = 0; nb < 16; nb++) {
            o[nb][0] *= corr0; o[nb][1] *= corr0;
            o[nb][2] *= corr1; o[nb][3] *= corr1;
        }

        // ---- P -> A fragments (fp16 hi only) ----
        uint32_t ph[4][4];
#pragma unroll
        for (int j = 0; j < 4; j++) {
            ph[j][0] = pack_h2(sc[2 * j][0],     sc[2 * j][1]);
            ph[j][1] = pack_h2(sc[2 * j][2],     sc[2 * j][3]);
            ph[j][2] = pack_h2(sc[2 * j + 1][0], sc[2 * j + 1][1]);
            ph[j][3] = pack_h2(sc[2 * j + 1][2], sc[2 * j + 1][3]);
        }

        // ---- O += P @ V ----  2 passes per nt2-pair, interleaved chains.
#pragma unroll
        for (int j = 0; j < 4; j++) {
#pragma unroll
            for (int p2 = 0; p2 < 4; p2++) {
                const int nt2a = 2 * p2, nt2b = 2 * p2 + 1;
                uint32_t voffa = (uint32_t)((j * 16 + vRow) * FSTR + nt2a * 16 + vCol) * 2;
                uint32_t voffb = (uint32_t)((j * 16 + vRow) * FSTR + nt2b * 16 + vCol) * 2;
                uint32_t vha[4], vla[4], vhb[4], vlb[4];
                ldm_x4_t(vha, sVh + voffa);
                ldm_x4_t(vla, sVl + voffa);
                ldm_x4_t(vhb, sVh + voffb);
                ldm_x4_t(vlb, sVl + voffb);
                mma_f16(o[nt2a * 2],     ph[j], &vha[0]);
                mma_f16(o[nt2a * 2 + 1], ph[j], &vha[2]);
                mma_f16(o[nt2b * 2],     ph[j], &vhb[0]);
                mma_f16(o[nt2b * 2 + 1], ph[j], &vhb[2]);
                mma_f16(o[nt2a * 2],     ph[j], &vla[0]);
                mma_f16(o[nt2a * 2 + 1], ph[j], &vla[2]);
                mma_f16(o[nt2b * 2],     ph[j], &vlb[0]);
                mma_f16(o[nt2b * 2 + 1], ph[j], &vlb[2]);
            }
        }
    }

    // ---- epilogue: normalize, fp16 hi only, write [B,S,H*dk] ----
    float inv0 = 1.0f / l_i[0], inv1 = 1.0f / l_i[1];
    size_t row0 = (size_t)(b * S_LEN + qblk * 64 + w * 16 + g);
    size_t row1 = row0 + 8;
#pragma unroll
    for (int nb = 0; nb < 16; nb++) {
        int col = h * DK + nb * 8 + t4 * 2;
        *(uint32_t*)&g_ah[row0 * D_MODEL + col] = pack_h2(o[nb][0] * inv0, o[nb][1] * inv0);
        *(uint32_t*)&g_ah[row1 * D_MODEL + col] = pack_h2(o[nb][2] * inv1, o[nb][3] * inv1);
    }
}

// ===========================================================================
// Launch
// ===========================================================================
extern "C" void kernel_launch(void* const* d_in, const int* in_sizes, int n_in,
                              void* d_out, int out_size) {
    const float* x     = (const float*)d_in[0];
    const float* w_qkv = (const float*)d_in[1];
    const float* w_o   = (const float*)d_in[2];
    float* out = (float*)d_out;

    float* qkv_ptr;
    __half *xh, *wqh, *wql, *woh, *wol, *ah;
    cudaGetSymbolAddress((void**)&qkv_ptr, g_qkv);
    cudaGetSymbolAddress((void**)&xh, g_xh);
    cudaGetSymbolAddress((void**)&wqh, g_wqh);
    cudaGetSymbolAddress((void**)&wql, g_wql);
    cudaGetSymbolAddress((void**)&woh, g_woh);
    cudaGetSymbolAddress((void**)&wol, g_wol);
    cudaGetSymbolAddress((void**)&ah, g_ah);

    const int M = BATCH * S_LEN;  // 4096

    // 0) Convert x (hi only) and split weights (hi/lo) to fp16
    conv_h_kernel<<<(XN + 255) / 256, 256>>>(x, xh, XN);
    split_h_kernel<<<(WQN + 255) / 256, 256>>>(w_qkv, wqh, wql, WQN);
    split_h_kernel<<<(WON + 255) / 256, 256>>>(w_o, woh, wol, WON);

    cudaFuncSetAttribute(gemm_hmma_x2, cudaFuncAttributeMaxDynamicSharedMemorySize,
                         GEMM_SMEM);

    // 1) QKV projection: persistent grid, 1536 tiles over 296 CTAs
    {
        gemm_hmma_x2<<<NSM_SLOTS, 128, GEMM_SMEM>>>(xh, wqh, wql, qkv_ptr,
                                                    M, 3 * D_MODEL, D_MODEL);
    }
    // 2) Rope + convert to head-major fp16
    {
        int n = BATCH * NH * S_LEN * 64;
        rope_split_kernel<<<(n + 255) / 256, 256>>>();
    }
    // 3) HMMA causal flash attention
    {
        cudaFuncSetAttribute(flash_hmma, cudaFuncAttributeMaxDynamicSharedMemorySize,
                             FLASH_SMEM);
        dim3 grid(S_LEN / 64, NH, BATCH);
        flash_hmma<<<grid, 128, FLASH_SMEM>>>();
    }
    // 4) Output projection: persistent grid, 512 tiles over 296 CTAs
    {
        gemm_hmma_x2<<<NSM_SLOTS, 128, GEMM_SMEM>>>(ah, woh, wol, out,
                                                    M, D_MODEL, D_MODEL);
    }
}

// round 16
// speedup vs baseline: 8.0911x; 1.6833x over previous
#include <cuda_runtime.h>
#include <cuda_fp16.h>
#include <math.h>
#include <stdint.h>

#define D_MODEL 2048
#define NH 16
#define DK 128
#define S_LEN 2048
#define BATCH 2

#define XN   (4096 * 2048)
#define WQN  (6144 * 2048)
#define WON  (2048 * 2048)
#define QKVN (BATCH * NH * S_LEN * DK)    // 8.4M per tensor

#define NSM_SLOTS 296                     // 148 SMs x 2 CTAs

// Scratch (device globals — no allocations allowed)
__device__ float g_qkv[(size_t)BATCH * S_LEN * 3 * D_MODEL];   // [B,S,3,H,dk] fp32
__device__ __half g_xh[XN];                       // x, fp16
__device__ __half g_wqh[WQN];                     // w_qkv fp16
__device__ __half g_woh[WON];                     // w_o fp16
__device__ __half g_ah[XN];                       // attention out fp16
// Rope Q/K/V, head-major [B,H,S,dk], fp16
__device__ __half g_qh[QKVN];
__device__ __half g_kh[QKVN];
__device__ __half g_vh[QKVN];

// ===========================================================================
// PTX helpers (sm_100-safe: mma.sync / ldmatrix / cp.async)
// ===========================================================================
__device__ __forceinline__ uint32_t smem_u32(const void* p) {
    uint32_t a;
    asm("{ .reg .u64 t; cvta.to.shared.u64 t, %1; cvt.u32.u64 %0, t; }"
        : "=r"(a) : "l"(p));
    return a;
}
__device__ __forceinline__ void cp16(uint32_t dst, const void* src) {
    asm volatile("cp.async.cg.shared.global [%0], [%1], 16;"
                 :: "r"(dst), "l"(src) : "memory");
}
__device__ __forceinline__ void cp_commit() {
    asm volatile("cp.async.commit_group;" ::: "memory");
}
__device__ __forceinline__ void cp_wait0() {
    asm volatile("cp.async.wait_group 0;" ::: "memory");
}
__device__ __forceinline__ void cp_wait1() {
    asm volatile("cp.async.wait_group 1;" ::: "memory");
}
__device__ __forceinline__ void ldm_x4(uint32_t* r, uint32_t addr) {
    asm volatile("ldmatrix.sync.aligned.m8n8.x4.shared.b16 {%0,%1,%2,%3}, [%4];"
                 : "=r"(r[0]), "=r"(r[1]), "=r"(r[2]), "=r"(r[3]) : "r"(addr));
}
__device__ __forceinline__ void ldm_x4_t(uint32_t* r, uint32_t addr) {
    asm volatile("ldmatrix.sync.aligned.m8n8.x4.trans.shared.b16 {%0,%1,%2,%3}, [%4];"
                 : "=r"(r[0]), "=r"(r[1]), "=r"(r[2]), "=r"(r[3]) : "r"(addr));
}
__device__ __forceinline__ void mma_f16(float* d, const uint32_t* a, const uint32_t* b) {
    asm volatile(
        "mma.sync.aligned.m16n8k16.row.col.f32.f16.f16.f32 "
        "{%0,%1,%2,%3}, {%4,%5,%6,%7}, {%8,%9}, {%0,%1,%2,%3};"
        : "+f"(d[0]), "+f"(d[1]), "+f"(d[2]), "+f"(d[3])
        : "r"(a[0]), "r"(a[1]), "r"(a[2]), "r"(a[3]), "r"(b[0]), "r"(b[1]));
}
__device__ __forceinline__ uint32_t pack_h2(float a, float b) {
    __half2 hv = __floats2half2_rn(a, b);
    return *(uint32_t*)&hv;
}

// ===========================================================================
// Conversion fp32 -> fp16
// ===========================================================================
__global__ void conv_h_kernel(const float* __restrict__ src,
                              __half* __restrict__ hi, int n) {
    int i = blockIdx.x * blockDim.x + threadIdx.x;
    if (i >= n) return;
    hi[i] = __float2half_rn(src[i]);
}

// ===========================================================================
// Persistent HMMA GEMM: C[M,N] = A[M,K] @ B[N,K]^T, fp16 x fp16 -> fp32.
// 128x128 tiles over a fixed 296-CTA grid. 4 warps (64x64 each), BK=32,
// 2-stage cp.async, 2 CTAs/SM.
// ===========================================================================
#define BK 32
#define ASTRIDE 40                        // halfs per smem row (32 + 8 pad)
#define TILE_B (128 * ASTRIDE * 2)        // 10240 B per tile
#define STAGE_B (2 * TILE_B)              // A, B = 20480 B
#define GEMM_SMEM (2 * STAGE_B)           // 40960 B (x2 CTAs = 81920)

__global__ __launch_bounds__(128, 2)
void gemm_hmma(const __half* __restrict__ Ah, const __half* __restrict__ Bh,
               float* __restrict__ C, int M, int N, int K) {
    extern __shared__ char dynsmem[];
    const uint32_t sbase = smem_u32(dynsmem);

    const int tid  = (int)threadIdx.x;
    const int wid  = tid >> 5;
    const int lane = tid & 31;
    const int wm = wid & 1;
    const int wn = wid >> 1;

    const int arow = wm * 64 + (lane & 7) + ((lane >> 3) & 1) * 8;   // + mt*16
    const int acol = ((lane >> 4) & 1) * 8;                          // + ks*16
    const int brow = wn * 64 + (lane & 7) + ((lane >> 4) & 1) * 8;   // + jp*16
    const int bcol = ((lane >> 3) & 1) * 8;                          // + ks*16
    const int g = lane >> 2, t = lane & 3;

    const int nx = N / 128;
    const int ntiles = (M / 128) * nx;
    const int nk = K / BK;

    for (int tile = (int)blockIdx.x; tile < ntiles; tile += (int)gridDim.x) {
        const int bm = (tile / nx) * 128;
        const int bn = (tile % nx) * 128;

        const __half* srcA = Ah + (size_t)bm * K;
        const __half* srcB = Bh + (size_t)bn * K;

        auto load_stage = [&](int stage, int k0) {
            const uint32_t stg = sbase + stage * STAGE_B;
#pragma unroll
            for (int i = 0; i < 8; i++) {
                int linear = i * 128 + tid;           // 0..1023
                int tt  = linear >> 9;                // tile 0..1
                int row = (linear >> 2) & 127;        // row 0..127
                int c16 = linear & 3;                 // 16B chunk 0..3
                const __half* src = (tt ? srcB : srcA) + (size_t)row * K + k0 + c16 * 8;
                cp16(stg + tt * TILE_B + (row * ASTRIDE + c16 * 8) * 2, src);
            }
            cp_commit();
        };

        float acc[4][8][4];
#pragma unroll
        for (int i = 0; i < 4; i++)
#pragma unroll
            for (int j = 0; j < 8; j++)
#pragma unroll
                for (int c = 0; c < 4; c++) acc[i][j][c] = 0.f;

        load_stage(0, 0);

        for (int c = 0; c < nk; c++) {
            if (c + 1 < nk) {
                load_stage((c + 1) & 1, (c + 1) * BK);
                cp_wait1();
            } else {
                cp_wait0();
            }
            __syncthreads();

            const uint32_t stg = sbase + (c & 1) * STAGE_B;
            const uint32_t sA  = stg;
            const uint32_t sB  = stg + TILE_B;

#pragma unroll
            for (int ks = 0; ks < 2; ks++) {
                uint32_t ah[4][4];
                uint32_t bh[8][2];
#pragma unroll
                for (int mt = 0; mt < 4; mt++) {
                    uint32_t off = (uint32_t)(((arow + mt * 16) * ASTRIDE) + ks * 16 + acol) * 2;
                    ldm_x4(ah[mt], sA + off);
                }
#pragma unroll
                for (int jp = 0; jp < 4; jp++) {
                    uint32_t off = (uint32_t)(((brow + jp * 16) * ASTRIDE) + ks * 16 + bcol) * 2;
                    uint32_t r[4];
                    ldm_x4(r, sB + off);
                    bh[jp * 2][0] = r[0]; bh[jp * 2][1] = r[1];
                    bh[jp * 2 + 1][0] = r[2]; bh[jp * 2 + 1][1] = r[3];
                }
#pragma unroll
                for (int mt = 0; mt < 4; mt++)
#pragma unroll
                    for (int nt = 0; nt < 8; nt++)
                        mma_f16(acc[mt][nt], ah[mt], bh[nt]);
            }
            __syncthreads();
        }

#pragma unroll
        for (int mt = 0; mt < 4; mt++) {
#pragma unroll
            for (int nt = 0; nt < 8; nt++) {
                size_t r0 = (size_t)(bm + wm * 64 + mt * 16 + g);
                int col = bn + wn * 64 + nt * 8 + t * 2;
                *(float2*)&C[r0 * N + col] = make_float2(acc[mt][nt][0], acc[mt][nt][1]);
                *(float2*)&C[(r0 + 8) * N + col] = make_float2(acc[mt][nt][2], acc[mt][nt][3]);
            }
        }
    }
}

// ===========================================================================
// Rope + convert: g_qkv fp32 -> Q/K (rotated)/V, fp16, [B,H,S,dk].
// ===========================================================================
__global__ void rope_split_kernel() {
    int idx = blockIdx.x * blockDim.x + threadIdx.x;
    const int total = BATCH * NH * S_LEN * 64;   // 2^22
    if (idx >= total) return;
    int j = idx & 63;
    int s = (idx >> 6) & (S_LEN - 1);
    int h = (idx >> 17) & 15;
    int b = idx >> 21;

    float freq = expf((float)j * (-9.210340371976184f / 63.0f));
    float theta = (float)s * freq;
    float sn, cs;
    sincosf(theta, &sn, &cs);

    size_t ibase = ((size_t)(b * S_LEN + s)) * 3 * (size_t)D_MODEL + (size_t)h * DK;
    size_t obase = (((size_t)(b * NH + h)) * S_LEN + s) * (size_t)DK;

    // Q (t=0)
    {
        float x1 = g_qkv[ibase + j], x2 = g_qkv[ibase + 64 + j];
        g_qh[obase + j]      = __float2half_rn(x1 * cs - x2 * sn);
        g_qh[obase + 64 + j] = __float2half_rn(x1 * sn + x2 * cs);
    }
    // K (t=1)
    {
        float x1 = g_qkv[ibase + D_MODEL + j], x2 = g_qkv[ibase + D_MODEL + 64 + j];
        g_kh[obase + j]      = __float2half_rn(x1 * cs - x2 * sn);
        g_kh[obase + 64 + j] = __float2half_rn(x1 * sn + x2 * cs);
    }
    // V (t=2)
    {
        float x1 = g_qkv[ibase + 2 * D_MODEL + j], x2 = g_qkv[ibase + 2 * D_MODEL + 64 + j];
        g_vh[obase + j]      = __float2half_rn(x1);
        g_vh[obase + 64 + j] = __float2half_rn(x2);
    }
}

// ===========================================================================
// HMMA causal flash attention, plain fp16. 128 threads (4 warps), BM=64,
// BN=64, dk=128. fp32 softmax. 3 smem tiles. Heavy blocks launch first.
// ===========================================================================
#define FSTR 136                          // smem row stride in halfs (128 + 8)
#define FTILE (64 * FSTR)                 // elems per tile
#define FLASH_SMEM (3 * FTILE * 2)        // 52224 B (x2 CTAs = 104448)

__global__ __launch_bounds__(128, 2)
void flash_hmma() {
    extern __shared__ __half fsm[];
    const uint32_t sb = smem_u32(fsm);
    const uint32_t sQh = sb;
    const uint32_t sKh = sb + 1 * FTILE * 2;
    const uint32_t sVh = sb + 2 * FTILE * 2;

    const int qblk = (int)gridDim.x - 1 - (int)blockIdx.x;   // heavy blocks first
    const int h = blockIdx.y, b = blockIdx.z;
    const int tid = (int)threadIdx.x;
    const int w = tid >> 5, lane = tid & 31;
    const int g = lane >> 2, t4 = lane & 3;
    const float scale = 0.08838834764831845f;   // 1/sqrt(128)

    const size_t hbase = (((size_t)(b * NH + h)) * S_LEN) * (size_t)DK;

    // Load Q tile: 64 rows x 128 halfs
    {
        const __half* qh = g_qh + hbase + (size_t)qblk * 64 * DK;
#pragma unroll
        for (int i = 0; i < 8; i++) {
            int e = i * 128 + tid;
            int row = e >> 4, c16 = e & 15;
            *(uint4*)(fsm + row * FSTR + c16 * 8) =
                *(const uint4*)(qh + (size_t)row * DK + c16 * 8);
        }
    }

    float o[16][4];
    float m_i[2] = {-1e30f, -1e30f}, l_i[2] = {0.f, 0.f};
#pragma unroll
    for (int nb = 0; nb < 16; nb++)
#pragma unroll
        for (int e = 0; e < 4; e++) o[nb][e] = 0.f;

    const int aQrow = w * 16 + (lane & 7) + ((lane >> 3) & 1) * 8;
    const int aQcol = ((lane >> 4) & 1) * 8;
    const int bKrow = (lane & 7) + ((lane >> 4) & 1) * 8;   // + jp*16
    const int bKcol = ((lane >> 3) & 1) * 8;                // + k16*16
    const int vRow  = (lane & 7) + ((lane >> 3) & 1) * 8;   // + j*16
    const int vCol  = ((lane >> 4) & 1) * 8;                // + nt2*16

    for (int jblk = 0; jblk <= qblk; jblk++) {
        __syncthreads();
        // Load K/V for this block
        {
            const size_t base = hbase + (size_t)jblk * 64 * DK;
#pragma unroll
            for (int i = 0; i < 8; i++) {
                int e = i * 128 + tid;
                int row = e >> 4, c16 = e & 15;
                size_t go = base + (size_t)row * DK + c16 * 8;
                int so = row * FSTR + c16 * 8;
                *(uint4*)(fsm + 1 * FTILE + so) = *(const uint4*)(g_kh + go);
                *(uint4*)(fsm + 2 * FTILE + so) = *(const uint4*)(g_vh + go);
            }
        }
        __syncthreads();

        // ---- QK^T ----  single pass, pass-major (8 independent chains).
        float sc[8][4];
#pragma unroll
        for (int nt = 0; nt < 8; nt++)
#pragma unroll
            for (int e = 0; e < 4; e++) sc[nt][e] = 0.f;

#pragma unroll
        for (int k16 = 0; k16 < 8; k16++) {
            uint32_t qh[4];
            uint32_t qoff = (uint32_t)(aQrow * FSTR + k16 * 16 + aQcol) * 2;
            ldm_x4(qh, sQh + qoff);
            uint32_t kh[4][4];
#pragma unroll
            for (int jp = 0; jp < 4; jp++) {
                uint32_t koff = (uint32_t)((bKrow + jp * 16) * FSTR + k16 * 16 + bKcol) * 2;
                ldm_x4(kh[jp], sKh + koff);
            }
#pragma unroll
            for (int jp = 0; jp < 4; jp++) {
                mma_f16(sc[jp * 2],     qh, &kh[jp][0]);
                mma_f16(sc[jp * 2 + 1], qh, &kh[jp][2]);
            }
        }

        // ---- scale + causal mask ----
#pragma unroll
        for (int nt = 0; nt < 8; nt++)
#pragma unroll
            for (int e = 0; e < 4; e++) sc[nt][e] *= scale;
        if (jblk == qblk) {
            const int qr0 = w * 16 + g, qr1 = qr0 + 8;
#pragma unroll
            for (int nt = 0; nt < 8; nt++) {
                int kc = nt * 8 + t4 * 2;
                if (kc > qr0)     sc[nt][0] = -1e30f;
                if (kc + 1 > qr0) sc[nt][1] = -1e30f;
                if (kc > qr1)     sc[nt][2] = -1e30f;
                if (kc + 1 > qr1) sc[nt][3] = -1e30f;
            }
        }

        // ---- online softmax (rows g, g+8) ----
        float r0 = -1e30f, r1 = -1e30f;
#pragma unroll
        for (int nt = 0; nt < 8; nt++) {
            r0 = fmaxf(r0, fmaxf(sc[nt][0], sc[nt][1]));
            r1 = fmaxf(r1, fmaxf(sc[nt][2], sc[nt][3]));
        }
        r0 = fmaxf(r0, __shfl_xor_sync(0xffffffffu, r0, 1));
        r0 = fmaxf(r0, __shfl_xor_sync(0xffffffffu, r0, 2));
        r1 = fmaxf(r1, __shfl_xor_sync(0xffffffffu, r1, 1));
        r1 = fmaxf(r1, __shfl_xor_sync(0xffffffffu, r1, 2));
        float mnew0 = fmaxf(m_i[0], r0), mnew1 = fmaxf(m_i[1], r1);
        float corr0 = __expf(m_i[0] - mnew0), corr1 = __expf(m_i[1] - mnew1);
        m_i[0] = mnew0; m_i[1] = mnew1;

        float sum0 = 0.f, sum1 = 0.f;
#pragma unroll
        for (int nt = 0; nt < 8; nt++) {
            sc[nt][0] = __expf(sc[nt][0] - mnew0);
            sc[nt][1] = __expf(sc[nt][1] - mnew0);
            sc[nt][2] = __expf(sc[nt][2] - mnew1);
            sc[nt][3] = __expf(sc[nt][3] - mnew1);
            sum0 += sc[nt][0] + sc[nt][1];
            sum1 += sc[nt][2] + sc[nt][3];
        }
        sum0 += __shfl_xor_sync(0xffffffffu, sum0, 1);
        sum0 += __shfl_xor_sync(0xffffffffu, sum0, 2);
        sum1 += __shfl_xor_sync(0xffffffffu, sum1, 1);
        sum1 += __shfl_xor_sync(0xffffffffu, sum1, 2);
        l_i[0] = l_i[0] * corr0 + sum0;
        l_i[1] = l_i[1] * corr1 + sum1;

#pragma unroll
        for (int nb = 0; nb < 16; nb++) {
            o[nb][0] *= corr0; o[nb][1] *= corr0;
            o[nb][2] *= corr1; o[nb][3] *= corr1;
        }

        // ---- P -> A fragments (fp16) ----
        uint32_t ph[4][4];
#pragma unroll
        for (int j = 0; j < 4; j++) {
            ph[j][0] = pack_h2(sc[2 * j][0],     sc[2 * j][1]);
            ph[j][1] = pack_h2(sc[2 * j][2],     sc[2 * j][3]);
            ph[j][2] = pack_h2(sc[2 * j + 1][0], sc[2 * j + 1][1]);
            ph[j][3] = pack_h2(sc[2 * j + 1][2], sc[2 * j + 1][3]);
        }

        // ---- O += P @ V ----  single pass, nt2-pairs interleaved.
#pragma unroll
        for (int j = 0; j < 4; j++) {
#pragma unroll
            for (int p2 = 0; p2 < 4; p2++) {
                const int nt2a = 2 * p2, nt2b = 2 * p2 + 1;
                uint32_t voffa = (uint32_t)((j * 16 + vRow) * FSTR + nt2a * 16 + vCol) * 2;
                uint32_t voffb = (uint32_t)((j * 16 + vRow) * FSTR + nt2b * 16 + vCol) * 2;
                uint32_t vha[4], vhb[4];
                ldm_x4_t(vha, sVh + voffa);
                ldm_x4_t(vhb, sVh + voffb);
                mma_f16(o[nt2a * 2],     ph[j], &vha[0]);
                mma_f16(o[nt2a * 2 + 1], ph[j], &vha[2]);
                mma_f16(o[nt2b * 2],     ph[j], &vhb[0]);
                mma_f16(o[nt2b * 2 + 1], ph[j], &vhb[2]);
            }
        }
    }

    // ---- epilogue: normalize, fp16, write [B,S,H*dk] ----
    float inv0 = 1.0f / l_i[0], inv1 = 1.0f / l_i[1];
    size_t row0 = (size_t)(b * S_LEN + qblk * 64 + w * 16 + g);
    size_t row1 = row0 + 8;
#pragma unroll
    for (int nb = 0; nb < 16; nb++) {
        int col = h * DK + nb * 8 + t4 * 2;
        *(uint32_t*)&g_ah[row0 * D_MODEL + col] = pack_h2(o[nb][0] * inv0, o[nb][1] * inv0);
        *(uint32_t*)&g_ah[row1 * D_MODEL + col] = pack_h2(o[nb][2] * inv1, o[nb][3] * inv1);
    }
}

// ===========================================================================
// Launch
// ===========================================================================
extern "C" void kernel_launch(void* const* d_in, const int* in_sizes, int n_in,
                              void* d_out, int out_size) {
    const float* x     = (const float*)d_in[0];
    const float* w_qkv = (const float*)d_in[1];
    const float* w_o   = (const float*)d_in[2];
    float* out = (float*)d_out;

    float* qkv_ptr;
    __half *xh, *wqh, *woh, *ah;
    cudaGetSymbolAddress((void**)&qkv_ptr, g_qkv);
    cudaGetSymbolAddress((void**)&xh, g_xh);
    cudaGetSymbolAddress((void**)&wqh, g_wqh);
    cudaGetSymbolAddress((void**)&woh, g_woh);
    cudaGetSymbolAddress((void**)&ah, g_ah);

    const int M = BATCH * S_LEN;  // 4096

    // 0) Convert inputs to fp16
    conv_h_kernel<<<(XN + 255) / 256, 256>>>(x, xh, XN);
    conv_h_kernel<<<(WQN + 255) / 256, 256>>>(w_qkv, wqh, WQN);
    conv_h_kernel<<<(WON + 255) / 256, 256>>>(w_o, woh, WON);

    cudaFuncSetAttribute(gemm_hmma, cudaFuncAttributeMaxDynamicSharedMemorySize,
                         GEMM_SMEM);

    // 1) QKV projection: persistent grid
    gemm_hmma<<<NSM_SLOTS, 128, GEMM_SMEM>>>(xh, wqh, qkv_ptr,
                                             M, 3 * D_MODEL, D_MODEL);
    // 2) Rope + convert to head-major fp16
    {
        int n = BATCH * NH * S_LEN * 64;
        rope_split_kernel<<<(n + 255) / 256, 256>>>();
    }
    // 3) HMMA causal flash attention
    {
        cudaFuncSetAttribute(flash_hmma, cudaFuncAttributeMaxDynamicSharedMemorySize,
                             FLASH_SMEM);
        dim3 grid(S_LEN / 64, NH, BATCH);
        flash_hmma<<<grid, 128, FLASH_SMEM>>>();
    }
    // 4) Output projection: persistent grid
    gemm_hmma<<<NSM_SLOTS, 128, GEMM_SMEM>>>(ah, woh, out,
                                             M, D_MODEL, D_MODEL);
}